// round 2
// baseline (speedup 1.0000x reference)
#include <cuda_runtime.h>
#include <cuda_bf16.h>
#include <math.h>

// Shapes: x (4,8,256,64,64) f32; w_k/w_q/w_v (128,256,3,3); w_out (256,128,3,3); b_out (256)
// out (4,8,256,64,64) f32
//
// Scratch (device globals; no runtime allocation):
//   g_k      (4,128,64,64)
//   g_q      (32,128,64,64)   [frame-major: b*8+t]
//   g_v      (32,128,64,64)
//   g_pooled (4,128,64,64)

#define HWPIX 4096  // 64*64

__device__ float g_scratch[(4 + 32 + 32 + 4) * 128 * HWPIX];

// ---------------------------------------------------------------------------
// Implicit-GEMM 3x3 conv, pad=1, 64x64 images.
// Block tile: 32 output channels x 4 rows x 64 cols. 256 threads.
// Thread: 8 oc x 4 rows x 1 col  (32 accumulators).
// Channel chunk: 8. smem: input 8x6x66 (12.7KB) + weights 32x8x9 (9.2KB).
// ---------------------------------------------------------------------------
template <int CIN>
__global__ __launch_bounds__(256) void conv3x3_kernel(
    const float* __restrict__ in, long inBatchStride,
    const float* __restrict__ w,
    const float* __restrict__ bias,
    float* __restrict__ out, long outBatchStride,
    int repl, long replStride)
{
    __shared__ float s_in[8][6][66];
    __shared__ float s_w[32][8][9];

    const int n   = blockIdx.z;
    const int oc0 = blockIdx.y * 32;
    const int r0  = blockIdx.x * 4;
    const int tid = threadIdx.x;
    const int col = tid & 63;
    const int og  = tid >> 6;   // 0..3  (8 output channels each)

    const float* inN = in + (long)n * inBatchStride;

    float acc[8][4];
#pragma unroll
    for (int j = 0; j < 8; j++)
#pragma unroll
        for (int r = 0; r < 4; r++) acc[j][r] = 0.f;

    for (int c0 = 0; c0 < CIN; c0 += 8) {
        __syncthreads();
        // ---- load input tile: 8 channels x 6 rows x 66 cols (zero-padded) ----
        for (int idx = tid; idx < 8 * 6 * 66; idx += 256) {
            int c   = idx / 396;
            int rem = idx - c * 396;
            int row = rem / 66;
            int cp  = rem - row * 66;
            int gr  = r0 - 1 + row;
            int gc  = cp - 1;
            float v = 0.f;
            if (gr >= 0 && gr < 64 && gc >= 0 && gc < 64)
                v = inN[(long)(c0 + c) * HWPIX + gr * 64 + gc];
            s_in[c][row][cp] = v;
        }
        // ---- load weight tile: 32 oc x 8 ic x 9 ----
        for (int idx = tid; idx < 32 * 8 * 9; idx += 256) {
            int o   = idx / 72;
            int rem = idx - o * 72;
            int c   = rem / 9;
            int k9  = rem - c * 9;
            s_w[o][c][k9] = w[((long)(oc0 + o) * CIN + (c0 + c)) * 9 + k9];
        }
        __syncthreads();

#pragma unroll
        for (int c = 0; c < 8; c++) {
            // cache the 6x3 input window for this thread's column
            float xall[6][3];
#pragma unroll
            for (int rr = 0; rr < 6; rr++)
#pragma unroll
                for (int dx = 0; dx < 3; dx++)
                    xall[rr][dx] = s_in[c][rr][col + dx];

#pragma unroll
            for (int dy = 0; dy < 3; dy++) {
#pragma unroll
                for (int dx = 0; dx < 3; dx++) {
#pragma unroll
                    for (int j = 0; j < 8; j++) {
                        float wv = s_w[og * 8 + j][c][dy * 3 + dx];
#pragma unroll
                        for (int r = 0; r < 4; r++)
                            acc[j][r] += wv * xall[r + dy][dx];
                    }
                }
            }
        }
    }

    // ---- store (optionally + bias, optionally replicated over T) ----
#pragma unroll
    for (int j = 0; j < 8; j++) {
        int o   = oc0 + og * 8 + j;
        float b = bias ? bias[o] : 0.f;
#pragma unroll
        for (int r = 0; r < 4; r++) {
            float v   = acc[j][r] + b;
            long base = (long)n * outBatchStride + (long)o * HWPIX + (r0 + r) * 64 + col;
            for (int t = 0; t < repl; t++)
                out[base + (long)t * replStride] = v;
        }
    }
}

// ---------------------------------------------------------------------------
// Per-pixel attention: dots over DH=128, softmax over T=8, pool v.
// q,v: (32,128,4096) frame-major; k,pooled: (4,128,4096)
// ---------------------------------------------------------------------------
__global__ __launch_bounds__(256) void attn_kernel(
    const float* __restrict__ q, const float* __restrict__ k,
    const float* __restrict__ v, float* __restrict__ pooled)
{
    const int pix = blockIdx.x * blockDim.x + threadIdx.x;  // 0..4095
    const int b   = blockIdx.y;

    const float* qb = q + (long)b * 8 * 128 * HWPIX;
    const float* kb = k + (long)b * 128 * HWPIX;
    const float* vb = v + (long)b * 8 * 128 * HWPIX;

    float dots[8];
#pragma unroll
    for (int t = 0; t < 8; t++) dots[t] = 0.f;

    for (int c = 0; c < 128; c++) {
        float kv = kb[c * HWPIX + pix];
#pragma unroll
        for (int t = 0; t < 8; t++)
            dots[t] += qb[((long)t * 128 + c) * HWPIX + pix] * kv;
    }

    float m = dots[0];
#pragma unroll
    for (int t = 1; t < 8; t++) m = fmaxf(m, dots[t]);
    float a[8];
    float s = 0.f;
#pragma unroll
    for (int t = 0; t < 8; t++) { a[t] = expf(dots[t] - m); s += a[t]; }
    float inv = 1.f / s;
#pragma unroll
    for (int t = 0; t < 8; t++) a[t] *= inv;

    for (int c = 0; c < 128; c++) {
        float accv = 0.f;
#pragma unroll
        for (int t = 0; t < 8; t++)
            accv += a[t] * vb[((long)t * 128 + c) * HWPIX + pix];
        pooled[(long)b * 128 * HWPIX + c * HWPIX + pix] = accv;
    }
}

// ---------------------------------------------------------------------------

extern "C" void kernel_launch(void* const* d_in, const int* in_sizes, int n_in,
                              void* d_out, int out_size)
{
    const float* x     = (const float*)d_in[0];
    const float* w_k   = (const float*)d_in[1];
    const float* w_q   = (const float*)d_in[2];
    const float* w_v   = (const float*)d_in[3];
    const float* w_out = (const float*)d_in[4];
    const float* b_out = (const float*)d_in[5];
    float* out = (float*)d_out;

    void* basev = nullptr;
    cudaGetSymbolAddress(&basev, g_scratch);
    float* gk = (float*)basev;                 // 4*128*4096
    float* gq = gk + (long)4  * 128 * HWPIX;   // 32*128*4096
    float* gv = gq + (long)32 * 128 * HWPIX;   // 32*128*4096
    float* gp = gv + (long)32 * 128 * HWPIX;   // 4*128*4096

    const long CHW   = (long)256 * HWPIX;        // per-frame x stride
    const long TCHW  = (long)8 * CHW;            // per-batch x stride
    const long DHW   = (long)128 * HWPIX;

    // k = conv(x[:,0], w_k): N=4 images, batch stride skips T
    conv3x3_kernel<256><<<dim3(16, 128 / 32, 4), 256>>>(
        x, TCHW, w_k, nullptr, gk, DHW, 1, 0);

    // q = conv(all 32 frames, w_q)
    conv3x3_kernel<256><<<dim3(16, 128 / 32, 32), 256>>>(
        x, CHW, w_q, nullptr, gq, DHW, 1, 0);

    // v = conv(all 32 frames, w_v)
    conv3x3_kernel<256><<<dim3(16, 128 / 32, 32), 256>>>(
        x, CHW, w_v, nullptr, gv, DHW, 1, 0);

    // attention + pooling
    attn_kernel<<<dim3(HWPIX / 256, 4), 256>>>(gq, gk, gv, gp);

    // out conv + bias, broadcast over T=8
    conv3x3_kernel<128><<<dim3(16, 256 / 32, 4), 256>>>(
        gp, DHW, w_out, b_out, out, TCHW, 8, CHW);
}

// round 4
// speedup vs baseline: 2.6878x; 2.6878x over previous
#include <cuda_runtime.h>
#include <cuda_bf16.h>
#include <cstdint>

#define HW 4096
#define PHW ((long)HW * 128)          // pixel-major frame stride (floats)
#define CHWX ((long)256 * HW)         // x per-frame stride
#define TCHWX ((long)8 * CHWX)        // x/out per-batch stride

// scratch: gk | gq | gv | gp | 4 packed-weight regions (bf16 hi|lo)
#define OFF_GK 0L
#define OFF_GQ 2097152L
#define OFF_GV 18874368L
#define OFF_GP 35651584L
#define OFF_PW 37748736L
__device__ __align__(256) float g_scratch[38928384];

// ---------------- helpers ----------------
__device__ __forceinline__ uint32_t s2u(const void* p) {
    uint32_t a;
    asm("{ .reg .u64 t; cvta.to.shared.u64 t, %1; cvt.u32.u64 %0, t; }" : "=r"(a) : "l"(p));
    return a;
}
__device__ __forceinline__ void sts128(uint32_t a, uint32_t x, uint32_t y, uint32_t z, uint32_t w) {
    asm volatile("st.shared.v4.b32 [%0], {%1,%2,%3,%4};" :: "r"(a), "r"(x), "r"(y), "r"(z), "r"(w) : "memory");
}
// split two fp32 into bf16 hi-pair and lo-pair (f0 -> low half)
__device__ __forceinline__ void split2(float f0, float f1, uint32_t& hi, uint32_t& lo) {
    uint32_t h;
    asm("cvt.rn.bf16x2.f32 %0, %1, %2;" : "=r"(h) : "f"(f1), "f"(f0));
    float h0 = __uint_as_float(h << 16);
    float h1 = __uint_as_float(h & 0xFFFF0000u);
    float l0 = f0 - h0, l1 = f1 - h1;
    uint32_t l;
    asm("cvt.rn.bf16x2.f32 %0, %1, %2;" : "=r"(l) : "f"(l1), "f"(l0));
    hi = h; lo = l;
}
__device__ __forceinline__ void ldm4(uint32_t a, uint32_t* r) {
    asm volatile("ldmatrix.sync.aligned.m8n8.x4.shared.b16 {%0,%1,%2,%3}, [%4];"
                 : "=r"(r[0]), "=r"(r[1]), "=r"(r[2]), "=r"(r[3]) : "r"(a));
}
__device__ __forceinline__ void mma16816(float* c, const uint32_t* a, uint32_t b0, uint32_t b1) {
    asm volatile("mma.sync.aligned.m16n8k16.row.col.f32.bf16.bf16.f32 "
                 "{%0,%1,%2,%3}, {%4,%5,%6,%7}, {%8,%9}, {%0,%1,%2,%3};"
                 : "+f"(c[0]), "+f"(c[1]), "+f"(c[2]), "+f"(c[3])
                 : "r"(a[0]), "r"(a[1]), "r"(a[2]), "r"(a[3]), "r"(b0), "r"(b1));
}

// ---- weight pack: w(OC,CIN,3,3) -> bf16 [it][oc][64] (32 hi | 32 lo), it = tap*CH + chunk ----
__global__ void pack_w(const float* __restrict__ src, __nv_bfloat16* __restrict__ dst, int OC, int CIN) {
    int CH = CIN >> 5;
    long total = (long)9 * CH * OC * 32;
    for (long i = (long)blockIdx.x * blockDim.x + threadIdx.x; i < total; i += (long)gridDim.x * blockDim.x) {
        int c = (int)(i & 31);
        long r = i >> 5;
        int oc = (int)(r % OC);
        int it = (int)(r / OC);
        int tap = it / CH, chk = it - tap * CH;
        float x = src[((long)oc * CIN + chk * 32 + c) * 9 + tap];
        __nv_bfloat16 hb = __float2bfloat16(x);
        float lo = x - __bfloat162float(hb);
        dst[((long)it * OC + oc) * 64 + c] = hb;
        dst[((long)it * OC + oc) * 64 + 32 + c] = __float2bfloat16(lo);
    }
}

// ---------------- mma.sync implicit-GEMM conv3x3 (3-term bf16 split) ----------------
// CTA: M=128 oc x N=128 pixels (2 rows x 64 cols), 256 threads (8 warps, 2m x 4n).
// smem buffers (x2): B tile 128 rows x 144B, A tile 128 rows x 144B (row = 32 hi bf16 | 32 lo bf16 | pad).
template <int CH, bool PIXMAJOR, bool FINAL>
__global__ __launch_bounds__(256) void conv_mma(
    const float* __restrict__ in, long inFrameStride,
    const __nv_bfloat16* __restrict__ pw, int OCTOT,
    const float* __restrict__ bias,
    float* __restrict__ out, long outFrameStride)
{
    extern __shared__ __align__(16) char dsm[];
    const uint32_t sb = s2u(dsm);
    const int t = threadIdx.x, lane = t & 31, w = t >> 5;
    const int tile = blockIdx.x, frame = blockIdx.y, oc0 = blockIdx.z * 128;
    const int p0 = tile * 128;
    const float* inF = in + (long)frame * inFrameStride;
    const int wm = w >> 2, wn = w & 3;
    const int pixcol = t & 63, cg = t >> 6;   // B fill: pixel col + channel-group(8)
    const int ao = t >> 1, ah = t & 1;        // A fill: oc row + half

    float acc[4][4][4];
#pragma unroll
    for (int i = 0; i < 4; i++)
#pragma unroll
        for (int j = 0; j < 4; j++)
#pragma unroll
            for (int r = 0; r < 4; r++) acc[i][j][r] = 0.f;

    float breg[2][8];
    uint4 areg[4];
    constexpr int ITERS = 9 * CH;

    // ---- prefetch iter 0 ----
    auto ldgs = [&](int it) {
        const int tap = it / CH, chk = it - tap * CH;
        const int dy = tap / 3 - 1, dx = tap - (tap / 3) * 3 - 1;
        const int c0 = chk * 32;
        const int gc = pixcol + dx;
        const bool cok = (unsigned)gc < 64u;
#pragma unroll
        for (int r = 0; r < 2; r++) {
            const int gr = tile * 2 + r + dy;
            const bool ok = cok && ((unsigned)gr < 64u);
            if (PIXMAJOR) {
                const float4* s = (const float4*)(inF + ((long)(gr * 64 + gc)) * 128 + c0 + cg * 8);
                float4 x0 = ok ? __ldg(s) : make_float4(0.f, 0.f, 0.f, 0.f);
                float4 x1 = ok ? __ldg(s + 1) : make_float4(0.f, 0.f, 0.f, 0.f);
                breg[r][0] = x0.x; breg[r][1] = x0.y; breg[r][2] = x0.z; breg[r][3] = x0.w;
                breg[r][4] = x1.x; breg[r][5] = x1.y; breg[r][6] = x1.z; breg[r][7] = x1.w;
            } else {
                const float* s = inF + (long)(c0 + cg * 8) * HW + gr * 64 + gc;
#pragma unroll
                for (int j = 0; j < 8; j++)
                    breg[r][j] = ok ? __ldg(s + (long)j * HW) : 0.f;
            }
        }
        const __nv_bfloat16* pA = pw + ((long)it * OCTOT + oc0 + ao) * 64 + ah * 32;
#pragma unroll
        for (int q = 0; q < 4; q++) areg[q] = __ldg((const uint4*)pA + q);
    };

    ldgs(0);

    for (int it = 0; it < ITERS; ++it) {
        const int buf = it & 1;
        const uint32_t bB = sb + buf * 36864;
        const uint32_t bA = bB + 18432;

        // ---- STS current iter ----
#pragma unroll
        for (int r = 0; r < 2; r++) {
            const int p = r * 64 + pixcol;
            uint32_t hi[4], lo[4];
#pragma unroll
            for (int j2 = 0; j2 < 4; j2++)
                split2(breg[r][2 * j2], breg[r][2 * j2 + 1], hi[j2], lo[j2]);
            sts128(bB + p * 144 + cg * 16, hi[0], hi[1], hi[2], hi[3]);
            sts128(bB + p * 144 + 64 + cg * 16, lo[0], lo[1], lo[2], lo[3]);
        }
#pragma unroll
        for (int q = 0; q < 4; q++)
            sts128(bA + ao * 144 + ah * 64 + q * 16, areg[q].x, areg[q].y, areg[q].z, areg[q].w);

        __syncthreads();

        if (it + 1 < ITERS) ldgs(it + 1);

        // ---- MMA phase ----
        const uint32_t aAddr0 = bA + (wm * 64 + (lane & 15)) * 144 + (lane >> 4) * 16;
        const uint32_t bAddr0 = bB + (wn * 32 + (lane & 15)) * 144 + (lane >> 4) * 16;
#pragma unroll
        for (int ks = 0; ks < 2; ks++) {
            uint32_t Bh[2][4], Bl[2][4];
#pragma unroll
            for (int g = 0; g < 2; g++) {
                ldm4(bAddr0 + g * 16 * 144 + ks * 32, Bh[g]);
                ldm4(bAddr0 + g * 16 * 144 + 64 + ks * 32, Bl[g]);
            }
#pragma unroll
            for (int i = 0; i < 4; i++) {
                uint32_t Ah[4], Al[4];
                ldm4(aAddr0 + i * 16 * 144 + ks * 32, Ah);
                ldm4(aAddr0 + i * 16 * 144 + 64 + ks * 32, Al);
#pragma unroll
                for (int j = 0; j < 4; j++) {
                    const int g = j >> 1, rs = j & 1;
                    mma16816(acc[i][j], Ah, Bh[g][rs], Bh[g][rs + 2]);
                    mma16816(acc[i][j], Ah, Bl[g][rs], Bl[g][rs + 2]);
                    mma16816(acc[i][j], Al, Bh[g][rs], Bh[g][rs + 2]);
                }
            }
        }
        __syncthreads();
    }

    // ---- epilogue: stage [pix][oc] in smem (132-float rows), then coalesced copy ----
    float* stage = (float*)dsm;
#pragma unroll
    for (int i = 0; i < 4; i++) {
        const int m = wm * 64 + i * 16 + (lane >> 2);
#pragma unroll
        for (int j = 0; j < 4; j++) {
            const int n = wn * 32 + j * 8 + (lane & 3) * 2;
            stage[n * 132 + m]           = acc[i][j][0];
            stage[(n + 1) * 132 + m]     = acc[i][j][1];
            stage[n * 132 + m + 8]       = acc[i][j][2];
            stage[(n + 1) * 132 + m + 8] = acc[i][j][3];
        }
    }
    __syncthreads();

    if (FINAL) {
        for (int idx = t; idx < 32 * 128; idx += 256) {
            const int pg = idx & 31, oc = idx >> 5;
            const float bv = bias[oc0 + oc];
            float4 v;
            v.x = stage[(pg * 4 + 0) * 132 + oc] + bv;
            v.y = stage[(pg * 4 + 1) * 132 + oc] + bv;
            v.z = stage[(pg * 4 + 2) * 132 + oc] + bv;
            v.w = stage[(pg * 4 + 3) * 132 + oc] + bv;
            float* ob = out + (long)frame * outFrameStride + (long)(oc0 + oc) * HW + p0 + pg * 4;
#pragma unroll
            for (int tt = 0; tt < 8; tt++)
                *(float4*)(ob + (long)tt * CHWX) = v;
        }
    } else {
        float* outF = out + (long)frame * outFrameStride;
        for (int idx = t; idx < 128 * 32; idx += 256) {
            const int p = idx >> 5, q = idx & 31;
            float4 v = *(float4*)(stage + p * 132 + q * 4);
            *(float4*)(outF + (long)(p0 + p) * 128 + q * 4) = v;
        }
    }
}

// ---------------- attention: warp per pixel, [pix][128] layout ----------------
__global__ __launch_bounds__(256) void attn_tc(
    const float* __restrict__ q, const float* __restrict__ k,
    const float* __restrict__ v, float* __restrict__ pooled)
{
    const int wid = threadIdx.x >> 5, lane = threadIdx.x & 31;
    const int g = blockIdx.x * 8 + wid;
    const int b = g >> 12, pix = g & 4095;

    float4 k4 = ((const float4*)(k + ((long)b * HW + pix) * 128))[lane];

    float dots[8];
#pragma unroll
    for (int t = 0; t < 8; t++) {
        float4 q4 = ((const float4*)(q + ((long)((b * 8 + t) * HW) + pix) * 128))[lane];
        float d = q4.x * k4.x + q4.y * k4.y + q4.z * k4.z + q4.w * k4.w;
#pragma unroll
        for (int off = 16; off; off >>= 1) d += __shfl_xor_sync(0xFFFFFFFFu, d, off);
        dots[t] = d;
    }
    float m = dots[0];
#pragma unroll
    for (int t = 1; t < 8; t++) m = fmaxf(m, dots[t]);
    float a[8], s = 0.f;
#pragma unroll
    for (int t = 0; t < 8; t++) { a[t] = expf(dots[t] - m); s += a[t]; }
    float inv = 1.f / s;

    float4 acc = make_float4(0.f, 0.f, 0.f, 0.f);
#pragma unroll
    for (int t = 0; t < 8; t++) {
        float4 v4 = ((const float4*)(v + ((long)((b * 8 + t) * HW) + pix) * 128))[lane];
        float wgt = a[t] * inv;
        acc.x += wgt * v4.x; acc.y += wgt * v4.y; acc.z += wgt * v4.z; acc.w += wgt * v4.w;
    }
    ((float4*)(pooled + ((long)b * HW + pix) * 128))[lane] = acc;
}

// ---------------------------------------------------------------------------
extern "C" void kernel_launch(void* const* d_in, const int* in_sizes, int n_in,
                              void* d_out, int out_size)
{
    const float* x     = (const float*)d_in[0];
    const float* w_k   = (const float*)d_in[1];
    const float* w_q   = (const float*)d_in[2];
    const float* w_v   = (const float*)d_in[3];
    const float* w_out = (const float*)d_in[4];
    const float* b_out = (const float*)d_in[5];
    float* out = (float*)d_out;

    void* basev = nullptr;
    cudaGetSymbolAddress(&basev, g_scratch);
    float* S = (float*)basev;
    float* gk = S + OFF_GK;
    float* gq = S + OFF_GQ;
    float* gv = S + OFF_GV;
    float* gp = S + OFF_GP;
    __nv_bfloat16* pwk = (__nv_bfloat16*)(S + OFF_PW);
    __nv_bfloat16* pwq = pwk + 589824;
    __nv_bfloat16* pwv = pwq + 589824;
    __nv_bfloat16* pwo = pwv + 589824;

    const int DSM = 2 * 36864;
    cudaFuncSetAttribute(conv_mma<8, false, false>, cudaFuncAttributeMaxDynamicSharedMemorySize, DSM);
    cudaFuncSetAttribute(conv_mma<4, true, true>,   cudaFuncAttributeMaxDynamicSharedMemorySize, DSM);

    pack_w<<<1152, 256>>>(w_k, pwk, 128, 256);
    pack_w<<<1152, 256>>>(w_q, pwq, 128, 256);
    pack_w<<<1152, 256>>>(w_v, pwv, 128, 256);
    pack_w<<<1152, 256>>>(w_out, pwo, 256, 128);

    // k conv: first frame of each batch
    conv_mma<8, false, false><<<dim3(32, 4, 1), 256, DSM>>>(x, TCHWX, pwk, 128, nullptr, gk, PHW);
    // q, v convs: all 32 frames
    conv_mma<8, false, false><<<dim3(32, 32, 1), 256, DSM>>>(x, CHWX, pwq, 128, nullptr, gq, PHW);
    conv_mma<8, false, false><<<dim3(32, 32, 1), 256, DSM>>>(x, CHWX, pwv, 128, nullptr, gv, PHW);
    // attention + pooling
    attn_tc<<<2048, 256>>>(gq, gk, gv, gp);
    // out conv: pixel-major input, 256 oc, bias + T-broadcast
    conv_mma<4, true, true><<<dim3(32, 4, 2), 256, DSM>>>(gp, PHW, pwo, 256, b_out, out, TCHWX);
}

// round 5
// speedup vs baseline: 2.6969x; 1.0034x over previous
#include <cuda_runtime.h>
#include <cuda_bf16.h>
#include <cstdint>

#define HW 4096
#define PHW ((long)HW * 128)          // fp32 pixel-major frame stride
#define CHWX ((long)256 * HW)         // x per-frame stride (floats)
#define TCHWX ((long)8 * CHWX)        // per-batch stride (floats)

// float offsets in g_scratch
#define OFF_GK  0L
#define OFF_GQ  2097152L
#define OFF_GV  18874368L
#define OFF_GP2 35651584L             // bf16 split pooled: 8MB
#define OFF_XS  37748736L             // bf16 split x: 128MB
#define OFF_PW  71303168L
__device__ __align__(256) float g_scratch[72482816];

// ---------------- helpers ----------------
__device__ __forceinline__ uint32_t s2u(const void* p) {
    uint32_t a;
    asm("{ .reg .u64 t; cvta.to.shared.u64 t, %1; cvt.u32.u64 %0, t; }" : "=r"(a) : "l"(p));
    return a;
}
__device__ __forceinline__ void split2(float f0, float f1, uint32_t& hi, uint32_t& lo) {
    uint32_t h;
    asm("cvt.rn.bf16x2.f32 %0, %1, %2;" : "=r"(h) : "f"(f1), "f"(f0));
    float h0 = __uint_as_float(h << 16);
    float h1 = __uint_as_float(h & 0xFFFF0000u);
    float l0 = f0 - h0, l1 = f1 - h1;
    uint32_t l;
    asm("cvt.rn.bf16x2.f32 %0, %1, %2;" : "=r"(l) : "f"(l1), "f"(l0));
    hi = h; lo = l;
}
__device__ __forceinline__ void ldm4(uint32_t a, uint32_t* r) {
    asm volatile("ldmatrix.sync.aligned.m8n8.x4.shared.b16 {%0,%1,%2,%3}, [%4];"
                 : "=r"(r[0]), "=r"(r[1]), "=r"(r[2]), "=r"(r[3]) : "r"(a));
}
__device__ __forceinline__ void mma16816(float* c, const uint32_t* a, uint32_t b0, uint32_t b1) {
    asm volatile("mma.sync.aligned.m16n8k16.row.col.f32.bf16.bf16.f32 "
                 "{%0,%1,%2,%3}, {%4,%5,%6,%7}, {%8,%9}, {%0,%1,%2,%3};"
                 : "+f"(c[0]), "+f"(c[1]), "+f"(c[2]), "+f"(c[3])
                 : "r"(a[0]), "r"(a[1]), "r"(a[2]), "r"(a[3]), "r"(b0), "r"(b1));
}
__device__ __forceinline__ void cp16(uint32_t d, const void* s) {
    asm volatile("cp.async.cg.shared.global [%0], [%1], 16;" :: "r"(d), "l"(s));
}
__device__ __forceinline__ void cp16z(uint32_t d, const void* s, int zf) {
    asm volatile("cp.async.cg.shared.global [%0], [%1], 16, %2;" :: "r"(d), "l"(s), "r"(zf));
}

// ---- weight pack: w(OC,CIN,3,3) -> bf16 [it][oc][32 hi | 32 lo], it = tap*CH + chunk ----
__global__ void pack_w(const float* __restrict__ src, __nv_bfloat16* __restrict__ dst, int OC, int CIN) {
    int CH = CIN >> 5;
    long total = (long)9 * CH * OC * 32;
    for (long i = (long)blockIdx.x * blockDim.x + threadIdx.x; i < total; i += (long)gridDim.x * blockDim.x) {
        int c = (int)(i & 31);
        long r = i >> 5;
        int oc = (int)(r % OC);
        int it = (int)(r / OC);
        int tap = it / CH, chk = it - tap * CH;
        float x = src[((long)oc * CIN + chk * 32 + c) * 9 + tap];
        __nv_bfloat16 hb = __float2bfloat16(x);
        float lo = x - __bfloat162float(hb);
        dst[((long)it * OC + oc) * 64 + c] = hb;
        dst[((long)it * OC + oc) * 64 + 32 + c] = __float2bfloat16(lo);
    }
}

// ---- x pre-split: x[f][256ch][4096pix] f32 -> xs[f][pix][chunk8][32hi|32lo bf16] ----
__global__ __launch_bounds__(256) void split_x(const float* __restrict__ x, uint8_t* __restrict__ xs) {
    __shared__ float sm[256][33];
    const int f = blockIdx.y;
    const int p0 = blockIdx.x * 32;
    const int t = threadIdx.x;
    const float* xf = x + (long)f * CHWX;
    const int pix = t & 31, cb = t >> 5;
#pragma unroll 8
    for (int i = 0; i < 32; i++) {
        int ch = cb * 32 + i;
        sm[ch][pix] = xf[(long)ch * HW + p0 + pix];
    }
    __syncthreads();
    uint8_t* of = xs + ((long)f * HW + p0) * 1024;
#pragma unroll
    for (int o = 0; o < 8; o++) {
        int n = t + o * 256;
        int p = n >> 6, q = n & 63;
        int chunk = q >> 3, qq = q & 7;
        bool hip = qq < 4;
        int chb = chunk * 32 + (hip ? qq * 8 : (qq - 4) * 8);
        uint32_t r[4];
#pragma unroll
        for (int j = 0; j < 4; j++) {
            uint32_t h, l;
            split2(sm[chb + 2 * j][p], sm[chb + 2 * j + 1][p], h, l);
            r[j] = hip ? h : l;
        }
        *(uint4*)(of + (long)p * 1024 + q * 16) = make_uint4(r[0], r[1], r[2], r[3]);
    }
}

// ---------------- multistage cp.async mma.sync conv3x3 (3-term bf16) ----------------
// CTA: M=128 oc x N=128 pixels, 256 threads (8 warps 2m x 4n), 4 stages.
// Stage: B 128x128B (XOR-swizzled) + NW x A 128x128B.
template <int CH, int CHT, int NW, bool FINAL>
__global__ __launch_bounds__(256) void conv_mma(
    const uint8_t* __restrict__ in, long inFrameB,
    const __nv_bfloat16* __restrict__ pw0, const __nv_bfloat16* __restrict__ pw1, int OCTOT,
    const float* __restrict__ bias,
    float* __restrict__ out0, float* __restrict__ out1, long outFrameStride)
{
    constexpr int ITERS = 9 * CH;
    constexpr int STAGE = 16384 * (1 + NW);
    extern __shared__ __align__(16) char dsm[];
    const uint32_t sb = s2u(dsm);
    const int t = threadIdx.x, lane = t & 31, w = t >> 5;
    const int tile = blockIdx.x, frame = blockIdx.y, oc0 = blockIdx.z * 128;
    const int p0 = tile * 128;
    const uint8_t* inF = in + (long)frame * inFrameB;
    const int wm = w >> 2, wn = w & 3;
    const int fp = t >> 1, fsub = (t & 1) * 4;
    const int prow = fp >> 6, pcol = fp & 63;

    auto issue = [&](int it) {
        const int tap = it / CH, chk = it - tap * CH;
        const int dy = tap / 3 - 1, dx = tap - (tap / 3) * 3 - 1;
        const uint32_t bufB = sb + (it & 3) * STAGE;
        const uint32_t bufA = bufB + 16384;
        const int gr = tile * 2 + prow + dy, gc = pcol + dx;
        const bool ok = ((unsigned)gr < 64u) & ((unsigned)gc < 64u);
        const uint8_t* srcB = inF + ((long)(ok ? (gr * 64 + gc) : 0) * CHT + chk) * 128;
        const int zf = ok ? 16 : 0;
#pragma unroll
        for (int i = 0; i < 4; i++) {
            int q = fsub + i;
            cp16z(bufB + fp * 128 + ((q ^ (fp & 7)) << 4), srcB + q * 16, zf);
        }
#pragma unroll
        for (int s = 0; s < NW; s++) {
            const __nv_bfloat16* pws = s ? pw1 : pw0;
            const uint8_t* srcA = (const uint8_t*)(pws + ((long)it * OCTOT + oc0 + fp) * 64);
#pragma unroll
            for (int i = 0; i < 4; i++) {
                int q = fsub + i;
                cp16(bufA + s * 16384 + fp * 128 + ((q ^ (fp & 7)) << 4), srcA + q * 16);
            }
        }
    };

    float acc[NW][4][4][4];
#pragma unroll
    for (int s = 0; s < NW; s++)
#pragma unroll
        for (int i = 0; i < 4; i++)
#pragma unroll
            for (int j = 0; j < 4; j++)
#pragma unroll
                for (int r = 0; r < 4; r++) acc[s][i][j][r] = 0.f;

#pragma unroll
    for (int s = 0; s < 3; s++) {
        issue(s);
        asm volatile("cp.async.commit_group;" ::: "memory");
    }

    for (int it = 0; it < ITERS; ++it) {
        asm volatile("cp.async.wait_group 2;" ::: "memory");
        __syncthreads();
        const uint32_t bufB = sb + (it & 3) * STAGE;
        const uint32_t bufA = bufB + 16384;
#pragma unroll
        for (int ks = 0; ks < 2; ks++) {
            uint32_t Bh[2][4], Bl[2][4];
#pragma unroll
            for (int g = 0; g < 2; g++) {
                int p = wn * 32 + g * 16 + (lane & 15);
                uint32_t rb = bufB + p * 128;
                int p7 = p & 7, qh = ks * 2 + (lane >> 4);
                ldm4(rb + ((qh ^ p7) << 4), Bh[g]);
                ldm4(rb + (((qh + 4) ^ p7) << 4), Bl[g]);
            }
#pragma unroll
            for (int s = 0; s < NW; s++) {
#pragma unroll
                for (int i = 0; i < 4; i++) {
                    int r = wm * 64 + i * 16 + (lane & 15);
                    uint32_t ra = bufA + s * 16384 + r * 128;
                    int r7 = r & 7, qh = ks * 2 + (lane >> 4);
                    uint32_t Ah[4], Al[4];
                    ldm4(ra + ((qh ^ r7) << 4), Ah);
                    ldm4(ra + (((qh + 4) ^ r7) << 4), Al);
#pragma unroll
                    for (int j = 0; j < 4; j++) {
                        int g = j >> 1, rs = j & 1;
                        mma16816(acc[s][i][j], Ah, Bh[g][rs], Bh[g][rs + 2]);
                        mma16816(acc[s][i][j], Ah, Bl[g][rs], Bl[g][rs + 2]);
                        mma16816(acc[s][i][j], Al, Bh[g][rs], Bh[g][rs + 2]);
                    }
                }
            }
        }
        if (it + 3 < ITERS) issue(it + 3);
        asm volatile("cp.async.commit_group;" ::: "memory");
    }
    asm volatile("cp.async.wait_group 0;" ::: "memory");

    // ---- epilogue: stage [pix][oc] per weight set ----
    float* stage = (float*)dsm;
#pragma unroll
    for (int s = 0; s < NW; s++) {
        __syncthreads();
#pragma unroll
        for (int i = 0; i < 4; i++) {
            int m = wm * 64 + i * 16 + (lane >> 2);
#pragma unroll
            for (int j = 0; j < 4; j++) {
                int n = wn * 32 + j * 8 + (lane & 3) * 2;
                stage[n * 132 + m]           = acc[s][i][j][0];
                stage[(n + 1) * 132 + m]     = acc[s][i][j][1];
                stage[n * 132 + m + 8]       = acc[s][i][j][2];
                stage[(n + 1) * 132 + m + 8] = acc[s][i][j][3];
            }
        }
        __syncthreads();
        if (FINAL) {
            for (int idx = t; idx < 32 * 128; idx += 256) {
                const int pg = idx & 31, oc = idx >> 5;
                const float bv = bias[oc0 + oc];
                float4 v;
                v.x = stage[(pg * 4 + 0) * 132 + oc] + bv;
                v.y = stage[(pg * 4 + 1) * 132 + oc] + bv;
                v.z = stage[(pg * 4 + 2) * 132 + oc] + bv;
                v.w = stage[(pg * 4 + 3) * 132 + oc] + bv;
                float* ob = out0 + (long)frame * outFrameStride + (long)(oc0 + oc) * HW + p0 + pg * 4;
#pragma unroll
                for (int tt = 0; tt < 8; tt++)
                    *(float4*)(ob + (long)tt * CHWX) = v;
            }
        } else {
            float* outF = (s ? out1 : out0) + (long)frame * outFrameStride;
            for (int idx = t; idx < 128 * 32; idx += 256) {
                int p = idx >> 5, q = idx & 31;
                *(float4*)(outF + (long)(p0 + p) * 128 + q * 4) = *(float4*)(stage + p * 132 + q * 4);
            }
        }
    }
}

// ---------------- attention: warp per pixel; emits bf16-split pooled (gp2) ----------------
__global__ __launch_bounds__(256) void attn_tc(
    const float* __restrict__ q, const float* __restrict__ k,
    const float* __restrict__ v, uint8_t* __restrict__ gp2)
{
    const int wid = threadIdx.x >> 5, lane = threadIdx.x & 31;
    const int g = blockIdx.x * 8 + wid;
    const int b = g >> 12, pix = g & 4095;

    float4 k4 = ((const float4*)(k + ((long)b * HW + pix) * 128))[lane];

    float dots[8];
#pragma unroll
    for (int t = 0; t < 8; t++) {
        float4 q4 = ((const float4*)(q + ((long)((b * 8 + t) * HW) + pix) * 128))[lane];
        float d = q4.x * k4.x + q4.y * k4.y + q4.z * k4.z + q4.w * k4.w;
#pragma unroll
        for (int off = 16; off; off >>= 1) d += __shfl_xor_sync(0xFFFFFFFFu, d, off);
        dots[t] = d;
    }
    float m = dots[0];
#pragma unroll
    for (int t = 1; t < 8; t++) m = fmaxf(m, dots[t]);
    float a[8], s = 0.f;
#pragma unroll
    for (int t = 0; t < 8; t++) { a[t] = expf(dots[t] - m); s += a[t]; }
    float inv = 1.f / s;

    float4 acc = make_float4(0.f, 0.f, 0.f, 0.f);
#pragma unroll
    for (int t = 0; t < 8; t++) {
        float4 v4 = ((const float4*)(v + ((long)((b * 8 + t) * HW) + pix) * 128))[lane];
        float wgt = a[t] * inv;
        acc.x += wgt * v4.x; acc.y += wgt * v4.y; acc.z += wgt * v4.z; acc.w += wgt * v4.w;
    }
    uint32_t h0, l0, h1, l1;
    split2(acc.x, acc.y, h0, l0);
    split2(acc.z, acc.w, h1, l1);
    const int chunk = lane >> 3, pos = lane & 7;
    uint8_t* row = gp2 + (((long)(b * HW + pix)) * 4 + chunk) * 128;
    *(uint2*)(row + pos * 8) = make_uint2(h0, h1);
    *(uint2*)(row + 64 + pos * 8) = make_uint2(l0, l1);
}

// ---------------------------------------------------------------------------
extern "C" void kernel_launch(void* const* d_in, const int* in_sizes, int n_in,
                              void* d_out, int out_size)
{
    const float* x     = (const float*)d_in[0];
    const float* w_k   = (const float*)d_in[1];
    const float* w_q   = (const float*)d_in[2];
    const float* w_v   = (const float*)d_in[3];
    const float* w_out = (const float*)d_in[4];
    const float* b_out = (const float*)d_in[5];
    float* out = (float*)d_out;

    void* basev = nullptr;
    cudaGetSymbolAddress(&basev, g_scratch);
    float* S = (float*)basev;
    float*   gk  = S + OFF_GK;
    float*   gq  = S + OFF_GQ;
    float*   gv  = S + OFF_GV;
    uint8_t* gp2 = (uint8_t*)(S + OFF_GP2);
    uint8_t* xs  = (uint8_t*)(S + OFF_XS);
    __nv_bfloat16* pwk = (__nv_bfloat16*)(S + OFF_PW);
    __nv_bfloat16* pwq = pwk + 589824;
    __nv_bfloat16* pwv = pwq + 589824;
    __nv_bfloat16* pwo = pwv + 589824;

    const int DSM1 = 4 * 32768;   // NW=1
    const int DSM2 = 4 * 49152;   // NW=2
    cudaFuncSetAttribute(conv_mma<8, 8, 1, false>, cudaFuncAttributeMaxDynamicSharedMemorySize, DSM1);
    cudaFuncSetAttribute(conv_mma<8, 8, 2, false>, cudaFuncAttributeMaxDynamicSharedMemorySize, DSM2);
    cudaFuncSetAttribute(conv_mma<4, 4, 1, true>,  cudaFuncAttributeMaxDynamicSharedMemorySize, DSM1);

    pack_w<<<1152, 256>>>(w_k, pwk, 128, 256);
    pack_w<<<1152, 256>>>(w_q, pwq, 128, 256);
    pack_w<<<1152, 256>>>(w_v, pwv, 128, 256);
    pack_w<<<1152, 256>>>(w_out, pwo, 256, 128);
    split_x<<<dim3(128, 32), 256>>>(x, xs);

    const long FRAME_B = (long)HW * 8 * 128;   // xs per-frame bytes (4MB)
    // k conv: frames 0,8,16,24 of xs
    conv_mma<8, 8, 1, false><<<dim3(32, 4, 1), 256, DSM1>>>(
        xs, 8 * FRAME_B, pwk, nullptr, 128, nullptr, gk, nullptr, PHW);
    // fused q+v conv over all 32 frames
    conv_mma<8, 8, 2, false><<<dim3(32, 32, 1), 256, DSM2>>>(
        xs, FRAME_B, pwq, pwv, 128, nullptr, gq, gv, PHW);
    // attention -> bf16-split pooled
    attn_tc<<<2048, 256>>>(gq, gk, gv, gp2);
    // out conv: gp2 (4 chunks), 256 oc, bias + T-broadcast
    const long GP_FRAME_B = (long)HW * 4 * 128; // 2MB per batch
    conv_mma<4, 4, 1, true><<<dim3(32, 4, 2), 256, DSM1>>>(
        gp2, GP_FRAME_B, pwo, nullptr, 256, b_out, out, nullptr, TCHWX);
}

// round 6
// speedup vs baseline: 3.0853x; 1.1441x over previous
#include <cuda_runtime.h>
#include <cuda_bf16.h>
#include <cstdint>

#define HW 4096
#define PHW ((long)HW * 128)          // fp32 pixel-major frame stride
#define CHWX ((long)256 * HW)         // x per-frame stride (floats)
#define TCHWX ((long)8 * CHWX)        // per-batch stride (floats)

// float offsets in g_scratch
#define OFF_GK  0L
#define OFF_GQ  2097152L
#define OFF_GV  18874368L
#define OFF_GP2 35651584L             // bf16-split pooled (8MB)
#define OFF_XS  37748736L             // bf16-split x, 4 key frames (16MB)
#define OFF_PWK 41943040L
#define OFF_PWO 42237952L
#define OFF_WTQ 42532864L
#define OFF_WTV 43057152L
#define OFF_XT  43581440L             // Winograd-transformed x, bf16 split (537MB)
#define OFF_YT  177799168L            // Winograd GEMM outputs fp32 (537MB)
__device__ __align__(256) float g_scratch[312016896];

#define XT_PLANE_B (32768L * 1024)    // bytes per Winograd component plane
#define YT_SET     (16L * 32768 * 128) // floats per yt weight-set

// ---------------- helpers ----------------
__device__ __forceinline__ uint32_t s2u(const void* p) {
    uint32_t a;
    asm("{ .reg .u64 t; cvta.to.shared.u64 t, %1; cvt.u32.u64 %0, t; }" : "=r"(a) : "l"(p));
    return a;
}
__device__ __forceinline__ void split2(float f0, float f1, uint32_t& hi, uint32_t& lo) {
    uint32_t h;
    asm("cvt.rn.bf16x2.f32 %0, %1, %2;" : "=r"(h) : "f"(f1), "f"(f0));
    float h0 = __uint_as_float(h << 16);
    float h1 = __uint_as_float(h & 0xFFFF0000u);
    float l0 = f0 - h0, l1 = f1 - h1;
    uint32_t l;
    asm("cvt.rn.bf16x2.f32 %0, %1, %2;" : "=r"(l) : "f"(l1), "f"(l0));
    hi = h; lo = l;
}
__device__ __forceinline__ void ldm4(uint32_t a, uint32_t* r) {
    asm volatile("ldmatrix.sync.aligned.m8n8.x4.shared.b16 {%0,%1,%2,%3}, [%4];"
                 : "=r"(r[0]), "=r"(r[1]), "=r"(r[2]), "=r"(r[3]) : "r"(a));
}
__device__ __forceinline__ void mma16816(float* c, const uint32_t* a, uint32_t b0, uint32_t b1) {
    asm volatile("mma.sync.aligned.m16n8k16.row.col.f32.bf16.bf16.f32 "
                 "{%0,%1,%2,%3}, {%4,%5,%6,%7}, {%8,%9}, {%0,%1,%2,%3};"
                 : "+f"(c[0]), "+f"(c[1]), "+f"(c[2]), "+f"(c[3])
                 : "r"(a[0]), "r"(a[1]), "r"(a[2]), "r"(a[3]), "r"(b0), "r"(b1));
}
__device__ __forceinline__ void cp16(uint32_t d, const void* s) {
    asm volatile("cp.async.cg.shared.global [%0], [%1], 16;" :: "r"(d), "l"(s));
}
__device__ __forceinline__ void cp16z(uint32_t d, const void* s, int zf) {
    asm volatile("cp.async.cg.shared.global [%0], [%1], 16, %2;" :: "r"(d), "l"(s), "r"(zf));
}

// ---- weight pack (direct convs): w(OC,CIN,3,3) -> bf16 [it][oc][32 hi | 32 lo] ----
__global__ void pack_w(const float* __restrict__ src, __nv_bfloat16* __restrict__ dst, int OC, int CIN) {
    int CH = CIN >> 5;
    long total = (long)9 * CH * OC * 32;
    for (long i = (long)blockIdx.x * blockDim.x + threadIdx.x; i < total; i += (long)gridDim.x * blockDim.x) {
        int c = (int)(i & 31);
        long r = i >> 5;
        int oc = (int)(r % OC);
        int it = (int)(r / OC);
        int tap = it / CH, chk = it - tap * CH;
        float x = src[((long)oc * CIN + chk * 32 + c) * 9 + tap];
        __nv_bfloat16 hb = __float2bfloat16(x);
        float lo = x - __bfloat162float(hb);
        dst[((long)it * OC + oc) * 64 + c] = hb;
        dst[((long)it * OC + oc) * 64 + 32 + c] = __float2bfloat16(lo);
    }
}

// ---- Winograd weight transform: w(128,256,3,3) -> wt[comp16][chunk8][oc128][32hi|32lo] ----
__global__ void wino_w(const float* __restrict__ src, __nv_bfloat16* __restrict__ dst) {
    int t = blockIdx.x * blockDim.x + threadIdx.x;
    if (t >= 128 * 256) return;
    int ic = t & 255, oc = t >> 8;
    float g[3][3];
#pragma unroll
    for (int r = 0; r < 3; r++)
#pragma unroll
        for (int c = 0; c < 3; c++)
            g[r][c] = src[((long)oc * 256 + ic) * 9 + r * 3 + c];
    float R[4][3];
#pragma unroll
    for (int c = 0; c < 3; c++) {
        R[0][c] = g[0][c];
        R[1][c] = 0.5f * (g[0][c] + g[1][c] + g[2][c]);
        R[2][c] = 0.5f * (g[0][c] - g[1][c] + g[2][c]);
        R[3][c] = g[2][c];
    }
    float U[4][4];
#pragma unroll
    for (int r = 0; r < 4; r++) {
        U[r][0] = R[r][0];
        U[r][1] = 0.5f * (R[r][0] + R[r][1] + R[r][2]);
        U[r][2] = 0.5f * (R[r][0] - R[r][1] + R[r][2]);
        U[r][3] = R[r][2];
    }
#pragma unroll
    for (int comp = 0; comp < 16; comp++) {
        float x = U[comp >> 2][comp & 3];
        __nv_bfloat16 hb = __float2bfloat16(x);
        float lo = x - __bfloat162float(hb);
        long base = ((long)(comp * 8 + (ic >> 5)) * 128 + oc) * 64 + (ic & 31);
        dst[base] = hb;
        dst[base + 32] = __float2bfloat16(lo);
    }
}

// ---- x pre-split (k conv): frames {0,8,16,24} -> xs[4][pix][chunk8][32hi|32lo] ----
__global__ __launch_bounds__(256) void split_x4(const float* __restrict__ x, uint8_t* __restrict__ xs) {
    __shared__ float sm[256][33];
    const int p0 = blockIdx.x * 32;
    const int t = threadIdx.x;
    const float* xf = x + (long)(blockIdx.y * 8) * CHWX;
    const int pix = t & 31, cb = t >> 5;
#pragma unroll 8
    for (int i = 0; i < 32; i++) {
        int ch = cb * 32 + i;
        sm[ch][pix] = xf[(long)ch * HW + p0 + pix];
    }
    __syncthreads();
    uint8_t* of = xs + ((long)blockIdx.y * HW + p0) * 1024;
#pragma unroll
    for (int o = 0; o < 8; o++) {
        int n = t + o * 256;
        int p = n >> 6, q = n & 63;
        int chunk = q >> 3, qq = q & 7;
        bool hip = qq < 4;
        int chb = chunk * 32 + (hip ? qq * 8 : (qq - 4) * 8);
        uint32_t r[4];
#pragma unroll
        for (int j = 0; j < 4; j++) {
            uint32_t h, l;
            split2(sm[chb + 2 * j][p], sm[chb + 2 * j + 1][p], h, l);
            r[j] = hip ? h : l;
        }
        *(uint4*)(of + (long)p * 1024 + q * 16) = make_uint4(r[0], r[1], r[2], r[3]);
    }
}

// ---- Winograd input transform: x -> xt[comp][tileG][chunk8][32hi|32lo bf16] ----
__global__ __launch_bounds__(256) void wino_in(const float* __restrict__ x, uint8_t* __restrict__ xt) {
    extern __shared__ float sm[];   // [256][137]
    const int f = blockIdx.y;
    const int ty = blockIdx.x >> 1, tx0 = (blockIdx.x & 1) * 16;
    const int t = threadIdx.x;
    const float* xf = x + (long)f * CHWX;
    const int gr0 = 2 * ty - 1, gc0 = 2 * tx0 - 1;
    for (int idx = t; idx < 256 * 4 * 34; idx += 256) {
        int c = idx % 34;
        int rc = idx / 34;
        int r = rc & 3, ch = rc >> 2;
        int gr = gr0 + r, gc = gc0 + c;
        float v = ((unsigned)gr < 64u && (unsigned)gc < 64u) ? xf[(long)ch * HW + gr * 64 + gc] : 0.f;
        sm[ch * 137 + r * 34 + c] = v;
    }
    __syncthreads();
    const int tl = t >> 4, cp = t & 15;
    const long tileG = (long)f * 1024 + ty * 32 + tx0 + tl;
    for (int cc = 0; cc < 8; cc++) {
        float d[2][16];
#pragma unroll
        for (int e = 0; e < 2; e++) {
            const float* s = sm + (cc * 32 + cp * 2 + e) * 137 + 2 * tl;
            float T[4][4];
#pragma unroll
            for (int c = 0; c < 4; c++) {
                float x0 = s[c], x1 = s[34 + c], x2 = s[68 + c], x3 = s[102 + c];
                T[0][c] = x0 - x2; T[1][c] = x1 + x2; T[2][c] = x2 - x1; T[3][c] = x1 - x3;
            }
#pragma unroll
            for (int r = 0; r < 4; r++) {
                d[e][r * 4 + 0] = T[r][0] - T[r][2];
                d[e][r * 4 + 1] = T[r][1] + T[r][2];
                d[e][r * 4 + 2] = T[r][2] - T[r][1];
                d[e][r * 4 + 3] = T[r][1] - T[r][3];
            }
        }
        uint8_t* base = xt + tileG * 1024 + cc * 128 + cp * 4;
#pragma unroll
        for (int comp = 0; comp < 16; comp++) {
            uint32_t h, l;
            split2(d[0][comp], d[1][comp], h, l);
            *(uint32_t*)(base + (long)comp * XT_PLANE_B) = h;
            *(uint32_t*)(base + (long)comp * XT_PLANE_B + 64) = l;
        }
    }
}

// ---------------- multistage cp.async mma.sync GEMM (direct conv or Winograd) ----------------
// CTA: M=128 x N=128, 256 threads (8 warps 2m x 4n), 4 stages.
template <int CH, int CHT, int NW, bool FINAL, bool WINO>
__global__ __launch_bounds__(256) void conv_mma(
    const uint8_t* __restrict__ in, long inFrameB,
    const __nv_bfloat16* __restrict__ pw0, const __nv_bfloat16* __restrict__ pw1, int OCTOT,
    const float* __restrict__ bias,
    float* __restrict__ out0, float* __restrict__ out1, long outFrameStride)
{
    constexpr int ITERS = WINO ? CH : 9 * CH;
    constexpr int STAGE = 16384 * (1 + NW);
    extern __shared__ __align__(16) char dsm[];
    const uint32_t sb = s2u(dsm);
    const int t = threadIdx.x, lane = t & 31, w = t >> 5;
    const int tile = blockIdx.x, frame = blockIdx.y, oc0 = blockIdx.z * 128;
    const int p0 = tile * 128;
    const uint8_t* inF = in + (long)frame * inFrameB;
    const int wm = w >> 2, wn = w & 3;
    const int fp = t >> 1, fsub = (t & 1) * 4;
    const int prow = fp >> 6, pcol = fp & 63;

    auto issue = [&](int it) {
        const uint32_t bufB = sb + (it & 3) * STAGE;
        const uint32_t bufA = bufB + 16384;
        const uint8_t* srcB;
        int zf = 16;
        if (WINO) {
            srcB = inF + ((long)(p0 + fp) * CHT + it) * 128;
        } else {
            const int tap = it / CH, chk = it - tap * CH;
            const int dy = tap / 3 - 1, dx = tap - (tap / 3) * 3 - 1;
            const int gr = tile * 2 + prow + dy, gc = pcol + dx;
            const bool ok = ((unsigned)gr < 64u) & ((unsigned)gc < 64u);
            srcB = inF + ((long)(ok ? (gr * 64 + gc) : 0) * CHT + chk) * 128;
            zf = ok ? 16 : 0;
        }
#pragma unroll
        for (int i = 0; i < 4; i++) {
            int q = fsub + i;
            cp16z(bufB + fp * 128 + ((q ^ (fp & 7)) << 4), srcB + q * 16, zf);
        }
        const int itA = WINO ? frame * CH + it : it;
#pragma unroll
        for (int s = 0; s < NW; s++) {
            const __nv_bfloat16* pws = s ? pw1 : pw0;
            const uint8_t* srcA = (const uint8_t*)(pws + ((long)itA * OCTOT + oc0 + fp) * 64);
#pragma unroll
            for (int i = 0; i < 4; i++) {
                int q = fsub + i;
                cp16(bufA + s * 16384 + fp * 128 + ((q ^ (fp & 7)) << 4), srcA + q * 16);
            }
        }
    };

    float acc[NW][4][4][4];
#pragma unroll
    for (int s = 0; s < NW; s++)
#pragma unroll
        for (int i = 0; i < 4; i++)
#pragma unroll
            for (int j = 0; j < 4; j++)
#pragma unroll
                for (int r = 0; r < 4; r++) acc[s][i][j][r] = 0.f;

#pragma unroll
    for (int s = 0; s < 3; s++) {
        issue(s);
        asm volatile("cp.async.commit_group;" ::: "memory");
    }

    for (int it = 0; it < ITERS; ++it) {
        asm volatile("cp.async.wait_group 2;" ::: "memory");
        __syncthreads();
        const uint32_t bufB = sb + (it & 3) * STAGE;
        const uint32_t bufA = bufB + 16384;
#pragma unroll
        for (int ks = 0; ks < 2; ks++) {
            uint32_t Bh[2][4], Bl[2][4];
#pragma unroll
            for (int g = 0; g < 2; g++) {
                int p = wn * 32 + g * 16 + (lane & 15);
                uint32_t rb = bufB + p * 128;
                int p7 = p & 7, qh = ks * 2 + (lane >> 4);
                ldm4(rb + ((qh ^ p7) << 4), Bh[g]);
                ldm4(rb + (((qh + 4) ^ p7) << 4), Bl[g]);
            }
#pragma unroll
            for (int s = 0; s < NW; s++) {
#pragma unroll
                for (int i = 0; i < 4; i++) {
                    int r = wm * 64 + i * 16 + (lane & 15);
                    uint32_t ra = bufA + s * 16384 + r * 128;
                    int r7 = r & 7, qh = ks * 2 + (lane >> 4);
                    uint32_t Ah[4], Al[4];
                    ldm4(ra + ((qh ^ r7) << 4), Ah);
                    ldm4(ra + (((qh + 4) ^ r7) << 4), Al);
#pragma unroll
                    for (int j = 0; j < 4; j++) {
                        int g = j >> 1, rs = j & 1;
                        mma16816(acc[s][i][j], Ah, Bh[g][rs], Bh[g][rs + 2]);
                        mma16816(acc[s][i][j], Ah, Bl[g][rs], Bl[g][rs + 2]);
                        mma16816(acc[s][i][j], Al, Bh[g][rs], Bh[g][rs + 2]);
                    }
                }
            }
        }
        if (it + 3 < ITERS) issue(it + 3);
        asm volatile("cp.async.commit_group;" ::: "memory");
    }
    asm volatile("cp.async.wait_group 0;" ::: "memory");

    // ---- epilogue: stage [pix][oc], then coalesced store ----
    float* stage = (float*)dsm;
#pragma unroll
    for (int s = 0; s < NW; s++) {
        __syncthreads();
#pragma unroll
        for (int i = 0; i < 4; i++) {
            int m = wm * 64 + i * 16 + (lane >> 2);
#pragma unroll
            for (int j = 0; j < 4; j++) {
                int n = wn * 32 + j * 8 + (lane & 3) * 2;
                stage[n * 132 + m]           = acc[s][i][j][0];
                stage[(n + 1) * 132 + m]     = acc[s][i][j][1];
                stage[n * 132 + m + 8]       = acc[s][i][j][2];
                stage[(n + 1) * 132 + m + 8] = acc[s][i][j][3];
            }
        }
        __syncthreads();
        if (FINAL) {
            for (int idx = t; idx < 32 * 128; idx += 256) {
                const int pg = idx & 31, oc = idx >> 5;
                const float bv = bias[oc0 + oc];
                float4 v;
                v.x = stage[(pg * 4 + 0) * 132 + oc] + bv;
                v.y = stage[(pg * 4 + 1) * 132 + oc] + bv;
                v.z = stage[(pg * 4 + 2) * 132 + oc] + bv;
                v.w = stage[(pg * 4 + 3) * 132 + oc] + bv;
                float* ob = out0 + (long)frame * outFrameStride + (long)(oc0 + oc) * HW + p0 + pg * 4;
#pragma unroll
                for (int tt = 0; tt < 8; tt++)
                    *(float4*)(ob + (long)tt * CHWX) = v;
            }
        } else {
            float* outF = (s ? out1 : out0) + (long)frame * outFrameStride;
            for (int idx = t; idx < 128 * 32; idx += 256) {
                int p = idx >> 5, q = idx & 31;
                *(float4*)(outF + (long)(p0 + p) * 128 + q * 4) = *(float4*)(stage + p * 132 + q * 4);
            }
        }
    }
}

// ---- Winograd inverse transform: yt[set][comp][tileG][oc] -> gq/gv pixel-major ----
__global__ __launch_bounds__(256) void wino_out(const float* __restrict__ yt,
                                                float* __restrict__ gq, float* __restrict__ gv) {
    const int t = threadIdx.x;
    const int oc = t & 127;
    const long tile = (long)blockIdx.x * 2 + (t >> 7);
    const int set = blockIdx.y;
    const float* Y = yt + (long)set * YT_SET + tile * 128 + oc;
    float y[16];
#pragma unroll
    for (int c = 0; c < 16; c++) y[c] = Y[(long)c * 32768 * 128];
    float z[2][4];
#pragma unroll
    for (int j = 0; j < 4; j++) {
        z[0][j] = y[j] + y[4 + j] + y[8 + j];
        z[1][j] = y[4 + j] - y[8 + j] - y[12 + j];
    }
    const int f = (int)(tile >> 10), tloc = (int)(tile & 1023);
    const int ty = tloc >> 5, tx = tloc & 31;
    float* dst = (set ? gv : gq) + (long)f * PHW;
#pragma unroll
    for (int a = 0; a < 2; a++) {
        float o0 = z[a][0] + z[a][1] + z[a][2];
        float o1 = z[a][1] - z[a][2] - z[a][3];
        long row = (long)((2 * ty + a) * 64 + 2 * tx) * 128 + oc;
        dst[row] = o0;
        dst[row + 128] = o1;
    }
}

// ---------------- attention: warp per pixel; emits bf16-split pooled (gp2) ----------------
__global__ __launch_bounds__(256) void attn_tc(
    const float* __restrict__ q, const float* __restrict__ k,
    const float* __restrict__ v, uint8_t* __restrict__ gp2)
{
    const int wid = threadIdx.x >> 5, lane = threadIdx.x & 31;
    const int g = blockIdx.x * 8 + wid;
    const int b = g >> 12, pix = g & 4095;

    float4 k4 = ((const float4*)(k + ((long)b * HW + pix) * 128))[lane];

    float dots[8];
#pragma unroll
    for (int t = 0; t < 8; t++) {
        float4 q4 = ((const float4*)(q + ((long)((b * 8 + t) * HW) + pix) * 128))[lane];
        float d = q4.x * k4.x + q4.y * k4.y + q4.z * k4.z + q4.w * k4.w;
#pragma unroll
        for (int off = 16; off; off >>= 1) d += __shfl_xor_sync(0xFFFFFFFFu, d, off);
        dots[t] = d;
    }
    float m = dots[0];
#pragma unroll
    for (int t = 1; t < 8; t++) m = fmaxf(m, dots[t]);
    float a[8], s = 0.f;
#pragma unroll
    for (int t = 0; t < 8; t++) { a[t] = expf(dots[t] - m); s += a[t]; }
    float inv = 1.f / s;

    float4 acc = make_float4(0.f, 0.f, 0.f, 0.f);
#pragma unroll
    for (int t = 0; t < 8; t++) {
        float4 v4 = ((const float4*)(v + ((long)((b * 8 + t) * HW) + pix) * 128))[lane];
        float wgt = a[t] * inv;
        acc.x += wgt * v4.x; acc.y += wgt * v4.y; acc.z += wgt * v4.z; acc.w += wgt * v4.w;
    }
    uint32_t h0, l0, h1, l1;
    split2(acc.x, acc.y, h0, l0);
    split2(acc.z, acc.w, h1, l1);
    const int chunk = lane >> 3, pos = lane & 7;
    uint8_t* row = gp2 + (((long)(b * HW + pix)) * 4 + chunk) * 128;
    *(uint2*)(row + pos * 8) = make_uint2(h0, h1);
    *(uint2*)(row + 64 + pos * 8) = make_uint2(l0, l1);
}

// ---------------------------------------------------------------------------
extern "C" void kernel_launch(void* const* d_in, const int* in_sizes, int n_in,
                              void* d_out, int out_size)
{
    const float* x     = (const float*)d_in[0];
    const float* w_k   = (const float*)d_in[1];
    const float* w_q   = (const float*)d_in[2];
    const float* w_v   = (const float*)d_in[3];
    const float* w_out = (const float*)d_in[4];
    const float* b_out = (const float*)d_in[5];
    float* out = (float*)d_out;

    void* basev = nullptr;
    cudaGetSymbolAddress(&basev, g_scratch);
    float* S = (float*)basev;
    float*   gk  = S + OFF_GK;
    float*   gq  = S + OFF_GQ;
    float*   gv  = S + OFF_GV;
    uint8_t* gp2 = (uint8_t*)(S + OFF_GP2);
    uint8_t* xs  = (uint8_t*)(S + OFF_XS);
    __nv_bfloat16* pwk = (__nv_bfloat16*)(S + OFF_PWK);
    __nv_bfloat16* pwo = (__nv_bfloat16*)(S + OFF_PWO);
    __nv_bfloat16* wtq = (__nv_bfloat16*)(S + OFF_WTQ);
    __nv_bfloat16* wtv = (__nv_bfloat16*)(S + OFF_WTV);
    uint8_t* xt = (uint8_t*)(S + OFF_XT);
    float*   yt = S + OFF_YT;

    const int DSM1 = 4 * 32768;   // NW=1
    const int DSM2 = 4 * 49152;   // NW=2
    const int DSMW = 256 * 137 * 4;
    cudaFuncSetAttribute(conv_mma<8, 8, 1, false, false>, cudaFuncAttributeMaxDynamicSharedMemorySize, DSM1);
    cudaFuncSetAttribute(conv_mma<8, 8, 2, false, true>,  cudaFuncAttributeMaxDynamicSharedMemorySize, DSM2);
    cudaFuncSetAttribute(conv_mma<4, 4, 1, true, false>,  cudaFuncAttributeMaxDynamicSharedMemorySize, DSM1);
    cudaFuncSetAttribute(wino_in, cudaFuncAttributeMaxDynamicSharedMemorySize, DSMW);

    pack_w<<<1152, 256>>>(w_k, pwk, 128, 256);
    pack_w<<<1152, 256>>>(w_out, pwo, 256, 128);
    wino_w<<<128, 256>>>(w_q, wtq);
    wino_w<<<128, 256>>>(w_v, wtv);
    split_x4<<<dim3(128, 4), 256>>>(x, xs);
    wino_in<<<dim3(64, 32), 256, DSMW>>>(x, xt);

    const long FRAME_B = (long)HW * 8 * 128;   // xs per-frame bytes
    // k conv (direct): 4 key frames
    conv_mma<8, 8, 1, false, false><<<dim3(32, 4, 1), 256, DSM1>>>(
        xs, FRAME_B, pwk, nullptr, 128, nullptr, gk, nullptr, PHW);
    // fused q+v Winograd GEMM: 256 tile-blocks x 16 components
    conv_mma<8, 8, 2, false, true><<<dim3(256, 16, 1), 256, DSM2>>>(
        xt, XT_PLANE_B, wtq, wtv, 128, nullptr, yt, yt + YT_SET, 32768L * 128);
    // inverse transform -> pixel-major q, v
    wino_out<<<dim3(16384, 2), 256>>>(yt, gq, gv);
    // attention -> bf16-split pooled
    attn_tc<<<2048, 256>>>(gq, gk, gv, gp2);
    // out conv (direct): bias + T-broadcast
    const long GP_FRAME_B = (long)HW * 4 * 128;
    conv_mma<4, 4, 1, true, false><<<dim3(32, 4, 2), 256, DSM1>>>(
        gp2, GP_FRAME_B, pwo, nullptr, 256, b_out, out, nullptr, TCHWX);
}

// round 7
// speedup vs baseline: 4.9672x; 1.6099x over previous
#include <cuda_runtime.h>
#include <cuda_bf16.h>
#include <cstdint>

#define HW 4096
#define PHW ((long)HW * 128)          // fp32 pixel-major frame stride
#define CHWX ((long)256 * HW)         // x per-frame stride (floats)
#define TCHWX ((long)8 * CHWX)        // per-batch stride (floats)

// float offsets in g_scratch
#define OFF_GK  0L
#define OFF_GQ  2097152L
#define OFF_GV  18874368L
#define OFF_GP2 35651584L
#define OFF_XS  37748736L
#define OFF_PWK 41943040L
#define OFF_PWO 42237952L
#define OFF_WTQ 42532864L
#define OFF_WTV 43712512L
#define OFF_XT  44892160L             // F(4,3) transformed x, bf16 split (302MB)
#define OFF_YT  120389632L            // Winograd GEMM outputs fp32 (302MB)
__device__ __align__(256) float g_scratch[195887104];

#define XT_PLANE_B 8388608L           // bytes per component plane (8192 tiles x 1024B)
#define YT_PLANE   1048576L           // floats per component plane (8192 x 128)
#define YT_SET     37748736L          // floats per weight-set (36 planes)

// ---------------- helpers ----------------
__device__ __forceinline__ uint32_t s2u(const void* p) {
    uint32_t a;
    asm("{ .reg .u64 t; cvta.to.shared.u64 t, %1; cvt.u32.u64 %0, t; }" : "=r"(a) : "l"(p));
    return a;
}
__device__ __forceinline__ void split2(float f0, float f1, uint32_t& hi, uint32_t& lo) {
    uint32_t h;
    asm("cvt.rn.bf16x2.f32 %0, %1, %2;" : "=r"(h) : "f"(f1), "f"(f0));
    float h0 = __uint_as_float(h << 16);
    float h1 = __uint_as_float(h & 0xFFFF0000u);
    float l0 = f0 - h0, l1 = f1 - h1;
    uint32_t l;
    asm("cvt.rn.bf16x2.f32 %0, %1, %2;" : "=r"(l) : "f"(l1), "f"(l0));
    hi = h; lo = l;
}
__device__ __forceinline__ void ldm4(uint32_t a, uint32_t* r) {
    asm volatile("ldmatrix.sync.aligned.m8n8.x4.shared.b16 {%0,%1,%2,%3}, [%4];"
                 : "=r"(r[0]), "=r"(r[1]), "=r"(r[2]), "=r"(r[3]) : "r"(a));
}
__device__ __forceinline__ void mma16816(float* c, const uint32_t* a, uint32_t b0, uint32_t b1) {
    asm volatile("mma.sync.aligned.m16n8k16.row.col.f32.bf16.bf16.f32 "
                 "{%0,%1,%2,%3}, {%4,%5,%6,%7}, {%8,%9}, {%0,%1,%2,%3};"
                 : "+f"(c[0]), "+f"(c[1]), "+f"(c[2]), "+f"(c[3])
                 : "r"(a[0]), "r"(a[1]), "r"(a[2]), "r"(a[3]), "r"(b0), "r"(b1));
}
__device__ __forceinline__ void cp16(uint32_t d, const void* s) {
    asm volatile("cp.async.cg.shared.global [%0], [%1], 16;" :: "r"(d), "l"(s));
}
__device__ __forceinline__ void cp16z(uint32_t d, const void* s, int zf) {
    asm volatile("cp.async.cg.shared.global [%0], [%1], 16, %2;" :: "r"(d), "l"(s), "r"(zf));
}

// ---- weight pack (direct convs): w(OC,CIN,3,3) -> bf16 [it][oc][32 hi | 32 lo] ----
__global__ void pack_w(const float* __restrict__ src, __nv_bfloat16* __restrict__ dst, int OC, int CIN) {
    int CH = CIN >> 5;
    long total = (long)9 * CH * OC * 32;
    for (long i = (long)blockIdx.x * blockDim.x + threadIdx.x; i < total; i += (long)gridDim.x * blockDim.x) {
        int c = (int)(i & 31);
        long r = i >> 5;
        int oc = (int)(r % OC);
        int it = (int)(r / OC);
        int tap = it / CH, chk = it - tap * CH;
        float x = src[((long)oc * CIN + chk * 32 + c) * 9 + tap];
        __nv_bfloat16 hb = __float2bfloat16(x);
        float lo = x - __bfloat162float(hb);
        dst[((long)it * OC + oc) * 64 + c] = hb;
        dst[((long)it * OC + oc) * 64 + 32 + c] = __float2bfloat16(lo);
    }
}

// ---- F(4,3) weight transform: w(128,256,3,3) -> wt[comp36*8+chunk][oc128][32hi|32lo] ----
__global__ void wino_w(const float* __restrict__ src, __nv_bfloat16* __restrict__ dst) {
    int t = blockIdx.x * blockDim.x + threadIdx.x;
    if (t >= 128 * 256) return;
    int ic = t & 255, oc = t >> 8;
    float g[3][3];
#pragma unroll
    for (int r = 0; r < 3; r++)
#pragma unroll
        for (int c = 0; c < 3; c++)
            g[r][c] = src[((long)oc * 256 + ic) * 9 + r * 3 + c];
    const float i6 = 1.f / 6.f, i12 = 1.f / 12.f, i24 = 1.f / 24.f;
    float R[6][3];
#pragma unroll
    for (int c = 0; c < 3; c++) {
        R[0][c] = 0.25f * g[0][c];
        R[1][c] = -i6 * (g[0][c] + g[1][c] + g[2][c]);
        R[2][c] = i6 * (-g[0][c] + g[1][c] - g[2][c]);
        R[3][c] = i24 * g[0][c] + i12 * g[1][c] + i6 * g[2][c];
        R[4][c] = i24 * g[0][c] - i12 * g[1][c] + i6 * g[2][c];
        R[5][c] = g[2][c];
    }
    float U[6][6];
#pragma unroll
    for (int r = 0; r < 6; r++) {
        U[r][0] = 0.25f * R[r][0];
        U[r][1] = -i6 * (R[r][0] + R[r][1] + R[r][2]);
        U[r][2] = i6 * (-R[r][0] + R[r][1] - R[r][2]);
        U[r][3] = i24 * R[r][0] + i12 * R[r][1] + i6 * R[r][2];
        U[r][4] = i24 * R[r][0] - i12 * R[r][1] + i6 * R[r][2];
        U[r][5] = R[r][2];
    }
#pragma unroll
    for (int comp = 0; comp < 36; comp++) {
        float x = U[comp / 6][comp % 6];
        __nv_bfloat16 hb = __float2bfloat16(x);
        float lo = x - __bfloat162float(hb);
        long base = ((long)(comp * 8 + (ic >> 5)) * 128 + oc) * 64 + (ic & 31);
        dst[base] = hb;
        dst[base + 32] = __float2bfloat16(lo);
    }
}

// ---- x pre-split (k conv): frames {0,8,16,24} -> xs[4][pix][chunk8][32hi|32lo] ----
__global__ __launch_bounds__(256) void split_x4(const float* __restrict__ x, uint8_t* __restrict__ xs) {
    __shared__ float sm[256][33];
    const int p0 = blockIdx.x * 32;
    const int t = threadIdx.x;
    const float* xf = x + (long)(blockIdx.y * 8) * CHWX;
    const int pix = t & 31, cb = t >> 5;
#pragma unroll 8
    for (int i = 0; i < 32; i++) {
        int ch = cb * 32 + i;
        sm[ch][pix] = xf[(long)ch * HW + p0 + pix];
    }
    __syncthreads();
    uint8_t* of = xs + ((long)blockIdx.y * HW + p0) * 1024;
#pragma unroll
    for (int o = 0; o < 8; o++) {
        int n = t + o * 256;
        int p = n >> 6, q = n & 63;
        int chunk = q >> 3, qq = q & 7;
        bool hip = qq < 4;
        int chb = chunk * 32 + (hip ? qq * 8 : (qq - 4) * 8);
        uint32_t r[4];
#pragma unroll
        for (int j = 0; j < 4; j++) {
            uint32_t h, l;
            split2(sm[chb + 2 * j][p], sm[chb + 2 * j + 1][p], h, l);
            r[j] = hip ? h : l;
        }
        *(uint4*)(of + (long)p * 1024 + q * 16) = make_uint4(r[0], r[1], r[2], r[3]);
    }
}

// ---- F(4,3) input transform: x -> xt[comp][tileG][chunk8][32hi|32lo bf16] ----
// CTA = (tile-row ty, frame); 16 tiles x 6 rows x 66 cols, chunked by 32 channels.
__global__ __launch_bounds__(256) void wino_in(const float* __restrict__ x, uint8_t* __restrict__ xt) {
    extern __shared__ float sm[];   // [32 ch][6 rows][67]
    const int f = blockIdx.y, ty = blockIdx.x;
    const int t = threadIdx.x;
    const float* xf = x + (long)f * CHWX;
    const int gr0 = 4 * ty - 1;
    const int tx = t >> 4, j = t & 15;
    const long tileG = (long)f * 256 + ty * 16 + tx;

    for (int cc = 0; cc < 8; cc++) {
        __syncthreads();
        for (int idx = t; idx < 32 * 6 * 66; idx += 256) {
            int c = idx % 66;
            int rc = idx / 66;
            int r = rc % 6, ch = rc / 6;
            int gr = gr0 + r, gc = c - 1;
            float v = ((unsigned)gr < 64u && (unsigned)gc < 64u)
                          ? xf[(long)(cc * 32 + ch) * HW + gr * 64 + gc] : 0.f;
            sm[(ch * 6 + r) * 67 + c] = v;
        }
        __syncthreads();
        float D[2][36];
#pragma unroll
        for (int e = 0; e < 2; e++) {
            const float* s = sm + (2 * j + e) * 402 + 4 * tx;
            float T[6][6];
#pragma unroll
            for (int c = 0; c < 6; c++) {
                float x0 = s[c], x1 = s[67 + c], x2 = s[134 + c],
                      x3 = s[201 + c], x4 = s[268 + c], x5 = s[335 + c];
                T[0][c] = 4.f * x0 - 5.f * x2 + x4;
                T[1][c] = -4.f * x1 - 4.f * x2 + x3 + x4;
                T[2][c] = 4.f * x1 - 4.f * x2 - x3 + x4;
                T[3][c] = -2.f * x1 - x2 + 2.f * x3 + x4;
                T[4][c] = 2.f * x1 - x2 - 2.f * x3 + x4;
                T[5][c] = 4.f * x1 - 5.f * x3 + x5;
            }
#pragma unroll
            for (int r = 0; r < 6; r++) {
                float t0 = T[r][0], t1 = T[r][1], t2 = T[r][2],
                      t3 = T[r][3], t4 = T[r][4], t5 = T[r][5];
                D[e][r * 6 + 0] = 4.f * t0 - 5.f * t2 + t4;
                D[e][r * 6 + 1] = -4.f * t1 - 4.f * t2 + t3 + t4;
                D[e][r * 6 + 2] = 4.f * t1 - 4.f * t2 - t3 + t4;
                D[e][r * 6 + 3] = -2.f * t1 - t2 + 2.f * t3 + t4;
                D[e][r * 6 + 4] = 2.f * t1 - t2 - 2.f * t3 + t4;
                D[e][r * 6 + 5] = 4.f * t1 - 5.f * t3 + t5;
            }
        }
        uint8_t* base = xt + tileG * 1024 + cc * 128 + j * 4;
#pragma unroll
        for (int comp = 0; comp < 36; comp++) {
            uint32_t h, l;
            split2(D[0][comp], D[1][comp], h, l);
            *(uint32_t*)(base + (long)comp * XT_PLANE_B) = h;
            *(uint32_t*)(base + (long)comp * XT_PLANE_B + 64) = l;
        }
    }
}

// ---------------- multistage cp.async mma.sync GEMM (direct conv or Winograd) ----------------
template <int CH, int CHT, int NW, bool FINAL, bool WINO>
__global__ __launch_bounds__(256) void conv_mma(
    const uint8_t* __restrict__ in, long inFrameB,
    const __nv_bfloat16* __restrict__ pw0, const __nv_bfloat16* __restrict__ pw1, int OCTOT,
    const float* __restrict__ bias,
    float* __restrict__ out0, float* __restrict__ out1, long outFrameStride)
{
    constexpr int ITERS = WINO ? CH : 9 * CH;
    constexpr int STAGE = 16384 * (1 + NW);
    extern __shared__ __align__(16) char dsm[];
    const uint32_t sb = s2u(dsm);
    const int t = threadIdx.x, lane = t & 31, w = t >> 5;
    const int tile = blockIdx.x, frame = blockIdx.y, oc0 = blockIdx.z * 128;
    const int p0 = tile * 128;
    const uint8_t* inF = in + (long)frame * inFrameB;
    const int wm = w >> 2, wn = w & 3;
    const int fp = t >> 1, fsub = (t & 1) * 4;
    const int prow = fp >> 6, pcol = fp & 63;

    auto issue = [&](int it) {
        const uint32_t bufB = sb + (it & 3) * STAGE;
        const uint32_t bufA = bufB + 16384;
        const uint8_t* srcB;
        int zf = 16;
        if (WINO) {
            srcB = inF + ((long)(p0 + fp) * CHT + it) * 128;
        } else {
            const int tap = it / CH, chk = it - tap * CH;
            const int dy = tap / 3 - 1, dx = tap - (tap / 3) * 3 - 1;
            const int gr = tile * 2 + prow + dy, gc = pcol + dx;
            const bool ok = ((unsigned)gr < 64u) & ((unsigned)gc < 64u);
            srcB = inF + ((long)(ok ? (gr * 64 + gc) : 0) * CHT + chk) * 128;
            zf = ok ? 16 : 0;
        }
#pragma unroll
        for (int i = 0; i < 4; i++) {
            int q = fsub + i;
            cp16z(bufB + fp * 128 + ((q ^ (fp & 7)) << 4), srcB + q * 16, zf);
        }
        const int itA = WINO ? frame * CH + it : it;
#pragma unroll
        for (int s = 0; s < NW; s++) {
            const __nv_bfloat16* pws = s ? pw1 : pw0;
            const uint8_t* srcA = (const uint8_t*)(pws + ((long)itA * OCTOT + oc0 + fp) * 64);
#pragma unroll
            for (int i = 0; i < 4; i++) {
                int q = fsub + i;
                cp16(bufA + s * 16384 + fp * 128 + ((q ^ (fp & 7)) << 4), srcA + q * 16);
            }
        }
    };

    float acc[NW][4][4][4];
#pragma unroll
    for (int s = 0; s < NW; s++)
#pragma unroll
        for (int i = 0; i < 4; i++)
#pragma unroll
            for (int j = 0; j < 4; j++)
#pragma unroll
                for (int r = 0; r < 4; r++) acc[s][i][j][r] = 0.f;

#pragma unroll
    for (int s = 0; s < 3; s++) {
        issue(s);
        asm volatile("cp.async.commit_group;" ::: "memory");
    }

    for (int it = 0; it < ITERS; ++it) {
        asm volatile("cp.async.wait_group 2;" ::: "memory");
        __syncthreads();
        const uint32_t bufB = sb + (it & 3) * STAGE;
        const uint32_t bufA = bufB + 16384;
#pragma unroll
        for (int ks = 0; ks < 2; ks++) {
            uint32_t Bh[2][4], Bl[2][4];
#pragma unroll
            for (int g = 0; g < 2; g++) {
                int p = wn * 32 + g * 16 + (lane & 15);
                uint32_t rb = bufB + p * 128;
                int p7 = p & 7, qh = ks * 2 + (lane >> 4);
                ldm4(rb + ((qh ^ p7) << 4), Bh[g]);
                ldm4(rb + (((qh + 4) ^ p7) << 4), Bl[g]);
            }
#pragma unroll
            for (int s = 0; s < NW; s++) {
#pragma unroll
                for (int i = 0; i < 4; i++) {
                    int r = wm * 64 + i * 16 + (lane & 15);
                    uint32_t ra = bufA + s * 16384 + r * 128;
                    int r7 = r & 7, qh = ks * 2 + (lane >> 4);
                    uint32_t Ah[4], Al[4];
                    ldm4(ra + ((qh ^ r7) << 4), Ah);
                    ldm4(ra + (((qh + 4) ^ r7) << 4), Al);
#pragma unroll
                    for (int j = 0; j < 4; j++) {
                        int g = j >> 1, rs = j & 1;
                        mma16816(acc[s][i][j], Ah, Bh[g][rs], Bh[g][rs + 2]);
                        mma16816(acc[s][i][j], Ah, Bl[g][rs], Bl[g][rs + 2]);
                        mma16816(acc[s][i][j], Al, Bh[g][rs], Bh[g][rs + 2]);
                    }
                }
            }
        }
        if (it + 3 < ITERS) issue(it + 3);
        asm volatile("cp.async.commit_group;" ::: "memory");
    }
    asm volatile("cp.async.wait_group 0;" ::: "memory");

    // ---- epilogue ----
    float* stage = (float*)dsm;
#pragma unroll
    for (int s = 0; s < NW; s++) {
        __syncthreads();
#pragma unroll
        for (int i = 0; i < 4; i++) {
            int m = wm * 64 + i * 16 + (lane >> 2);
#pragma unroll
            for (int j = 0; j < 4; j++) {
                int n = wn * 32 + j * 8 + (lane & 3) * 2;
                stage[n * 132 + m]           = acc[s][i][j][0];
                stage[(n + 1) * 132 + m]     = acc[s][i][j][1];
                stage[n * 132 + m + 8]       = acc[s][i][j][2];
                stage[(n + 1) * 132 + m + 8] = acc[s][i][j][3];
            }
        }
        __syncthreads();
        if (FINAL) {
            for (int idx = t; idx < 32 * 128; idx += 256) {
                const int pg = idx & 31, oc = idx >> 5;
                const float bv = bias[oc0 + oc];
                float4 v;
                v.x = stage[(pg * 4 + 0) * 132 + oc] + bv;
                v.y = stage[(pg * 4 + 1) * 132 + oc] + bv;
                v.z = stage[(pg * 4 + 2) * 132 + oc] + bv;
                v.w = stage[(pg * 4 + 3) * 132 + oc] + bv;
                float* ob = out0 + (long)frame * outFrameStride + (long)(oc0 + oc) * HW + p0 + pg * 4;
#pragma unroll
                for (int tt = 0; tt < 8; tt++)
                    *(float4*)(ob + (long)tt * CHWX) = v;
            }
        } else {
            float* outF = (s ? out1 : out0) + (long)frame * outFrameStride;
            for (int idx = t; idx < 128 * 32; idx += 256) {
                int p = idx >> 5, q = idx & 31;
                *(float4*)(outF + (long)(p0 + p) * 128 + q * 4) = *(float4*)(stage + p * 132 + q * 4);
            }
        }
    }
}

// ---- F(4,3) inverse transform: yt[set][comp][tile][oc] -> gq/gv pixel-major ----
__global__ __launch_bounds__(256) void wino_out(const float* __restrict__ yt,
                                                float* __restrict__ gq, float* __restrict__ gv) {
    const int t = threadIdx.x;
    const int oc = t & 127;
    const long tile = (long)blockIdx.x * 2 + (t >> 7);
    const int set = blockIdx.y;
    const float* Y = yt + (long)set * YT_SET + tile * 128 + oc;
    float y[36];
#pragma unroll
    for (int c = 0; c < 36; c++) y[c] = Y[(long)c * YT_PLANE];
    float Z[4][6];
#pragma unroll
    for (int c = 0; c < 6; c++) {
        float a0 = y[c], a1 = y[6 + c], a2 = y[12 + c],
              a3 = y[18 + c], a4 = y[24 + c], a5 = y[30 + c];
        Z[0][c] = a0 + a1 + a2 + a3 + a4;
        Z[1][c] = a1 - a2 + 2.f * a3 - 2.f * a4;
        Z[2][c] = a1 + a2 + 4.f * a3 + 4.f * a4;
        Z[3][c] = a1 - a2 + 8.f * a3 - 8.f * a4 + a5;
    }
    const int f = (int)(tile >> 8), tloc = (int)(tile & 255);
    const int ty = tloc >> 4, tx = tloc & 15;
    float* dst = (set ? gv : gq) + (long)f * PHW;
#pragma unroll
    for (int a = 0; a < 4; a++) {
        float z0 = Z[a][0], z1 = Z[a][1], z2 = Z[a][2],
              z3 = Z[a][3], z4 = Z[a][4], z5 = Z[a][5];
        float o0 = z0 + z1 + z2 + z3 + z4;
        float o1 = z1 - z2 + 2.f * z3 - 2.f * z4;
        float o2 = z1 + z2 + 4.f * z3 + 4.f * z4;
        float o3 = z1 - z2 + 8.f * z3 - 8.f * z4 + z5;
        long row = (long)((4 * ty + a) * 64 + 4 * tx) * 128 + oc;
        dst[row] = o0;
        dst[row + 128] = o1;
        dst[row + 256] = o2;
        dst[row + 384] = o3;
    }
}

// ---------------- attention: warp per pixel; emits bf16-split pooled (gp2) ----------------
__global__ __launch_bounds__(256) void attn_tc(
    const float* __restrict__ q, const float* __restrict__ k,
    const float* __restrict__ v, uint8_t* __restrict__ gp2)
{
    const int wid = threadIdx.x >> 5, lane = threadIdx.x & 31;
    const int g = blockIdx.x * 8 + wid;
    const int b = g >> 12, pix = g & 4095;

    float4 k4 = ((const float4*)(k + ((long)b * HW + pix) * 128))[lane];

    float dots[8];
#pragma unroll
    for (int t = 0; t < 8; t++) {
        float4 q4 = ((const float4*)(q + ((long)((b * 8 + t) * HW) + pix) * 128))[lane];
        float d = q4.x * k4.x + q4.y * k4.y + q4.z * k4.z + q4.w * k4.w;
#pragma unroll
        for (int off = 16; off; off >>= 1) d += __shfl_xor_sync(0xFFFFFFFFu, d, off);
        dots[t] = d;
    }
    float m = dots[0];
#pragma unroll
    for (int t = 1; t < 8; t++) m = fmaxf(m, dots[t]);
    float a[8], s = 0.f;
#pragma unroll
    for (int t = 0; t < 8; t++) { a[t] = expf(dots[t] - m); s += a[t]; }
    float inv = 1.f / s;

    float4 acc = make_float4(0.f, 0.f, 0.f, 0.f);
#pragma unroll
    for (int t = 0; t < 8; t++) {
        float4 v4 = ((const float4*)(v + ((long)((b * 8 + t) * HW) + pix) * 128))[lane];
        float wgt = a[t] * inv;
        acc.x += wgt * v4.x; acc.y += wgt * v4.y; acc.z += wgt * v4.z; acc.w += wgt * v4.w;
    }
    uint32_t h0, l0, h1, l1;
    split2(acc.x, acc.y, h0, l0);
    split2(acc.z, acc.w, h1, l1);
    const int chunk = lane >> 3, pos = lane & 7;
    uint8_t* row = gp2 + (((long)(b * HW + pix)) * 4 + chunk) * 128;
    *(uint2*)(row + pos * 8) = make_uint2(h0, h1);
    *(uint2*)(row + 64 + pos * 8) = make_uint2(l0, l1);
}

// ---------------------------------------------------------------------------
extern "C" void kernel_launch(void* const* d_in, const int* in_sizes, int n_in,
                              void* d_out, int out_size)
{
    const float* x     = (const float*)d_in[0];
    const float* w_k   = (const float*)d_in[1];
    const float* w_q   = (const float*)d_in[2];
    const float* w_v   = (const float*)d_in[3];
    const float* w_out = (const float*)d_in[4];
    const float* b_out = (const float*)d_in[5];
    float* out = (float*)d_out;

    void* basev = nullptr;
    cudaGetSymbolAddress(&basev, g_scratch);
    float* S = (float*)basev;
    float*   gk  = S + OFF_GK;
    float*   gq  = S + OFF_GQ;
    float*   gv  = S + OFF_GV;
    uint8_t* gp2 = (uint8_t*)(S + OFF_GP2);
    uint8_t* xs  = (uint8_t*)(S + OFF_XS);
    __nv_bfloat16* pwk = (__nv_bfloat16*)(S + OFF_PWK);
    __nv_bfloat16* pwo = (__nv_bfloat16*)(S + OFF_PWO);
    __nv_bfloat16* wtq = (__nv_bfloat16*)(S + OFF_WTQ);
    __nv_bfloat16* wtv = (__nv_bfloat16*)(S + OFF_WTV);
    uint8_t* xt = (uint8_t*)(S + OFF_XT);
    float*   yt = S + OFF_YT;

    const int DSM1 = 4 * 32768;
    const int DSM2 = 4 * 49152;
    const int DSMW = 32 * 6 * 67 * 4;   // 51456
    cudaFuncSetAttribute(conv_mma<8, 8, 1, false, false>, cudaFuncAttributeMaxDynamicSharedMemorySize, DSM1);
    cudaFuncSetAttribute(conv_mma<8, 8, 2, false, true>,  cudaFuncAttributeMaxDynamicSharedMemorySize, DSM2);
    cudaFuncSetAttribute(conv_mma<4, 4, 1, true, false>,  cudaFuncAttributeMaxDynamicSharedMemorySize, DSM1);
    cudaFuncSetAttribute(wino_in, cudaFuncAttributeMaxDynamicSharedMemorySize, DSMW);

    pack_w<<<1152, 256>>>(w_k, pwk, 128, 256);
    pack_w<<<1152, 256>>>(w_out, pwo, 256, 128);
    wino_w<<<128, 256>>>(w_q, wtq);
    wino_w<<<128, 256>>>(w_v, wtv);
    split_x4<<<dim3(128, 4), 256>>>(x, xs);
    wino_in<<<dim3(16, 32), 256, DSMW>>>(x, xt);

    const long FRAME_B = (long)HW * 8 * 128;
    // k conv (direct): 4 key frames
    conv_mma<8, 8, 1, false, false><<<dim3(32, 4, 1), 256, DSM1>>>(
        xs, FRAME_B, pwk, nullptr, 128, nullptr, gk, nullptr, PHW);
    // fused q+v F(4,3) Winograd GEMM: 64 tile-blocks x 36 components
    conv_mma<8, 8, 2, false, true><<<dim3(64, 36, 1), 256, DSM2>>>(
        xt, XT_PLANE_B, wtq, wtv, 128, nullptr, yt, yt + YT_SET, YT_PLANE);
    // inverse transform -> pixel-major q, v
    wino_out<<<dim3(4096, 2), 256>>>(yt, gq, gv);
    // attention -> bf16-split pooled
    attn_tc<<<2048, 256>>>(gq, gk, gv, gp2);
    // out conv (direct): bias + T-broadcast
    const long GP_FRAME_B = (long)HW * 4 * 128;
    conv_mma<4, 4, 1, true, false><<<dim3(32, 4, 2), 256, DSM1>>>(
        gp2, GP_FRAME_B, pwo, nullptr, 256, b_out, out, nullptr, TCHWX);
}

// round 8
// speedup vs baseline: 5.3330x; 1.0737x over previous
#include <cuda_runtime.h>
#include <cuda_bf16.h>
#include <cstdint>

#define HW 4096
#define PHW ((long)HW * 128)          // fp32 pixel-major frame stride
#define CHWX ((long)256 * HW)         // x per-frame stride (floats)
#define TCHWX ((long)8 * CHWX)        // per-batch stride (floats)

// float offsets in g_scratch
#define OFF_GK  0L
#define OFF_GQ  2097152L
#define OFF_GV  18874368L
#define OFF_GP2 35651584L
#define OFF_PWO 37748736L
#define OFF_WTQ 38043648L
#define OFF_WTV 39223296L
#define OFF_WTK 40402944L
#define OFF_XT  41582592L             // F(4,3) transformed x, bf16 split (302MB)
#define OFF_YT  117080064L            // q/v GEMM outputs fp32 (2 x 151MB)
#define OFF_YTK 192577536L            // k GEMM output fp32 (19MB)
__device__ __align__(256) float g_scratch[197296128];

#define XT_PLANE_B 8388608L           // bytes per component plane (8192 tiles x 1024B)
#define YT_PLANE   1048576L           // floats per component plane (8192 x 128)
#define YT_SET     37748736L          // floats per q/v weight-set (36 planes)
#define YTK_PLANE  131072L            // floats per k component plane (1024 x 128)

// ---------------- helpers ----------------
__device__ __forceinline__ uint32_t s2u(const void* p) {
    uint32_t a;
    asm("{ .reg .u64 t; cvta.to.shared.u64 t, %1; cvt.u32.u64 %0, t; }" : "=r"(a) : "l"(p));
    return a;
}
__device__ __forceinline__ void split2(float f0, float f1, uint32_t& hi, uint32_t& lo) {
    uint32_t h;
    asm("cvt.rn.bf16x2.f32 %0, %1, %2;" : "=r"(h) : "f"(f1), "f"(f0));
    float h0 = __uint_as_float(h << 16);
    float h1 = __uint_as_float(h & 0xFFFF0000u);
    float l0 = f0 - h0, l1 = f1 - h1;
    uint32_t l;
    asm("cvt.rn.bf16x2.f32 %0, %1, %2;" : "=r"(l) : "f"(l1), "f"(l0));
    hi = h; lo = l;
}
__device__ __forceinline__ void ldm4(uint32_t a, uint32_t* r) {
    asm volatile("ldmatrix.sync.aligned.m8n8.x4.shared.b16 {%0,%1,%2,%3}, [%4];"
                 : "=r"(r[0]), "=r"(r[1]), "=r"(r[2]), "=r"(r[3]) : "r"(a));
}
__device__ __forceinline__ void mma16816(float* c, const uint32_t* a, uint32_t b0, uint32_t b1) {
    asm volatile("mma.sync.aligned.m16n8k16.row.col.f32.bf16.bf16.f32 "
                 "{%0,%1,%2,%3}, {%4,%5,%6,%7}, {%8,%9}, {%0,%1,%2,%3};"
                 : "+f"(c[0]), "+f"(c[1]), "+f"(c[2]), "+f"(c[3])
                 : "r"(a[0]), "r"(a[1]), "r"(a[2]), "r"(a[3]), "r"(b0), "r"(b1));
}
__device__ __forceinline__ void cp16(uint32_t d, const void* s) {
    asm volatile("cp.async.cg.shared.global [%0], [%1], 16;" :: "r"(d), "l"(s));
}
__device__ __forceinline__ void cp16z(uint32_t d, const void* s, int zf) {
    asm volatile("cp.async.cg.shared.global [%0], [%1], 16, %2;" :: "r"(d), "l"(s), "r"(zf));
}
__device__ __forceinline__ void cp_commit() { asm volatile("cp.async.commit_group;" ::: "memory"); }

// ---- weight pack (direct out conv): w(OC,CIN,3,3) -> bf16 [it][oc][32 hi | 32 lo] ----
__global__ void pack_w(const float* __restrict__ src, __nv_bfloat16* __restrict__ dst, int OC, int CIN) {
    int CH = CIN >> 5;
    long total = (long)9 * CH * OC * 32;
    for (long i = (long)blockIdx.x * blockDim.x + threadIdx.x; i < total; i += (long)gridDim.x * blockDim.x) {
        int c = (int)(i & 31);
        long r = i >> 5;
        int oc = (int)(r % OC);
        int it = (int)(r / OC);
        int tap = it / CH, chk = it - tap * CH;
        float x = src[((long)oc * CIN + chk * 32 + c) * 9 + tap];
        __nv_bfloat16 hb = __float2bfloat16(x);
        float lo = x - __bfloat162float(hb);
        dst[((long)it * OC + oc) * 64 + c] = hb;
        dst[((long)it * OC + oc) * 64 + 32 + c] = __float2bfloat16(lo);
    }
}

// ---- F(4,3) weight transform: w(128,256,3,3) -> wt[comp36*8+chunk][oc128][32hi|32lo] ----
__global__ void wino_w(const float* __restrict__ src, __nv_bfloat16* __restrict__ dst) {
    int t = blockIdx.x * blockDim.x + threadIdx.x;
    if (t >= 128 * 256) return;
    int ic = t & 255, oc = t >> 8;
    float g[3][3];
#pragma unroll
    for (int r = 0; r < 3; r++)
#pragma unroll
        for (int c = 0; c < 3; c++)
            g[r][c] = src[((long)oc * 256 + ic) * 9 + r * 3 + c];
    const float i6 = 1.f / 6.f, i12 = 1.f / 12.f, i24 = 1.f / 24.f;
    float R[6][3];
#pragma unroll
    for (int c = 0; c < 3; c++) {
        R[0][c] = 0.25f * g[0][c];
        R[1][c] = -i6 * (g[0][c] + g[1][c] + g[2][c]);
        R[2][c] = i6 * (-g[0][c] + g[1][c] - g[2][c]);
        R[3][c] = i24 * g[0][c] + i12 * g[1][c] + i6 * g[2][c];
        R[4][c] = i24 * g[0][c] - i12 * g[1][c] + i6 * g[2][c];
        R[5][c] = g[2][c];
    }
    float U[6][6];
#pragma unroll
    for (int r = 0; r < 6; r++) {
        U[r][0] = 0.25f * R[r][0];
        U[r][1] = -i6 * (R[r][0] + R[r][1] + R[r][2]);
        U[r][2] = i6 * (-R[r][0] + R[r][1] - R[r][2]);
        U[r][3] = i24 * R[r][0] + i12 * R[r][1] + i6 * R[r][2];
        U[r][4] = i24 * R[r][0] - i12 * R[r][1] + i6 * R[r][2];
        U[r][5] = R[r][2];
    }
#pragma unroll
    for (int comp = 0; comp < 36; comp++) {
        float x = U[comp / 6][comp % 6];
        __nv_bfloat16 hb = __float2bfloat16(x);
        float lo = x - __bfloat162float(hb);
        long base = ((long)(comp * 8 + (ic >> 5)) * 128 + oc) * 64 + (ic & 31);
        dst[base] = hb;
        dst[base + 32] = __float2bfloat16(lo);
    }
}

// ---- F(4,3) input transform: x -> xt[comp][tileG][chunk8][32hi|32lo bf16] ----
__global__ __launch_bounds__(256) void wino_in(const float* __restrict__ x, uint8_t* __restrict__ xt) {
    extern __shared__ float sm[];   // [32 ch][6 rows][67]
    const int f = blockIdx.y, ty = blockIdx.x;
    const int t = threadIdx.x;
    const float* xf = x + (long)f * CHWX;
    const int gr0 = 4 * ty - 1;
    const int tx = t >> 4, j = t & 15;
    const long tileG = (long)f * 256 + ty * 16 + tx;

    for (int cc = 0; cc < 8; cc++) {
        __syncthreads();
        for (int idx = t; idx < 32 * 6 * 66; idx += 256) {
            int c = idx % 66;
            int rc = idx / 66;
            int r = rc % 6, ch = rc / 6;
            int gr = gr0 + r, gc = c - 1;
            float v = ((unsigned)gr < 64u && (unsigned)gc < 64u)
                          ? xf[(long)(cc * 32 + ch) * HW + gr * 64 + gc] : 0.f;
            sm[(ch * 6 + r) * 67 + c] = v;
        }
        __syncthreads();
        float D[2][36];
#pragma unroll
        for (int e = 0; e < 2; e++) {
            const float* s = sm + (2 * j + e) * 402 + 4 * tx;
            float T[6][6];
#pragma unroll
            for (int c = 0; c < 6; c++) {
                float x0 = s[c], x1 = s[67 + c], x2 = s[134 + c],
                      x3 = s[201 + c], x4 = s[268 + c], x5 = s[335 + c];
                T[0][c] = 4.f * x0 - 5.f * x2 + x4;
                T[1][c] = -4.f * x1 - 4.f * x2 + x3 + x4;
                T[2][c] = 4.f * x1 - 4.f * x2 - x3 + x4;
                T[3][c] = -2.f * x1 - x2 + 2.f * x3 + x4;
                T[4][c] = 2.f * x1 - x2 - 2.f * x3 + x4;
                T[5][c] = 4.f * x1 - 5.f * x3 + x5;
            }
#pragma unroll
            for (int r = 0; r < 6; r++) {
                float t0 = T[r][0], t1 = T[r][1], t2 = T[r][2],
                      t3 = T[r][3], t4 = T[r][4], t5 = T[r][5];
                D[e][r * 6 + 0] = 4.f * t0 - 5.f * t2 + t4;
                D[e][r * 6 + 1] = -4.f * t1 - 4.f * t2 + t3 + t4;
                D[e][r * 6 + 2] = 4.f * t1 - 4.f * t2 - t3 + t4;
                D[e][r * 6 + 3] = -2.f * t1 - t2 + 2.f * t3 + t4;
                D[e][r * 6 + 4] = 2.f * t1 - t2 - 2.f * t3 + t4;
                D[e][r * 6 + 5] = 4.f * t1 - 5.f * t3 + t5;
            }
        }
        uint8_t* base = xt + tileG * 1024 + cc * 128 + j * 4;
#pragma unroll
        for (int comp = 0; comp < 36; comp++) {
            uint32_t h, l;
            split2(D[0][comp], D[1][comp], h, l);
            *(uint32_t*)(base + (long)comp * XT_PLANE_B) = h;
            *(uint32_t*)(base + (long)comp * XT_PLANE_B + 64) = l;
        }
    }
}

// ---------------- persistent Winograd GEMM (3-term bf16, mma.sync) ----------------
// Work item = (tile-block of 128 tiles, component). K=256 over 8 chunk-iters.
// 4-stage cp.async pipeline continues ACROSS items; buffer 3 is free during
// epilogues (in-flight = buffers 0,1,2) and doubles as the staging buffer.
template <int NW, bool KMAP>
__global__ __launch_bounds__(256) void wino_gemm_p(
    const uint8_t* __restrict__ xt,
    const __nv_bfloat16* __restrict__ wt0, const __nv_bfloat16* __restrict__ wt1,
    float* __restrict__ yt0, float* __restrict__ yt1,
    int nItems, long ytPlane)
{
    constexpr int STAGE = 16384 * (1 + NW);
    extern __shared__ __align__(16) char dsm[];
    const uint32_t sb = s2u(dsm);
    const int t = threadIdx.x, lane = t & 31, w = t >> 5;
    const int wm = w >> 2, wn = w & 3;
    const int fp = t >> 1, fsub = (t & 1) * 4;

    const int nloc = (nItems - blockIdx.x + gridDim.x - 1) / gridDim.x;
    if (nloc <= 0) return;
    const int totalP = nloc * 8;

    auto issue = [&](int p) {
        const int j = p >> 3, it = p & 7;
        const int item = blockIdx.x + j * (int)gridDim.x;
        int comp; long tileB0;
        if (KMAP) { comp = item >> 3; int tb = item & 7; tileB0 = (long)(tb >> 1) * 2048 + (tb & 1) * 128; }
        else      { comp = item >> 6; tileB0 = (long)(item & 63) * 128; }
        const uint32_t bufB = sb + (p & 3) * STAGE;
        const uint32_t bufA = bufB + 16384;
        const uint8_t* srcB = xt + (long)comp * XT_PLANE_B + ((tileB0 + fp) * 8 + it) * 128;
#pragma unroll
        for (int i = 0; i < 4; i++) {
            int q = fsub + i;
            cp16(bufB + fp * 128 + ((q ^ (fp & 7)) << 4), srcB + q * 16);
        }
        const long aoff = ((long)(comp * 8 + it) * 128 + fp) * 64;
#pragma unroll
        for (int s = 0; s < NW; s++) {
            const uint8_t* srcA = (const uint8_t*)((s ? wt1 : wt0) + aoff);
#pragma unroll
            for (int i = 0; i < 4; i++) {
                int q = fsub + i;
                cp16(bufA + s * 16384 + fp * 128 + ((q ^ (fp & 7)) << 4), srcA + q * 16);
            }
        }
    };

    float acc[NW][4][4][4];
#pragma unroll
    for (int s = 0; s < NW; s++)
#pragma unroll
        for (int i = 0; i < 4; i++)
#pragma unroll
            for (int jj = 0; jj < 4; jj++)
#pragma unroll
                for (int r = 0; r < 4; r++) acc[s][i][jj][r] = 0.f;

#pragma unroll
    for (int p = 0; p < 3; p++) { issue(p); cp_commit(); }

    for (int j = 0; j < nloc; j++) {
        for (int it = 0; it < 8; it++) {
            const int p = j * 8 + it;
            asm volatile("cp.async.wait_group 2;" ::: "memory");
            __syncthreads();
            const uint32_t bufB = sb + (p & 3) * STAGE;
            const uint32_t bufA = bufB + 16384;
#pragma unroll
            for (int ks = 0; ks < 2; ks++) {
                uint32_t Bh[2][4], Bl[2][4];
#pragma unroll
                for (int g = 0; g < 2; g++) {
                    int pp = wn * 32 + g * 16 + (lane & 15);
                    uint32_t rb = bufB + pp * 128;
                    int p7 = pp & 7, qh = ks * 2 + (lane >> 4);
                    ldm4(rb + ((qh ^ p7) << 4), Bh[g]);
                    ldm4(rb + (((qh + 4) ^ p7) << 4), Bl[g]);
                }
#pragma unroll
                for (int s = 0; s < NW; s++) {
#pragma unroll
                    for (int i = 0; i < 4; i++) {
                        int r = wm * 64 + i * 16 + (lane & 15);
                        uint32_t ra = bufA + s * 16384 + r * 128;
                        int r7 = r & 7, qh = ks * 2 + (lane >> 4);
                        uint32_t Ah[4], Al[4];
                        ldm4(ra + ((qh ^ r7) << 4), Ah);
                        ldm4(ra + (((qh + 4) ^ r7) << 4), Al);
#pragma unroll
                        for (int jj = 0; jj < 4; jj++) {
                            int g = jj >> 1, rs = jj & 1;
                            mma16816(acc[s][i][jj], Ah, Bh[g][rs], Bh[g][rs + 2]);
                            mma16816(acc[s][i][jj], Ah, Bl[g][rs], Bl[g][rs + 2]);
                            mma16816(acc[s][i][jj], Al, Bh[g][rs], Bh[g][rs + 2]);
                        }
                    }
                }
            }
            if (p + 3 < totalP) issue(p + 3);
            cp_commit();
        }

        // ---- epilogue for item j: buffers 0,1,2 in flight; buffer 3 free for staging ----
        {
            const int item = blockIdx.x + j * (int)gridDim.x;
            int comp; long ytTile0;
            if (KMAP) { comp = item >> 3; ytTile0 = (long)(item & 7) * 128; }
            else      { comp = item >> 6; ytTile0 = (long)(item & 63) * 128; }
            float* stage = (float*)(dsm + 3 * STAGE);
#pragma unroll
            for (int s = 0; s < NW; s++) {
                float* ytS = (s ? yt1 : yt0) + (long)comp * ytPlane + ytTile0 * 128;
#pragma unroll
                for (int pass = 0; pass < 4; pass++) {
                    __syncthreads();
                    if (wn == pass) {
#pragma unroll
                        for (int i = 0; i < 4; i++) {
                            int m = wm * 64 + i * 16 + (lane >> 2);
#pragma unroll
                            for (int jj = 0; jj < 4; jj++) {
                                int nn = jj * 8 + (lane & 3) * 2;
                                stage[nn * 132 + m]           = acc[s][i][jj][0];
                                stage[(nn + 1) * 132 + m]     = acc[s][i][jj][1];
                                stage[nn * 132 + m + 8]       = acc[s][i][jj][2];
                                stage[(nn + 1) * 132 + m + 8] = acc[s][i][jj][3];
                            }
                        }
                    }
                    __syncthreads();
#pragma unroll
                    for (int kk = 0; kk < 4; kk++) {
                        int idx = t + kk * 256;
                        int r = idx >> 5, q = idx & 31;
                        *(float4*)(ytS + (long)(pass * 32 + r) * 128 + q * 4) =
                            *(float4*)(stage + r * 132 + q * 4);
                    }
                }
            }
            __syncthreads();
#pragma unroll
            for (int s = 0; s < NW; s++)
#pragma unroll
                for (int i = 0; i < 4; i++)
#pragma unroll
                    for (int jj = 0; jj < 4; jj++)
#pragma unroll
                        for (int r = 0; r < 4; r++) acc[s][i][jj][r] = 0.f;
        }
    }
}

// ---- F(4,3) inverse transform: yt[comp][tile][oc] -> dst pixel-major (frame = tile>>8) ----
__global__ __launch_bounds__(256) void wino_out(const float* __restrict__ yt,
                                                float* __restrict__ dst0, long plane) {
    const int t = threadIdx.x;
    const int oc = t & 127;
    const long tile = (long)blockIdx.x * 2 + (t >> 7);
    const float* Y = yt + tile * 128 + oc;
    float y[36];
#pragma unroll
    for (int c = 0; c < 36; c++) y[c] = Y[(long)c * plane];
    float Z[4][6];
#pragma unroll
    for (int c = 0; c < 6; c++) {
        float a0 = y[c], a1 = y[6 + c], a2 = y[12 + c],
              a3 = y[18 + c], a4 = y[24 + c], a5 = y[30 + c];
        Z[0][c] = a0 + a1 + a2 + a3 + a4;
        Z[1][c] = a1 - a2 + 2.f * a3 - 2.f * a4;
        Z[2][c] = a1 + a2 + 4.f * a3 + 4.f * a4;
        Z[3][c] = a1 - a2 + 8.f * a3 - 8.f * a4 + a5;
    }
    const int f = (int)(tile >> 8), tloc = (int)(tile & 255);
    const int ty = tloc >> 4, tx = tloc & 15;
    float* dst = dst0 + (long)f * PHW;
#pragma unroll
    for (int a = 0; a < 4; a++) {
        float z0 = Z[a][0], z1 = Z[a][1], z2 = Z[a][2],
              z3 = Z[a][3], z4 = Z[a][4], z5 = Z[a][5];
        float o0 = z0 + z1 + z2 + z3 + z4;
        float o1 = z1 - z2 + 2.f * z3 - 2.f * z4;
        float o2 = z1 + z2 + 4.f * z3 + 4.f * z4;
        float o3 = z1 - z2 + 8.f * z3 - 8.f * z4 + z5;
        long row = (long)((4 * ty + a) * 64 + 4 * tx) * 128 + oc;
        dst[row] = o0;
        dst[row + 128] = o1;
        dst[row + 256] = o2;
        dst[row + 384] = o3;
    }
}

// ---------------- direct conv for the final out-conv (bias + T-broadcast) ----------------
template <int CH, int CHT, bool FINAL>
__global__ __launch_bounds__(256) void conv_mma(
    const uint8_t* __restrict__ in, long inFrameB,
    const __nv_bfloat16* __restrict__ pw0, int OCTOT,
    const float* __restrict__ bias,
    float* __restrict__ out0, long outFrameStride)
{
    constexpr int ITERS = 9 * CH;
    constexpr int STAGE = 32768;
    extern __shared__ __align__(16) char dsm[];
    const uint32_t sb = s2u(dsm);
    const int t = threadIdx.x, lane = t & 31, w = t >> 5;
    const int tile = blockIdx.x, frame = blockIdx.y, oc0 = blockIdx.z * 128;
    const int p0 = tile * 128;
    const uint8_t* inF = in + (long)frame * inFrameB;
    const int wm = w >> 2, wn = w & 3;
    const int fp = t >> 1, fsub = (t & 1) * 4;
    const int prow = fp >> 6, pcol = fp & 63;

    auto issue = [&](int it) {
        const uint32_t bufB = sb + (it & 3) * STAGE;
        const uint32_t bufA = bufB + 16384;
        const int tap = it / CH, chk = it - tap * CH;
        const int dy = tap / 3 - 1, dx = tap - (tap / 3) * 3 - 1;
        const int gr = tile * 2 + prow + dy, gc = pcol + dx;
        const bool ok = ((unsigned)gr < 64u) & ((unsigned)gc < 64u);
        const uint8_t* srcB = inF + ((long)(ok ? (gr * 64 + gc) : 0) * CHT + chk) * 128;
        const int zf = ok ? 16 : 0;
#pragma unroll
        for (int i = 0; i < 4; i++) {
            int q = fsub + i;
            cp16z(bufB + fp * 128 + ((q ^ (fp & 7)) << 4), srcB + q * 16, zf);
        }
        const uint8_t* srcA = (const uint8_t*)(pw0 + ((long)it * OCTOT + oc0 + fp) * 64);
#pragma unroll
        for (int i = 0; i < 4; i++) {
            int q = fsub + i;
            cp16(bufA + fp * 128 + ((q ^ (fp & 7)) << 4), srcA + q * 16);
        }
    };

    float acc[4][4][4];
#pragma unroll
    for (int i = 0; i < 4; i++)
#pragma unroll
        for (int j = 0; j < 4; j++)
#pragma unroll
            for (int r = 0; r < 4; r++) acc[i][j][r] = 0.f;

#pragma unroll
    for (int s = 0; s < 3; s++) { issue(s); cp_commit(); }

    for (int it = 0; it < ITERS; ++it) {
        asm volatile("cp.async.wait_group 2;" ::: "memory");
        __syncthreads();
        const uint32_t bufB = sb + (it & 3) * STAGE;
        const uint32_t bufA = bufB + 16384;
#pragma unroll
        for (int ks = 0; ks < 2; ks++) {
            uint32_t Bh[2][4], Bl[2][4];
#pragma unroll
            for (int g = 0; g < 2; g++) {
                int p = wn * 32 + g * 16 + (lane & 15);
                uint32_t rb = bufB + p * 128;
                int p7 = p & 7, qh = ks * 2 + (lane >> 4);
                ldm4(rb + ((qh ^ p7) << 4), Bh[g]);
                ldm4(rb + (((qh + 4) ^ p7) << 4), Bl[g]);
            }
#pragma unroll
            for (int i = 0; i < 4; i++) {
                int r = wm * 64 + i * 16 + (lane & 15);
                uint32_t ra = bufA + r * 128;
                int r7 = r & 7, qh = ks * 2 + (lane >> 4);
                uint32_t Ah[4], Al[4];
                ldm4(ra + ((qh ^ r7) << 4), Ah);
                ldm4(ra + (((qh + 4) ^ r7) << 4), Al);
#pragma unroll
                for (int j = 0; j < 4; j++) {
                    int g = j >> 1, rs = j & 1;
                    mma16816(acc[i][j], Ah, Bh[g][rs], Bh[g][rs + 2]);
                    mma16816(acc[i][j], Ah, Bl[g][rs], Bl[g][rs + 2]);
                    mma16816(acc[i][j], Al, Bh[g][rs], Bh[g][rs + 2]);
                }
            }
        }
        if (it + 3 < ITERS) issue(it + 3);
        cp_commit();
    }
    asm volatile("cp.async.wait_group 0;" ::: "memory");

    float* stage = (float*)dsm;
    __syncthreads();
#pragma unroll
    for (int i = 0; i < 4; i++) {
        int m = wm * 64 + i * 16 + (lane >> 2);
#pragma unroll
        for (int j = 0; j < 4; j++) {
            int n = wn * 32 + j * 8 + (lane & 3) * 2;
            stage[n * 132 + m]           = acc[i][j][0];
            stage[(n + 1) * 132 + m]     = acc[i][j][1];
            stage[n * 132 + m + 8]       = acc[i][j][2];
            stage[(n + 1) * 132 + m + 8] = acc[i][j][3];
        }
    }
    __syncthreads();
    if (FINAL) {
        for (int idx = t; idx < 32 * 128; idx += 256) {
            const int pg = idx & 31, oc = idx >> 5;
            const float bv = bias[oc0 + oc];
            float4 v;
            v.x = stage[(pg * 4 + 0) * 132 + oc] + bv;
            v.y = stage[(pg * 4 + 1) * 132 + oc] + bv;
            v.z = stage[(pg * 4 + 2) * 132 + oc] + bv;
            v.w = stage[(pg * 4 + 3) * 132 + oc] + bv;
            float* ob = out0 + (long)frame * outFrameStride + (long)(oc0 + oc) * HW + p0 + pg * 4;
#pragma unroll
            for (int tt = 0; tt < 8; tt++)
                *(float4*)(ob + (long)tt * CHWX) = v;
        }
    } else {
        float* outF = out0 + (long)frame * outFrameStride;
        for (int idx = t; idx < 128 * 32; idx += 256) {
            int p = idx >> 5, q = idx & 31;
            *(float4*)(outF + (long)(p0 + p) * 128 + q * 4) = *(float4*)(stage + p * 132 + q * 4);
        }
    }
}

// ---------------- attention: warp per pixel; emits bf16-split pooled (gp2) ----------------
__global__ __launch_bounds__(256) void attn_tc(
    const float* __restrict__ q, const float* __restrict__ k,
    const float* __restrict__ v, uint8_t* __restrict__ gp2)
{
    const int wid = threadIdx.x >> 5, lane = threadIdx.x & 31;
    const int g = blockIdx.x * 8 + wid;
    const int b = g >> 12, pix = g & 4095;

    float4 k4 = ((const float4*)(k + ((long)b * HW + pix) * 128))[lane];

    float dots[8];
#pragma unroll
    for (int t = 0; t < 8; t++) {
        float4 q4 = ((const float4*)(q + ((long)((b * 8 + t) * HW) + pix) * 128))[lane];
        float d = q4.x * k4.x + q4.y * k4.y + q4.z * k4.z + q4.w * k4.w;
#pragma unroll
        for (int off = 16; off; off >>= 1) d += __shfl_xor_sync(0xFFFFFFFFu, d, off);
        dots[t] = d;
    }
    float m = dots[0];
#pragma unroll
    for (int t = 1; t < 8; t++) m = fmaxf(m, dots[t]);
    float a[8], s = 0.f;
#pragma unroll
    for (int t = 0; t < 8; t++) { a[t] = expf(dots[t] - m); s += a[t]; }
    float inv = 1.f / s;

    float4 acc = make_float4(0.f, 0.f, 0.f, 0.f);
#pragma unroll
    for (int t = 0; t < 8; t++) {
        float4 v4 = ((const float4*)(v + ((long)((b * 8 + t) * HW) + pix) * 128))[lane];
        float wgt = a[t] * inv;
        acc.x += wgt * v4.x; acc.y += wgt * v4.y; acc.z += wgt * v4.z; acc.w += wgt * v4.w;
    }
    uint32_t h0, l0, h1, l1;
    split2(acc.x, acc.y, h0, l0);
    split2(acc.z, acc.w, h1, l1);
    const int chunk = lane >> 3, pos = lane & 7;
    uint8_t* row = gp2 + (((long)(b * HW + pix)) * 4 + chunk) * 128;
    *(uint2*)(row + pos * 8) = make_uint2(h0, h1);
    *(uint2*)(row + 64 + pos * 8) = make_uint2(l0, l1);
}

// ---------------------------------------------------------------------------
extern "C" void kernel_launch(void* const* d_in, const int* in_sizes, int n_in,
                              void* d_out, int out_size)
{
    const float* x     = (const float*)d_in[0];
    const float* w_k   = (const float*)d_in[1];
    const float* w_q   = (const float*)d_in[2];
    const float* w_v   = (const float*)d_in[3];
    const float* w_out = (const float*)d_in[4];
    const float* b_out = (const float*)d_in[5];
    float* out = (float*)d_out;

    void* basev = nullptr;
    cudaGetSymbolAddress(&basev, g_scratch);
    float* S = (float*)basev;
    float*   gk  = S + OFF_GK;
    float*   gq  = S + OFF_GQ;
    float*   gv  = S + OFF_GV;
    uint8_t* gp2 = (uint8_t*)(S + OFF_GP2);
    __nv_bfloat16* pwo = (__nv_bfloat16*)(S + OFF_PWO);
    __nv_bfloat16* wtq = (__nv_bfloat16*)(S + OFF_WTQ);
    __nv_bfloat16* wtv = (__nv_bfloat16*)(S + OFF_WTV);
    __nv_bfloat16* wtk = (__nv_bfloat16*)(S + OFF_WTK);
    uint8_t* xt  = (uint8_t*)(S + OFF_XT);
    float*   yt  = S + OFF_YT;
    float*   ytk = S + OFF_YTK;

    const int DSM1 = 4 * 32768;
    const int DSM2 = 4 * 49152;
    const int DSMW = 32 * 6 * 67 * 4;
    cudaFuncSetAttribute(wino_gemm_p<2, false>, cudaFuncAttributeMaxDynamicSharedMemorySize, DSM2);
    cudaFuncSetAttribute(wino_gemm_p<1, true>,  cudaFuncAttributeMaxDynamicSharedMemorySize, DSM1);
    cudaFuncSetAttribute(conv_mma<4, 4, true>,  cudaFuncAttributeMaxDynamicSharedMemorySize, DSM1);
    cudaFuncSetAttribute(wino_in, cudaFuncAttributeMaxDynamicSharedMemorySize, DSMW);

    pack_w<<<288, 256>>>(w_out, pwo, 256, 128);
    wino_w<<<128, 256>>>(w_q, wtq);
    wino_w<<<128, 256>>>(w_v, wtv);
    wino_w<<<128, 256>>>(w_k, wtk);
    wino_in<<<dim3(16, 32), 256, DSMW>>>(x, xt);

    // fused q+v Winograd GEMM: persistent, 2304 items
    wino_gemm_p<2, false><<<148, 256, DSM2>>>(xt, wtq, wtv, yt, yt + YT_SET, 2304, YT_PLANE);
    // k Winograd GEMM over key frames 0/8/16/24: 288 items
    wino_gemm_p<1, true><<<148, 256, DSM1>>>(xt, wtk, nullptr, ytk, nullptr, 288, YTK_PLANE);

    // inverse transforms -> pixel-major q, v, k
    wino_out<<<4096, 256>>>(yt, gq, YT_PLANE);
    wino_out<<<4096, 256>>>(yt + YT_SET, gv, YT_PLANE);
    wino_out<<<512, 256>>>(ytk, gk, YTK_PLANE);

    // attention -> bf16-split pooled
    attn_tc<<<2048, 256>>>(gq, gk, gv, gp2);

    // out conv (direct): bias + T-broadcast
    const long GP_FRAME_B = (long)HW * 4 * 128;
    conv_mma<4, 4, true><<<dim3(32, 4, 2), 256, DSM1>>>(
        gp2, GP_FRAME_B, pwo, 256, b_out, out, TCHWX);
}

// round 9
// speedup vs baseline: 5.5217x; 1.0354x over previous
#include <cuda_runtime.h>
#include <cuda_bf16.h>
#include <cstdint>

#define HW 4096
#define PHW ((long)HW * 128)
#define CHWX ((long)256 * HW)
#define TCHWX ((long)8 * CHWX)

// float offsets in g_scratch
#define OFF_GP2 35651584L
#define OFF_PWO 37748736L
#define OFF_WTQ 38043648L
#define OFF_WTV 39223296L
#define OFF_WTK 40402944L
#define OFF_XT  41582592L             // F(4,3) transformed x, bf16 split (302MB)
#define OFF_YT  117080064L            // q/v GEMM outputs fp32 (2 x 151MB)
#define OFF_YTK 192577536L            // k GEMM output fp32 (19MB)
__device__ __align__(256) float g_scratch[197296128];

#define XT_PLANE_B 8388608L
#define YT_PLANE   1048576L
#define YT_SET     37748736L
#define YTK_PLANE  131072L

// ---------------- helpers ----------------
__device__ __forceinline__ uint32_t s2u(const void* p) {
    uint32_t a;
    asm("{ .reg .u64 t; cvta.to.shared.u64 t, %1; cvt.u32.u64 %0, t; }" : "=r"(a) : "l"(p));
    return a;
}
__device__ __forceinline__ void split2(float f0, float f1, uint32_t& hi, uint32_t& lo) {
    uint32_t h;
    asm("cvt.rn.bf16x2.f32 %0, %1, %2;" : "=r"(h) : "f"(f1), "f"(f0));
    float h0 = __uint_as_float(h << 16);
    float h1 = __uint_as_float(h & 0xFFFF0000u);
    float l0 = f0 - h0, l1 = f1 - h1;
    uint32_t l;
    asm("cvt.rn.bf16x2.f32 %0, %1, %2;" : "=r"(l) : "f"(l1), "f"(l0));
    hi = h; lo = l;
}
__device__ __forceinline__ void ldm4(uint32_t a, uint32_t* r) {
    asm volatile("ldmatrix.sync.aligned.m8n8.x4.shared.b16 {%0,%1,%2,%3}, [%4];"
                 : "=r"(r[0]), "=r"(r[1]), "=r"(r[2]), "=r"(r[3]) : "r"(a));
}
__device__ __forceinline__ void mma16816(float* c, const uint32_t* a, uint32_t b0, uint32_t b1) {
    asm volatile("mma.sync.aligned.m16n8k16.row.col.f32.bf16.bf16.f32 "
                 "{%0,%1,%2,%3}, {%4,%5,%6,%7}, {%8,%9}, {%0,%1,%2,%3};"
                 : "+f"(c[0]), "+f"(c[1]), "+f"(c[2]), "+f"(c[3])
                 : "r"(a[0]), "r"(a[1]), "r"(a[2]), "r"(a[3]), "r"(b0), "r"(b1));
}
__device__ __forceinline__ void cp16(uint32_t d, const void* s) {
    asm volatile("cp.async.cg.shared.global [%0], [%1], 16;" :: "r"(d), "l"(s));
}
__device__ __forceinline__ void cp16z(uint32_t d, const void* s, int zf) {
    asm volatile("cp.async.cg.shared.global [%0], [%1], 16, %2;" :: "r"(d), "l"(s), "r"(zf));
}
__device__ __forceinline__ void cp_commit() { asm volatile("cp.async.commit_group;" ::: "memory"); }

// ---- weight pack (direct out conv) ----
__global__ void pack_w(const float* __restrict__ src, __nv_bfloat16* __restrict__ dst, int OC, int CIN) {
    int CH = CIN >> 5;
    long total = (long)9 * CH * OC * 32;
    for (long i = (long)blockIdx.x * blockDim.x + threadIdx.x; i < total; i += (long)gridDim.x * blockDim.x) {
        int c = (int)(i & 31);
        long r = i >> 5;
        int oc = (int)(r % OC);
        int it = (int)(r / OC);
        int tap = it / CH, chk = it - tap * CH;
        float x = src[((long)oc * CIN + chk * 32 + c) * 9 + tap];
        __nv_bfloat16 hb = __float2bfloat16(x);
        float lo = x - __bfloat162float(hb);
        dst[((long)it * OC + oc) * 64 + c] = hb;
        dst[((long)it * OC + oc) * 64 + 32 + c] = __float2bfloat16(lo);
    }
}

// ---- F(4,3) weight transform ----
__global__ void wino_w(const float* __restrict__ src, __nv_bfloat16* __restrict__ dst) {
    int t = blockIdx.x * blockDim.x + threadIdx.x;
    if (t >= 128 * 256) return;
    int ic = t & 255, oc = t >> 8;
    float g[3][3];
#pragma unroll
    for (int r = 0; r < 3; r++)
#pragma unroll
        for (int c = 0; c < 3; c++)
            g[r][c] = src[((long)oc * 256 + ic) * 9 + r * 3 + c];
    const float i6 = 1.f / 6.f, i12 = 1.f / 12.f, i24 = 1.f / 24.f;
    float R[6][3];
#pragma unroll
    for (int c = 0; c < 3; c++) {
        R[0][c] = 0.25f * g[0][c];
        R[1][c] = -i6 * (g[0][c] + g[1][c] + g[2][c]);
        R[2][c] = i6 * (-g[0][c] + g[1][c] - g[2][c]);
        R[3][c] = i24 * g[0][c] + i12 * g[1][c] + i6 * g[2][c];
        R[4][c] = i24 * g[0][c] - i12 * g[1][c] + i6 * g[2][c];
        R[5][c] = g[2][c];
    }
    float U[6][6];
#pragma unroll
    for (int r = 0; r < 6; r++) {
        U[r][0] = 0.25f * R[r][0];
        U[r][1] = -i6 * (R[r][0] + R[r][1] + R[r][2]);
        U[r][2] = i6 * (-R[r][0] + R[r][1] - R[r][2]);
        U[r][3] = i24 * R[r][0] + i12 * R[r][1] + i6 * R[r][2];
        U[r][4] = i24 * R[r][0] - i12 * R[r][1] + i6 * R[r][2];
        U[r][5] = R[r][2];
    }
#pragma unroll
    for (int comp = 0; comp < 36; comp++) {
        float x = U[comp / 6][comp % 6];
        __nv_bfloat16 hb = __float2bfloat16(x);
        float lo = x - __bfloat162float(hb);
        long base = ((long)(comp * 8 + (ic >> 5)) * 128 + oc) * 64 + (ic & 31);
        dst[base] = hb;
        dst[base + 32] = __float2bfloat16(lo);
    }
}

// ---- F(4,3) input transform ----
__global__ __launch_bounds__(256) void wino_in(const float* __restrict__ x, uint8_t* __restrict__ xt) {
    extern __shared__ float sm[];
    const int f = blockIdx.y, ty = blockIdx.x;
    const int t = threadIdx.x;
    const float* xf = x + (long)f * CHWX;
    const int gr0 = 4 * ty - 1;
    const int tx = t >> 4, j = t & 15;
    const long tileG = (long)f * 256 + ty * 16 + tx;

    for (int cc = 0; cc < 8; cc++) {
        __syncthreads();
        for (int idx = t; idx < 32 * 6 * 66; idx += 256) {
            int c = idx % 66;
            int rc = idx / 66;
            int r = rc % 6, ch = rc / 6;
            int gr = gr0 + r, gc = c - 1;
            float v = ((unsigned)gr < 64u && (unsigned)gc < 64u)
                          ? xf[(long)(cc * 32 + ch) * HW + gr * 64 + gc] : 0.f;
            sm[(ch * 6 + r) * 67 + c] = v;
        }
        __syncthreads();
        float D[2][36];
#pragma unroll
        for (int e = 0; e < 2; e++) {
            const float* s = sm + (2 * j + e) * 402 + 4 * tx;
            float T[6][6];
#pragma unroll
            for (int c = 0; c < 6; c++) {
                float x0 = s[c], x1 = s[67 + c], x2 = s[134 + c],
                      x3 = s[201 + c], x4 = s[268 + c], x5 = s[335 + c];
                T[0][c] = 4.f * x0 - 5.f * x2 + x4;
                T[1][c] = -4.f * x1 - 4.f * x2 + x3 + x4;
                T[2][c] = 4.f * x1 - 4.f * x2 - x3 + x4;
                T[3][c] = -2.f * x1 - x2 + 2.f * x3 + x4;
                T[4][c] = 2.f * x1 - x2 - 2.f * x3 + x4;
                T[5][c] = 4.f * x1 - 5.f * x3 + x5;
            }
#pragma unroll
            for (int r = 0; r < 6; r++) {
                float t0 = T[r][0], t1 = T[r][1], t2 = T[r][2],
                      t3 = T[r][3], t4 = T[r][4], t5 = T[r][5];
                D[e][r * 6 + 0] = 4.f * t0 - 5.f * t2 + t4;
                D[e][r * 6 + 1] = -4.f * t1 - 4.f * t2 + t3 + t4;
                D[e][r * 6 + 2] = 4.f * t1 - 4.f * t2 - t3 + t4;
                D[e][r * 6 + 3] = -2.f * t1 - t2 + 2.f * t3 + t4;
                D[e][r * 6 + 4] = 2.f * t1 - t2 - 2.f * t3 + t4;
                D[e][r * 6 + 5] = 4.f * t1 - 5.f * t3 + t5;
            }
        }
        uint8_t* base = xt + tileG * 1024 + cc * 128 + j * 4;
#pragma unroll
        for (int comp = 0; comp < 36; comp++) {
            uint32_t h, l;
            split2(D[0][comp], D[1][comp], h, l);
            *(uint32_t*)(base + (long)comp * XT_PLANE_B) = h;
            *(uint32_t*)(base + (long)comp * XT_PLANE_B + 64) = l;
        }
    }
}

// ---------------- persistent Winograd GEMM (3-term bf16, mma.sync) ----------------
template <int NW, bool KMAP>
__global__ __launch_bounds__(256) void wino_gemm_p(
    const uint8_t* __restrict__ xt,
    const __nv_bfloat16* __restrict__ wt0, const __nv_bfloat16* __restrict__ wt1,
    float* __restrict__ yt0, float* __restrict__ yt1,
    int nItems, long ytPlane)
{
    constexpr int STAGE = 16384 * (1 + NW);
    extern __shared__ __align__(16) char dsm[];
    const uint32_t sb = s2u(dsm);
    const int t = threadIdx.x, lane = t & 31, w = t >> 5;
    const int wm = w >> 2, wn = w & 3;
    const int fp = t >> 1, fsub = (t & 1) * 4;

    const int nloc = (nItems - blockIdx.x + gridDim.x - 1) / gridDim.x;
    if (nloc <= 0) return;
    const int totalP = nloc * 8;

    auto issue = [&](int p) {
        const int j = p >> 3, it = p & 7;
        const int item = blockIdx.x + j * (int)gridDim.x;
        int comp; long tileB0;
        if (KMAP) { comp = item >> 3; int tb = item & 7; tileB0 = (long)(tb >> 1) * 2048 + (tb & 1) * 128; }
        else      { comp = item >> 6; tileB0 = (long)(item & 63) * 128; }
        const uint32_t bufB = sb + (p & 3) * STAGE;
        const uint32_t bufA = bufB + 16384;
        const uint8_t* srcB = xt + (long)comp * XT_PLANE_B + ((tileB0 + fp) * 8 + it) * 128;
#pragma unroll
        for (int i = 0; i < 4; i++) {
            int q = fsub + i;
            cp16(bufB + fp * 128 + ((q ^ (fp & 7)) << 4), srcB + q * 16);
        }
        const long aoff = ((long)(comp * 8 + it) * 128 + fp) * 64;
#pragma unroll
        for (int s = 0; s < NW; s++) {
            const uint8_t* srcA = (const uint8_t*)((s ? wt1 : wt0) + aoff);
#pragma unroll
            for (int i = 0; i < 4; i++) {
                int q = fsub + i;
                cp16(bufA + s * 16384 + fp * 128 + ((q ^ (fp & 7)) << 4), srcA + q * 16);
            }
        }
    };

    float acc[NW][4][4][4];
#pragma unroll
    for (int s = 0; s < NW; s++)
#pragma unroll
        for (int i = 0; i < 4; i++)
#pragma unroll
            for (int jj = 0; jj < 4; jj++)
#pragma unroll
                for (int r = 0; r < 4; r++) acc[s][i][jj][r] = 0.f;

#pragma unroll
    for (int p = 0; p < 3; p++) { issue(p); cp_commit(); }

    for (int j = 0; j < nloc; j++) {
        for (int it = 0; it < 8; it++) {
            const int p = j * 8 + it;
            asm volatile("cp.async.wait_group 2;" ::: "memory");
            __syncthreads();
            const uint32_t bufB = sb + (p & 3) * STAGE;
            const uint32_t bufA = bufB + 16384;
#pragma unroll
            for (int ks = 0; ks < 2; ks++) {
                uint32_t Bh[2][4], Bl[2][4];
#pragma unroll
                for (int g = 0; g < 2; g++) {
                    int pp = wn * 32 + g * 16 + (lane & 15);
                    uint32_t rb = bufB + pp * 128;
                    int p7 = pp & 7, qh = ks * 2 + (lane >> 4);
                    ldm4(rb + ((qh ^ p7) << 4), Bh[g]);
                    ldm4(rb + (((qh + 4) ^ p7) << 4), Bl[g]);
                }
#pragma unroll
                for (int s = 0; s < NW; s++) {
#pragma unroll
                    for (int i = 0; i < 4; i++) {
                        int r = wm * 64 + i * 16 + (lane & 15);
                        uint32_t ra = bufA + s * 16384 + r * 128;
                        int r7 = r & 7, qh = ks * 2 + (lane >> 4);
                        uint32_t Ah[4], Al[4];
                        ldm4(ra + ((qh ^ r7) << 4), Ah);
                        ldm4(ra + (((qh + 4) ^ r7) << 4), Al);
#pragma unroll
                        for (int jj = 0; jj < 4; jj++) {
                            int g = jj >> 1, rs = jj & 1;
                            mma16816(acc[s][i][jj], Ah, Bh[g][rs], Bh[g][rs + 2]);
                            mma16816(acc[s][i][jj], Ah, Bl[g][rs], Bl[g][rs + 2]);
                            mma16816(acc[s][i][jj], Al, Bh[g][rs], Bh[g][rs + 2]);
                        }
                    }
                }
            }
            if (p + 3 < totalP) issue(p + 3);
            cp_commit();
        }

        // ---- epilogue (buffer 3 free for staging) ----
        {
            const int item = blockIdx.x + j * (int)gridDim.x;
            int comp; long ytTile0;
            if (KMAP) { comp = item >> 3; ytTile0 = (long)(item & 7) * 128; }
            else      { comp = item >> 6; ytTile0 = (long)(item & 63) * 128; }
            float* stage = (float*)(dsm + 3 * STAGE);
#pragma unroll
            for (int s = 0; s < NW; s++) {
                float* ytS = (s ? yt1 : yt0) + (long)comp * ytPlane + ytTile0 * 128;
#pragma unroll
                for (int pass = 0; pass < 4; pass++) {
                    __syncthreads();
                    if (wn == pass) {
#pragma unroll
                        for (int i = 0; i < 4; i++) {
                            int m = wm * 64 + i * 16 + (lane >> 2);
#pragma unroll
                            for (int jj = 0; jj < 4; jj++) {
                                int nn = jj * 8 + (lane & 3) * 2;
                                stage[nn * 132 + m]           = acc[s][i][jj][0];
                                stage[(nn + 1) * 132 + m]     = acc[s][i][jj][1];
                                stage[nn * 132 + m + 8]       = acc[s][i][jj][2];
                                stage[(nn + 1) * 132 + m + 8] = acc[s][i][jj][3];
                            }
                        }
                    }
                    __syncthreads();
#pragma unroll
                    for (int kk = 0; kk < 4; kk++) {
                        int idx = t + kk * 256;
                        int r = idx >> 5, q = idx & 31;
                        *(float4*)(ytS + (long)(pass * 32 + r) * 128 + q * 4) =
                            *(float4*)(stage + r * 132 + q * 4);
                    }
                }
            }
            __syncthreads();
#pragma unroll
            for (int s = 0; s < NW; s++)
#pragma unroll
                for (int i = 0; i < 4; i++)
#pragma unroll
                    for (int jj = 0; jj < 4; jj++)
#pragma unroll
                        for (int r = 0; r < 4; r++) acc[s][i][jj][r] = 0.f;
        }
    }
}

// ---- F(4,3) inverse transform of 36 comps -> 16 pixels (register-resident) ----
__device__ __forceinline__ void inv36(const float* __restrict__ Y, long plane, float* o) {
    float y[36];
#pragma unroll
    for (int c = 0; c < 36; c++) y[c] = __ldg(Y + c * plane);
    float Z[4][6];
#pragma unroll
    for (int c = 0; c < 6; c++) {
        float a0 = y[c], a1 = y[6 + c], a2 = y[12 + c],
              a3 = y[18 + c], a4 = y[24 + c], a5 = y[30 + c];
        Z[0][c] = a0 + a1 + a2 + a3 + a4;
        Z[1][c] = a1 - a2 + 2.f * a3 - 2.f * a4;
        Z[2][c] = a1 + a2 + 4.f * a3 + 4.f * a4;
        Z[3][c] = a1 - a2 + 8.f * a3 - 8.f * a4 + a5;
    }
#pragma unroll
    for (int a = 0; a < 4; a++) {
        float z0 = Z[a][0], z1 = Z[a][1], z2 = Z[a][2],
              z3 = Z[a][3], z4 = Z[a][4], z5 = Z[a][5];
        o[a * 4 + 0] = z0 + z1 + z2 + z3 + z4;
        o[a * 4 + 1] = z1 - z2 + 2.f * z3 - 2.f * z4;
        o[a * 4 + 2] = z1 + z2 + 4.f * z3 + 4.f * z4;
        o[a * 4 + 3] = z1 - z2 + 8.f * z3 - 8.f * z4 + z5;
    }
}

// ---- fused inverse-transform + attention + bf16-split pooled output ----
// CTA = (batch, 2 spatial tiles); thread = (tile, oc). Online softmax over 8 frames.
__global__ __launch_bounds__(256) void attn_wino(
    const float* __restrict__ yt, const float* __restrict__ ytk,
    uint8_t* __restrict__ gp2)
{
    __shared__ float sdots[2][4][16];
    __shared__ float fdots[2][16];
    __shared__ float stage[2][16][128];
    const int t = threadIdx.x, lane = t & 31;
    const int oc = t & 127, tl = t >> 7;
    const int wsub = (t >> 5) & 3;
    const int b = blockIdx.x >> 7, tp = blockIdx.x & 127;
    const int tloc = tp * 2 + tl;

    float k16[16];
    inv36(ytk + (long)(b * 256 + tloc) * 128 + oc, YTK_PLANE, k16);

    float m[16], s[16], acc[16];

    for (int f = 0; f < 8; f++) {
        const long tg = ((long)((b * 8 + f) * 256 + tloc)) * 128 + oc;
        float q16[16];
        inv36(yt + tg, YT_PLANE, q16);
        float p[16];
#pragma unroll
        for (int px = 0; px < 16; px++) p[px] = q16[px] * k16[px];
#pragma unroll
        for (int off = 16; off; off >>= 1)
#pragma unroll
            for (int px = 0; px < 16; px++) p[px] += __shfl_xor_sync(0xFFFFFFFFu, p[px], off);
        if (lane == 0)
#pragma unroll
            for (int px = 0; px < 16; px++) sdots[tl][wsub][px] = p[px];
        __syncthreads();
        if (t < 32) {
            int t2 = t >> 4, px = t & 15;
            fdots[t2][px] = sdots[t2][0][px] + sdots[t2][1][px] + sdots[t2][2][px] + sdots[t2][3][px];
        }
        float v16[16];
        inv36(yt + YT_SET + tg, YT_PLANE, v16);
        __syncthreads();
#pragma unroll
        for (int px = 0; px < 16; px++) {
            float d = fdots[tl][px];
            if (f == 0) { m[px] = d; s[px] = 1.f; acc[px] = v16[px]; }
            else {
                float nm = fmaxf(m[px], d);
                float sc = expf(m[px] - nm);
                float e  = expf(d - nm);
                s[px] = s[px] * sc + e;
                acc[px] = acc[px] * sc + e * v16[px];
                m[px] = nm;
            }
        }
    }

#pragma unroll
    for (int px = 0; px < 16; px++) stage[tl][px][oc] = acc[px] / s[px];
    __syncthreads();
    for (int idx = t; idx < 2 * 16 * 32; idx += 256) {
        int l = idx & 31, px = (idx >> 5) & 15, tt = idx >> 9;
        const float* sp = &stage[tt][px][l * 4];
        uint32_t h0, l0, h1, l1;
        split2(sp[0], sp[1], h0, l0);
        split2(sp[2], sp[3], h1, l1);
        int tw = tp * 2 + tt;
        int ty = tw >> 4, tx = tw & 15;
        int pix = (4 * ty + (px >> 2)) * 64 + 4 * tx + (px & 3);
        uint8_t* row = gp2 + ((long)(b * HW + pix)) * 512;
        int chunk = l >> 3, pos = l & 7;
        *(uint2*)(row + chunk * 128 + pos * 8) = make_uint2(h0, h1);
        *(uint2*)(row + chunk * 128 + 64 + pos * 8) = make_uint2(l0, l1);
    }
}

// ---------------- direct conv for the final out-conv (bias + T-broadcast) ----------------
template <int CH, int CHT, bool FINAL>
__global__ __launch_bounds__(256) void conv_mma(
    const uint8_t* __restrict__ in, long inFrameB,
    const __nv_bfloat16* __restrict__ pw0, int OCTOT,
    const float* __restrict__ bias,
    float* __restrict__ out0, long outFrameStride)
{
    constexpr int ITERS = 9 * CH;
    constexpr int STAGE = 32768;
    extern __shared__ __align__(16) char dsm[];
    const uint32_t sb = s2u(dsm);
    const int t = threadIdx.x, lane = t & 31, w = t >> 5;
    const int tile = blockIdx.x, frame = blockIdx.y, oc0 = blockIdx.z * 128;
    const int p0 = tile * 128;
    const uint8_t* inF = in + (long)frame * inFrameB;
    const int wm = w >> 2, wn = w & 3;
    const int fp = t >> 1, fsub = (t & 1) * 4;
    const int prow = fp >> 6, pcol = fp & 63;

    auto issue = [&](int it) {
        const uint32_t bufB = sb + (it & 3) * STAGE;
        const uint32_t bufA = bufB + 16384;
        const int tap = it / CH, chk = it - tap * CH;
        const int dy = tap / 3 - 1, dx = tap - (tap / 3) * 3 - 1;
        const int gr = tile * 2 + prow + dy, gc = pcol + dx;
        const bool ok = ((unsigned)gr < 64u) & ((unsigned)gc < 64u);
        const uint8_t* srcB = inF + ((long)(ok ? (gr * 64 + gc) : 0) * CHT + chk) * 128;
        const int zf = ok ? 16 : 0;
#pragma unroll
        for (int i = 0; i < 4; i++) {
            int q = fsub + i;
            cp16z(bufB + fp * 128 + ((q ^ (fp & 7)) << 4), srcB + q * 16, zf);
        }
        const uint8_t* srcA = (const uint8_t*)(pw0 + ((long)it * OCTOT + oc0 + fp) * 64);
#pragma unroll
        for (int i = 0; i < 4; i++) {
            int q = fsub + i;
            cp16(bufA + fp * 128 + ((q ^ (fp & 7)) << 4), srcA + q * 16);
        }
    };

    float acc[4][4][4];
#pragma unroll
    for (int i = 0; i < 4; i++)
#pragma unroll
        for (int j = 0; j < 4; j++)
#pragma unroll
            for (int r = 0; r < 4; r++) acc[i][j][r] = 0.f;

#pragma unroll
    for (int s = 0; s < 3; s++) { issue(s); cp_commit(); }

    for (int it = 0; it < ITERS; ++it) {
        asm volatile("cp.async.wait_group 2;" ::: "memory");
        __syncthreads();
        const uint32_t bufB = sb + (it & 3) * STAGE;
        const uint32_t bufA = bufB + 16384;
#pragma unroll
        for (int ks = 0; ks < 2; ks++) {
            uint32_t Bh[2][4], Bl[2][4];
#pragma unroll
            for (int g = 0; g < 2; g++) {
                int p = wn * 32 + g * 16 + (lane & 15);
                uint32_t rb = bufB + p * 128;
                int p7 = p & 7, qh = ks * 2 + (lane >> 4);
                ldm4(rb + ((qh ^ p7) << 4), Bh[g]);
                ldm4(rb + (((qh + 4) ^ p7) << 4), Bl[g]);
            }
#pragma unroll
            for (int i = 0; i < 4; i++) {
                int r = wm * 64 + i * 16 + (lane & 15);
                uint32_t ra = bufA + r * 128;
                int r7 = r & 7, qh = ks * 2 + (lane >> 4);
                uint32_t Ah[4], Al[4];
                ldm4(ra + ((qh ^ r7) << 4), Ah);
                ldm4(ra + (((qh + 4) ^ r7) << 4), Al);
#pragma unroll
                for (int j = 0; j < 4; j++) {
                    int g = j >> 1, rs = j & 1;
                    mma16816(acc[i][j], Ah, Bh[g][rs], Bh[g][rs + 2]);
                    mma16816(acc[i][j], Ah, Bl[g][rs], Bl[g][rs + 2]);
                    mma16816(acc[i][j], Al, Bh[g][rs], Bh[g][rs + 2]);
                }
            }
        }
        if (it + 3 < ITERS) issue(it + 3);
        cp_commit();
    }
    asm volatile("cp.async.wait_group 0;" ::: "memory");

    float* stage = (float*)dsm;
    __syncthreads();
#pragma unroll
    for (int i = 0; i < 4; i++) {
        int m = wm * 64 + i * 16 + (lane >> 2);
#pragma unroll
        for (int j = 0; j < 4; j++) {
            int n = wn * 32 + j * 8 + (lane & 3) * 2;
            stage[n * 132 + m]           = acc[i][j][0];
            stage[(n + 1) * 132 + m]     = acc[i][j][1];
            stage[n * 132 + m + 8]       = acc[i][j][2];
            stage[(n + 1) * 132 + m + 8] = acc[i][j][3];
        }
    }
    __syncthreads();
    if (FINAL) {
        for (int idx = t; idx < 32 * 128; idx += 256) {
            const int pg = idx & 31, oc = idx >> 5;
            const float bv = bias[oc0 + oc];
            float4 v;
            v.x = stage[(pg * 4 + 0) * 132 + oc] + bv;
            v.y = stage[(pg * 4 + 1) * 132 + oc] + bv;
            v.z = stage[(pg * 4 + 2) * 132 + oc] + bv;
            v.w = stage[(pg * 4 + 3) * 132 + oc] + bv;
            float* ob = out0 + (long)frame * outFrameStride + (long)(oc0 + oc) * HW + p0 + pg * 4;
#pragma unroll
            for (int tt = 0; tt < 8; tt++)
                *(float4*)(ob + (long)tt * CHWX) = v;
        }
    } else {
        float* outF = out0 + (long)frame * outFrameStride;
        for (int idx = t; idx < 128 * 32; idx += 256) {
            int p = idx >> 5, q = idx & 31;
            *(float4*)(outF + (long)(p0 + p) * 128 + q * 4) = *(float4*)(stage + p * 132 + q * 4);
        }
    }
}

// ---------------------------------------------------------------------------
extern "C" void kernel_launch(void* const* d_in, const int* in_sizes, int n_in,
                              void* d_out, int out_size)
{
    const float* x     = (const float*)d_in[0];
    const float* w_k   = (const float*)d_in[1];
    const float* w_q   = (const float*)d_in[2];
    const float* w_v   = (const float*)d_in[3];
    const float* w_out = (const float*)d_in[4];
    const float* b_out = (const float*)d_in[5];
    float* out = (float*)d_out;

    void* basev = nullptr;
    cudaGetSymbolAddress(&basev, g_scratch);
    float* S = (float*)basev;
    uint8_t* gp2 = (uint8_t*)(S + OFF_GP2);
    __nv_bfloat16* pwo = (__nv_bfloat16*)(S + OFF_PWO);
    __nv_bfloat16* wtq = (__nv_bfloat16*)(S + OFF_WTQ);
    __nv_bfloat16* wtv = (__nv_bfloat16*)(S + OFF_WTV);
    __nv_bfloat16* wtk = (__nv_bfloat16*)(S + OFF_WTK);
    uint8_t* xt  = (uint8_t*)(S + OFF_XT);
    float*   yt  = S + OFF_YT;
    float*   ytk = S + OFF_YTK;

    const int DSM1 = 4 * 32768;
    const int DSM2 = 4 * 49152;
    const int DSMW = 32 * 6 * 67 * 4;
    cudaFuncSetAttribute(wino_gemm_p<2, false>, cudaFuncAttributeMaxDynamicSharedMemorySize, DSM2);
    cudaFuncSetAttribute(wino_gemm_p<1, true>,  cudaFuncAttributeMaxDynamicSharedMemorySize, DSM1);
    cudaFuncSetAttribute(conv_mma<4, 4, true>,  cudaFuncAttributeMaxDynamicSharedMemorySize, DSM1);
    cudaFuncSetAttribute(wino_in, cudaFuncAttributeMaxDynamicSharedMemorySize, DSMW);

    pack_w<<<288, 256>>>(w_out, pwo, 256, 128);
    wino_w<<<128, 256>>>(w_q, wtq);
    wino_w<<<128, 256>>>(w_v, wtv);
    wino_w<<<128, 256>>>(w_k, wtk);
    wino_in<<<dim3(16, 32), 256, DSMW>>>(x, xt);

    // fused q+v Winograd GEMM: persistent, 2304 items
    wino_gemm_p<2, false><<<148, 256, DSM2>>>(xt, wtq, wtv, yt, yt + YT_SET, 2304, YT_PLANE);
    // k Winograd GEMM over key frames 0/8/16/24: 288 items
    wino_gemm_p<1, true><<<148, 256, DSM1>>>(xt, wtk, nullptr, ytk, nullptr, 288, YTK_PLANE);

    // fused inverse transform + attention -> bf16-split pooled
    attn_wino<<<512, 256>>>(yt, ytk, gp2);

    // out conv (direct): bias + T-broadcast
    const long GP_FRAME_B = (long)HW * 4 * 128;
    conv_mma<4, 4, true><<<dim3(32, 4, 2), 256, DSM1>>>(
        gp2, GP_FRAME_B, pwo, 256, b_out, out, TCHWX);
}

// round 10
// speedup vs baseline: 6.3798x; 1.1554x over previous
#include <cuda_runtime.h>
#include <cuda_bf16.h>
#include <cstdint>

#define HW 4096
#define CHWX ((long)256 * HW)

// float offsets in g_scratch
#define OFF_GP    35651584L
#define OFF_WTO0  37748736L
#define OFF_WTO1  38338560L
#define OFF_WTQ   38928384L
#define OFF_WTV   40108032L
#define OFF_WTK   41287680L
#define OFF_XTP   42467328L
#define OFF_YTO   47185920L
#define OFF_XT    56623104L
#define OFF_YT    132120576L
#define OFF_YTK   207618048L
__device__ __align__(256) float g_scratch[212336640];

#define XT_PLANE_B  8388608L
#define XTP_PLANE_B 524288L
#define YT_PLANE    1048576L
#define YT_SET      37748736L
#define YTK_PLANE   131072L
#define YTO_PLANE   131072L
#define YTO_HALF    4718592L

// ---------------- helpers ----------------
__device__ __forceinline__ uint32_t s2u(const void* p) {
    uint32_t a;
    asm("{ .reg .u64 t; cvta.to.shared.u64 t, %1; cvt.u32.u64 %0, t; }" : "=r"(a) : "l"(p));
    return a;
}
__device__ __forceinline__ void split2(float f0, float f1, uint32_t& hi, uint32_t& lo) {
    uint32_t h;
    asm("cvt.rn.bf16x2.f32 %0, %1, %2;" : "=r"(h) : "f"(f1), "f"(f0));
    float h0 = __uint_as_float(h << 16);
    float h1 = __uint_as_float(h & 0xFFFF0000u);
    float l0 = f0 - h0, l1 = f1 - h1;
    uint32_t l;
    asm("cvt.rn.bf16x2.f32 %0, %1, %2;" : "=r"(l) : "f"(l1), "f"(l0));
    hi = h; lo = l;
}
__device__ __forceinline__ void ldm4(uint32_t a, uint32_t* r) {
    asm volatile("ldmatrix.sync.aligned.m8n8.x4.shared.b16 {%0,%1,%2,%3}, [%4];"
                 : "=r"(r[0]), "=r"(r[1]), "=r"(r[2]), "=r"(r[3]) : "r"(a));
}
__device__ __forceinline__ void mma16816(float* c, const uint32_t* a, uint32_t b0, uint32_t b1) {
    asm volatile("mma.sync.aligned.m16n8k16.row.col.f32.bf16.bf16.f32 "
                 "{%0,%1,%2,%3}, {%4,%5,%6,%7}, {%8,%9}, {%0,%1,%2,%3};"
                 : "+f"(c[0]), "+f"(c[1]), "+f"(c[2]), "+f"(c[3])
                 : "r"(a[0]), "r"(a[1]), "r"(a[2]), "r"(a[3]), "r"(b0), "r"(b1));
}
__device__ __forceinline__ void cp16(uint32_t d, const void* s) {
    asm volatile("cp.async.cg.shared.global [%0], [%1], 16;" :: "r"(d), "l"(s));
}
__device__ __forceinline__ void cp_commit() { asm volatile("cp.async.commit_group;" ::: "memory"); }

// ---- F(4,3) weight transform: w(128,256,3,3) -> wt[comp36*8+chunk][oc128][32hi|32lo] ----
__global__ void wino_w(const float* __restrict__ src, __nv_bfloat16* __restrict__ dst) {
    int t = blockIdx.x * blockDim.x + threadIdx.x;
    if (t >= 128 * 256) return;
    int ic = t & 255, oc = t >> 8;
    float g[3][3];
#pragma unroll
    for (int r = 0; r < 3; r++)
#pragma unroll
        for (int c = 0; c < 3; c++)
            g[r][c] = src[((long)oc * 256 + ic) * 9 + r * 3 + c];
    const float i6 = 1.f / 6.f, i12 = 1.f / 12.f, i24 = 1.f / 24.f;
    float R[6][3];
#pragma unroll
    for (int c = 0; c < 3; c++) {
        R[0][c] = 0.25f * g[0][c];
        R[1][c] = -i6 * (g[0][c] + g[1][c] + g[2][c]);
        R[2][c] = i6 * (-g[0][c] + g[1][c] - g[2][c]);
        R[3][c] = i24 * g[0][c] + i12 * g[1][c] + i6 * g[2][c];
        R[4][c] = i24 * g[0][c] - i12 * g[1][c] + i6 * g[2][c];
        R[5][c] = g[2][c];
    }
    float U[6][6];
#pragma unroll
    for (int r = 0; r < 6; r++) {
        U[r][0] = 0.25f * R[r][0];
        U[r][1] = -i6 * (R[r][0] + R[r][1] + R[r][2]);
        U[r][2] = i6 * (-R[r][0] + R[r][1] - R[r][2]);
        U[r][3] = i24 * R[r][0] + i12 * R[r][1] + i6 * R[r][2];
        U[r][4] = i24 * R[r][0] - i12 * R[r][1] + i6 * R[r][2];
        U[r][5] = R[r][2];
    }
#pragma unroll
    for (int comp = 0; comp < 36; comp++) {
        float x = U[comp / 6][comp % 6];
        __nv_bfloat16 hb = __float2bfloat16(x);
        float lo = x - __bfloat162float(hb);
        long base = ((long)(comp * 8 + (ic >> 5)) * 128 + oc) * 64 + (ic & 31);
        dst[base] = hb;
        dst[base + 32] = __float2bfloat16(lo);
    }
}

// ---- F(4,3) weight transform for out conv: w(256,128,3,3) -> two 128-oc halves ----
__global__ void wino_w_out(const float* __restrict__ src,
                           __nv_bfloat16* __restrict__ dst0, __nv_bfloat16* __restrict__ dst1) {
    int t = blockIdx.x * blockDim.x + threadIdx.x;
    if (t >= 256 * 128) return;
    int ic = t & 127, oc = t >> 7;
    float g[3][3];
#pragma unroll
    for (int r = 0; r < 3; r++)
#pragma unroll
        for (int c = 0; c < 3; c++)
            g[r][c] = src[((long)oc * 128 + ic) * 9 + r * 3 + c];
    const float i6 = 1.f / 6.f, i12 = 1.f / 12.f, i24 = 1.f / 24.f;
    float R[6][3];
#pragma unroll
    for (int c = 0; c < 3; c++) {
        R[0][c] = 0.25f * g[0][c];
        R[1][c] = -i6 * (g[0][c] + g[1][c] + g[2][c]);
        R[2][c] = i6 * (-g[0][c] + g[1][c] - g[2][c]);
        R[3][c] = i24 * g[0][c] + i12 * g[1][c] + i6 * g[2][c];
        R[4][c] = i24 * g[0][c] - i12 * g[1][c] + i6 * g[2][c];
        R[5][c] = g[2][c];
    }
    float U[6][6];
#pragma unroll
    for (int r = 0; r < 6; r++) {
        U[r][0] = 0.25f * R[r][0];
        U[r][1] = -i6 * (R[r][0] + R[r][1] + R[r][2]);
        U[r][2] = i6 * (-R[r][0] + R[r][1] - R[r][2]);
        U[r][3] = i24 * R[r][0] + i12 * R[r][1] + i6 * R[r][2];
        U[r][4] = i24 * R[r][0] - i12 * R[r][1] + i6 * R[r][2];
        U[r][5] = R[r][2];
    }
    __nv_bfloat16* dst = (oc < 128) ? dst0 : dst1;
    int ocl = oc & 127;
#pragma unroll
    for (int comp = 0; comp < 36; comp++) {
        float x = U[comp / 6][comp % 6];
        __nv_bfloat16 hb = __float2bfloat16(x);
        float lo = x - __bfloat162float(hb);
        long base = ((long)(comp * 4 + (ic >> 5)) * 128 + ocl) * 64 + (ic & 31);
        dst[base] = hb;
        dst[base + 32] = __float2bfloat16(lo);
    }
}

// ---- shared transform core: sm[32ch][6r][67] -> D[2][36] for (tx, j) ----
__device__ __forceinline__ void wtransform(const float* sm, int tx, int j, float D[2][36]) {
#pragma unroll
    for (int e = 0; e < 2; e++) {
        const float* s = sm + (2 * j + e) * 402 + 4 * tx;
        float T[6][6];
#pragma unroll
        for (int c = 0; c < 6; c++) {
            float x0 = s[c], x1 = s[67 + c], x2 = s[134 + c],
                  x3 = s[201 + c], x4 = s[268 + c], x5 = s[335 + c];
            T[0][c] = 4.f * x0 - 5.f * x2 + x4;
            T[1][c] = -4.f * x1 - 4.f * x2 + x3 + x4;
            T[2][c] = 4.f * x1 - 4.f * x2 - x3 + x4;
            T[3][c] = -2.f * x1 - x2 + 2.f * x3 + x4;
            T[4][c] = 2.f * x1 - x2 - 2.f * x3 + x4;
            T[5][c] = 4.f * x1 - 5.f * x3 + x5;
        }
#pragma unroll
        for (int r = 0; r < 6; r++) {
            float t0 = T[r][0], t1 = T[r][1], t2 = T[r][2],
                  t3 = T[r][3], t4 = T[r][4], t5 = T[r][5];
            D[e][r * 6 + 0] = 4.f * t0 - 5.f * t2 + t4;
            D[e][r * 6 + 1] = -4.f * t1 - 4.f * t2 + t3 + t4;
            D[e][r * 6 + 2] = 4.f * t1 - 4.f * t2 - t3 + t4;
            D[e][r * 6 + 3] = -2.f * t1 - t2 + 2.f * t3 + t4;
            D[e][r * 6 + 4] = 2.f * t1 - t2 - 2.f * t3 + t4;
            D[e][r * 6 + 5] = 4.f * t1 - 5.f * t3 + t5;
        }
    }
}

// ---- F(4,3) input transform: x (channel-major) -> xt[comp][tileG][chunk8][32hi|32lo] ----
__global__ __launch_bounds__(256) void wino_in(const float* __restrict__ x, uint8_t* __restrict__ xt) {
    extern __shared__ float sm[];   // [32 ch][6 rows][67]
    const int f = blockIdx.y, ty = blockIdx.x;
    const int t = threadIdx.x;
    const float* xf = x + (long)f * CHWX;
    const int gr0 = 4 * ty - 1;
    const int tx = t >> 4, j = t & 15;
    const long tileG = (long)f * 256 + ty * 16 + tx;

    // halo columns gc=-1 and gc=64 are always out of image -> zero once
    for (int idx = t; idx < 32 * 6; idx += 256) {
        int r = idx % 6, ch = idx / 6;
        sm[(ch * 6 + r) * 67 + 0] = 0.f;
        sm[(ch * 6 + r) * 67 + 65] = 0.f;
    }

    for (int cc = 0; cc < 8; cc++) {
        __syncthreads();
        for (int idx = t; idx < 32 * 6 * 16; idx += 256) {
            int c4 = idx & 15, rc = idx >> 4;
            int r = rc % 6, ch = rc / 6;
            int gr = gr0 + r;
            float4 v = make_float4(0.f, 0.f, 0.f, 0.f);
            if ((unsigned)gr < 64u)
                v = *(const float4*)(xf + (long)(cc * 32 + ch) * HW + gr * 64 + c4 * 4);
            float* sp = sm + (ch * 6 + r) * 67 + 1 + c4 * 4;
            sp[0] = v.x; sp[1] = v.y; sp[2] = v.z; sp[3] = v.w;
        }
        __syncthreads();
        float D[2][36];
        wtransform(sm, tx, j, D);
        uint8_t* base = xt + tileG * 1024 + cc * 128 + j * 4;
#pragma unroll
        for (int comp = 0; comp < 36; comp++) {
            uint32_t h, l;
            split2(D[0][comp], D[1][comp], h, l);
            *(uint32_t*)(base + (long)comp * XT_PLANE_B) = h;
            *(uint32_t*)(base + (long)comp * XT_PLANE_B + 64) = l;
        }
    }
}

// ---- F(4,3) input transform of pooled (pixel-major): gp -> xtp[comp][tile][chunk4][..] ----
__global__ __launch_bounds__(256) void wino_in_p(const float* __restrict__ gp, uint8_t* __restrict__ xtp) {
    extern __shared__ float sm[];   // [32 ch][6 rows][67]
    const int b = blockIdx.y, ty = blockIdx.x;
    const int t = threadIdx.x;
    const float* gb = gp + (long)b * HW * 128;
    const int gr0 = 4 * ty - 1;
    const int tx = t >> 4, j = t & 15;
    const long tileG = (long)b * 256 + ty * 16 + tx;

    for (int idx = t; idx < 32 * 6; idx += 256) {
        int r = idx % 6, ch = idx / 6;
        sm[(ch * 6 + r) * 67 + 0] = 0.f;
        sm[(ch * 6 + r) * 67 + 65] = 0.f;
    }

    for (int cc = 0; cc < 4; cc++) {
        __syncthreads();
        // interior: pos (r, gc) x ch4; gp pixel-major -> 16B per (pos, ch4)
        for (int idx = t; idx < 6 * 64 * 8; idx += 256) {
            int ch4 = idx & 7, pc = idx >> 3;
            int gc = pc & 63, r = pc >> 6;
            int gr = gr0 + r;
            float4 v = make_float4(0.f, 0.f, 0.f, 0.f);
            if ((unsigned)gr < 64u)
                v = *(const float4*)(gb + (long)(gr * 64 + gc) * 128 + cc * 32 + ch4 * 4);
            int ch = ch4 * 4;
            sm[((ch + 0) * 6 + r) * 67 + 1 + gc] = v.x;
            sm[((ch + 1) * 6 + r) * 67 + 1 + gc] = v.y;
            sm[((ch + 2) * 6 + r) * 67 + 1 + gc] = v.z;
            sm[((ch + 3) * 6 + r) * 67 + 1 + gc] = v.w;
        }
        __syncthreads();
        float D[2][36];
        wtransform(sm, tx, j, D);
        uint8_t* base = xtp + tileG * 512 + cc * 128 + j * 4;
#pragma unroll
        for (int comp = 0; comp < 36; comp++) {
            uint32_t h, l;
            split2(D[0][comp], D[1][comp], h, l);
            *(uint32_t*)(base + (long)comp * XTP_PLANE_B) = h;
            *(uint32_t*)(base + (long)comp * XTP_PLANE_B + 64) = l;
        }
    }
}

// ---------------- persistent Winograd GEMM (3-term bf16, mma.sync) ----------------
// MAP 0: qv (64 tile-blocks/comp), MAP 1: k key-frames, MAP 2: out conv (8 blocks/comp)
template <int NW, int KITERS, int MAP>
__global__ __launch_bounds__(256) void wino_gemm_p(
    const uint8_t* __restrict__ xt, long xtPlaneB,
    const __nv_bfloat16* __restrict__ wt0, const __nv_bfloat16* __restrict__ wt1,
    float* __restrict__ yt0, float* __restrict__ yt1,
    int nItems, long ytPlane)
{
    constexpr int STAGE = 16384 * (1 + NW);
    extern __shared__ __align__(16) char dsm[];
    const uint32_t sb = s2u(dsm);
    const int t = threadIdx.x, lane = t & 31, w = t >> 5;
    const int wm = w >> 2, wn = w & 3;
    const int fp = t >> 1, fsub = (t & 1) * 4;

    const int nloc = (nItems - blockIdx.x + gridDim.x - 1) / gridDim.x;
    if (nloc <= 0) return;
    const int totalP = nloc * KITERS;

    auto issue = [&](int p) {
        const int j = p / KITERS, it = p % KITERS;
        const int item = blockIdx.x + j * (int)gridDim.x;
        int comp; long tileB0;
        if (MAP == 0)      { comp = item >> 6; tileB0 = (long)(item & 63) * 128; }
        else if (MAP == 1) { comp = item >> 3; int tb = item & 7; tileB0 = (long)(tb >> 1) * 2048 + (tb & 1) * 128; }
        else               { comp = item >> 3; tileB0 = (long)(item & 7) * 128; }
        const uint32_t bufB = sb + (p & 3) * STAGE;
        const uint32_t bufA = bufB + 16384;
        const uint8_t* srcB = xt + (long)comp * xtPlaneB + ((tileB0 + fp) * KITERS + it) * 128;
#pragma unroll
        for (int i = 0; i < 4; i++) {
            int q = fsub + i;
            cp16(bufB + fp * 128 + ((q ^ (fp & 7)) << 4), srcB + q * 16);
        }
        const long aoff = ((long)(comp * KITERS + it) * 128 + fp) * 64;
#pragma unroll
        for (int s = 0; s < NW; s++) {
            const uint8_t* srcA = (const uint8_t*)((s ? wt1 : wt0) + aoff);
#pragma unroll
            for (int i = 0; i < 4; i++) {
                int q = fsub + i;
                cp16(bufA + s * 16384 + fp * 128 + ((q ^ (fp & 7)) << 4), srcA + q * 16);
            }
        }
    };

    float acc[NW][4][4][4];
#pragma unroll
    for (int s = 0; s < NW; s++)
#pragma unroll
        for (int i = 0; i < 4; i++)
#pragma unroll
            for (int jj = 0; jj < 4; jj++)
#pragma unroll
                for (int r = 0; r < 4; r++) acc[s][i][jj][r] = 0.f;

#pragma unroll
    for (int p = 0; p < 3; p++) { issue(p); cp_commit(); }

    for (int j = 0; j < nloc; j++) {
        for (int it = 0; it < KITERS; it++) {
            const int p = j * KITERS + it;
            asm volatile("cp.async.wait_group 2;" ::: "memory");
            __syncthreads();
            const uint32_t bufB = sb + (p & 3) * STAGE;
            const uint32_t bufA = bufB + 16384;
#pragma unroll
            for (int ks = 0; ks < 2; ks++) {
                uint32_t Bh[2][4], Bl[2][4];
#pragma unroll
                for (int g = 0; g < 2; g++) {
                    int pp = wn * 32 + g * 16 + (lane & 15);
                    uint32_t rb = bufB + pp * 128;
                    int p7 = pp & 7, qh = ks * 2 + (lane >> 4);
                    ldm4(rb + ((qh ^ p7) << 4), Bh[g]);
                    ldm4(rb + (((qh + 4) ^ p7) << 4), Bl[g]);
                }
#pragma unroll
                for (int s = 0; s < NW; s++) {
#pragma unroll
                    for (int i = 0; i < 4; i++) {
                        int r = wm * 64 + i * 16 + (lane & 15);
                        uint32_t ra = bufA + s * 16384 + r * 128;
                        int r7 = r & 7, qh = ks * 2 + (lane >> 4);
                        uint32_t Ah[4], Al[4];
                        ldm4(ra + ((qh ^ r7) << 4), Ah);
                        ldm4(ra + (((qh + 4) ^ r7) << 4), Al);
#pragma unroll
                        for (int jj = 0; jj < 4; jj++) {
                            int g = jj >> 1, rs = jj & 1;
                            mma16816(acc[s][i][jj], Ah, Bh[g][rs], Bh[g][rs + 2]);
                            mma16816(acc[s][i][jj], Ah, Bl[g][rs], Bl[g][rs + 2]);
                            mma16816(acc[s][i][jj], Al, Bh[g][rs], Bh[g][rs + 2]);
                        }
                    }
                }
            }
            if (p + 3 < totalP) issue(p + 3);
            cp_commit();
        }

        // ---- epilogue (buffer 3 free for staging) ----
        {
            const int item = blockIdx.x + j * (int)gridDim.x;
            int comp; long ytTile0;
            if (MAP == 0) { comp = item >> 6; ytTile0 = (long)(item & 63) * 128; }
            else          { comp = item >> 3; ytTile0 = (long)(item & 7) * 128; }
            float* stage = (float*)(dsm + 3 * STAGE);
#pragma unroll
            for (int s = 0; s < NW; s++) {
                float* ytS = (s ? yt1 : yt0) + (long)comp * ytPlane + ytTile0 * 128;
#pragma unroll
                for (int pass = 0; pass < 4; pass++) {
                    __syncthreads();
                    if (wn == pass) {
#pragma unroll
                        for (int i = 0; i < 4; i++) {
                            int m = wm * 64 + i * 16 + (lane >> 2);
#pragma unroll
                            for (int jj = 0; jj < 4; jj++) {
                                int nn = jj * 8 + (lane & 3) * 2;
                                stage[nn * 132 + m]           = acc[s][i][jj][0];
                                stage[(nn + 1) * 132 + m]     = acc[s][i][jj][1];
                                stage[nn * 132 + m + 8]       = acc[s][i][jj][2];
                                stage[(nn + 1) * 132 + m + 8] = acc[s][i][jj][3];
                            }
                        }
                    }
                    __syncthreads();
#pragma unroll
                    for (int kk = 0; kk < 4; kk++) {
                        int idx = t + kk * 256;
                        int r = idx >> 5, q = idx & 31;
                        *(float4*)(ytS + (long)(pass * 32 + r) * 128 + q * 4) =
                            *(float4*)(stage + r * 132 + q * 4);
                    }
                }
            }
            __syncthreads();
#pragma unroll
            for (int s = 0; s < NW; s++)
#pragma unroll
                for (int i = 0; i < 4; i++)
#pragma unroll
                    for (int jj = 0; jj < 4; jj++)
#pragma unroll
                        for (int r = 0; r < 4; r++) acc[s][i][jj][r] = 0.f;
        }
    }
}

// ---- F(4,3) inverse transform of 36 comps -> 16 pixels (register-resident) ----
__device__ __forceinline__ void inv36(const float* __restrict__ Y, long plane, float* o) {
    float y[36];
#pragma unroll
    for (int c = 0; c < 36; c++) y[c] = __ldg(Y + c * plane);
    float Z[4][6];
#pragma unroll
    for (int c = 0; c < 6; c++) {
        float a0 = y[c], a1 = y[6 + c], a2 = y[12 + c],
              a3 = y[18 + c], a4 = y[24 + c], a5 = y[30 + c];
        Z[0][c] = a0 + a1 + a2 + a3 + a4;
        Z[1][c] = a1 - a2 + 2.f * a3 - 2.f * a4;
        Z[2][c] = a1 + a2 + 4.f * a3 + 4.f * a4;
        Z[3][c] = a1 - a2 + 8.f * a3 - 8.f * a4 + a5;
    }
#pragma unroll
    for (int a = 0; a < 4; a++) {
        float z0 = Z[a][0], z1 = Z[a][1], z2 = Z[a][2],
              z3 = Z[a][3], z4 = Z[a][4], z5 = Z[a][5];
        o[a * 4 + 0] = z0 + z1 + z2 + z3 + z4;
        o[a * 4 + 1] = z1 - z2 + 2.f * z3 - 2.f * z4;
        o[a * 4 + 2] = z1 + z2 + 4.f * z3 + 4.f * z4;
        o[a * 4 + 3] = z1 - z2 + 8.f * z3 - 8.f * z4 + z5;
    }
}

// ---- fused inverse-transform + attention -> pooled fp32 pixel-major ----
__global__ __launch_bounds__(256) void attn_wino(
    const float* __restrict__ yt, const float* __restrict__ ytk,
    float* __restrict__ gp)
{
    __shared__ float sdots[2][4][16];
    __shared__ float fdots[2][16];
    __shared__ float stage[2][16][128];
    const int t = threadIdx.x, lane = t & 31;
    const int oc = t & 127, tl = t >> 7;
    const int wsub = (t >> 5) & 3;
    const int b = blockIdx.x >> 7, tp = blockIdx.x & 127;
    const int tloc = tp * 2 + tl;

    float k16[16];
    inv36(ytk + (long)(b * 256 + tloc) * 128 + oc, YTK_PLANE, k16);

    float m[16], s[16], acc[16];

    for (int f = 0; f < 8; f++) {
        const long tg = ((long)((b * 8 + f) * 256 + tloc)) * 128 + oc;
        float q16[16];
        inv36(yt + tg, YT_PLANE, q16);
        float p[16];
#pragma unroll
        for (int px = 0; px < 16; px++) p[px] = q16[px] * k16[px];
#pragma unroll
        for (int off = 16; off; off >>= 1)
#pragma unroll
            for (int px = 0; px < 16; px++) p[px] += __shfl_xor_sync(0xFFFFFFFFu, p[px], off);
        if (lane == 0)
#pragma unroll
            for (int px = 0; px < 16; px++) sdots[tl][wsub][px] = p[px];
        __syncthreads();
        if (t < 32) {
            int t2 = t >> 4, px = t & 15;
            fdots[t2][px] = sdots[t2][0][px] + sdots[t2][1][px] + sdots[t2][2][px] + sdots[t2][3][px];
        }
        float v16[16];
        inv36(yt + YT_SET + tg, YT_PLANE, v16);
        __syncthreads();
#pragma unroll
        for (int px = 0; px < 16; px++) {
            float d = fdots[tl][px];
            if (f == 0) { m[px] = d; s[px] = 1.f; acc[px] = v16[px]; }
            else {
                float nm = fmaxf(m[px], d);
                float sc = expf(m[px] - nm);
                float e  = expf(d - nm);
                s[px] = s[px] * sc + e;
                acc[px] = acc[px] * sc + e * v16[px];
                m[px] = nm;
            }
        }
    }

#pragma unroll
    for (int px = 0; px < 16; px++) stage[tl][px][oc] = acc[px] / s[px];
    __syncthreads();
    for (int idx = t; idx < 2 * 16 * 32; idx += 256) {
        int l = idx & 31, px = (idx >> 5) & 15, tt = idx >> 9;
        int tw = tp * 2 + tt;
        int ty = tw >> 4, tx = tw & 15;
        int pix = (4 * ty + (px >> 2)) * 64 + 4 * tx + (px & 3);
        float4 v = *(float4*)&stage[tt][px][l * 4];
        *(float4*)(gp + ((long)(b * HW + pix)) * 128 + l * 4) = v;
    }
}

// ---- final: inverse transform + bias + T-broadcast, full-row staged stores ----
__global__ __launch_bounds__(256) void wino_out_final(
    const float* __restrict__ yto, const float* __restrict__ bias, float* __restrict__ out)
{
    extern __shared__ float st[];   // [4 rows][64 cols][128 oc] = 128KB
    const int b = blockIdx.x >> 5, rest = blockIdx.x & 31;
    const int ty = rest >> 1, half = rest & 1;
    const int t = threadIdx.x;
    const int oc = t & 127, tl = t >> 7;

    for (int pass = 0; pass < 8; pass++) {
        int tx = pass * 2 + tl;
        long tile = (long)b * 256 + ty * 16 + tx;
        const float* Y = yto + (long)half * YTO_HALF + tile * 128 + oc;
        float o[16];
        inv36(Y, YTO_PLANE, o);
#pragma unroll
        for (int px = 0; px < 16; px++)
            st[((px >> 2) * 64 + tx * 4 + (px & 3)) * 128 + oc] = o[px];
    }
    __syncthreads();

    for (int u = t; u < 512; u += 256) {
        int oc2 = u & 127, row = u >> 7;
        float bv = bias[half * 128 + oc2];
        float4 rv[16];
#pragma unroll
        for (int c4 = 0; c4 < 16; c4++) {
            rv[c4].x = st[(row * 64 + c4 * 4 + 0) * 128 + oc2] + bv;
            rv[c4].y = st[(row * 64 + c4 * 4 + 1) * 128 + oc2] + bv;
            rv[c4].z = st[(row * 64 + c4 * 4 + 2) * 128 + oc2] + bv;
            rv[c4].w = st[(row * 64 + c4 * 4 + 3) * 128 + oc2] + bv;
        }
#pragma unroll
        for (int tt = 0; tt < 8; tt++) {
            float* op = out + ((long)(b * 8 + tt) * 256 + half * 128 + oc2) * HW
                        + (ty * 4 + row) * 64;
#pragma unroll
            for (int c4 = 0; c4 < 16; c4++)
                *(float4*)(op + c4 * 4) = rv[c4];
        }
    }
}

// ---------------------------------------------------------------------------
extern "C" void kernel_launch(void* const* d_in, const int* in_sizes, int n_in,
                              void* d_out, int out_size)
{
    const float* x     = (const float*)d_in[0];
    const float* w_k   = (const float*)d_in[1];
    const float* w_q   = (const float*)d_in[2];
    const float* w_v   = (const float*)d_in[3];
    const float* w_out = (const float*)d_in[4];
    const float* b_out = (const float*)d_in[5];
    float* out = (float*)d_out;

    void* basev = nullptr;
    cudaGetSymbolAddress(&basev, g_scratch);
    float* S = (float*)basev;
    float* gp = S + OFF_GP;
    __nv_bfloat16* wtO0 = (__nv_bfloat16*)(S + OFF_WTO0);
    __nv_bfloat16* wtO1 = (__nv_bfloat16*)(S + OFF_WTO1);
    __nv_bfloat16* wtq  = (__nv_bfloat16*)(S + OFF_WTQ);
    __nv_bfloat16* wtv  = (__nv_bfloat16*)(S + OFF_WTV);
    __nv_bfloat16* wtk  = (__nv_bfloat16*)(S + OFF_WTK);
    uint8_t* xtp = (uint8_t*)(S + OFF_XTP);
    float*   yto = S + OFF_YTO;
    uint8_t* xt  = (uint8_t*)(S + OFF_XT);
    float*   yt  = S + OFF_YT;
    float*   ytk = S + OFF_YTK;

    const int DSM1 = 4 * 32768;
    const int DSM2 = 4 * 49152;
    const int DSMW = 32 * 6 * 67 * 4;
    const int DSMF = 4 * 64 * 128 * 4;
    cudaFuncSetAttribute(wino_gemm_p<2, 8, 0>, cudaFuncAttributeMaxDynamicSharedMemorySize, DSM2);
    cudaFuncSetAttribute(wino_gemm_p<1, 8, 1>, cudaFuncAttributeMaxDynamicSharedMemorySize, DSM1);
    cudaFuncSetAttribute(wino_gemm_p<2, 4, 2>, cudaFuncAttributeMaxDynamicSharedMemorySize, DSM2);
    cudaFuncSetAttribute(wino_in,   cudaFuncAttributeMaxDynamicSharedMemorySize, DSMW);
    cudaFuncSetAttribute(wino_in_p, cudaFuncAttributeMaxDynamicSharedMemorySize, DSMW);
    cudaFuncSetAttribute(wino_out_final, cudaFuncAttributeMaxDynamicSharedMemorySize, DSMF);

    wino_w<<<128, 256>>>(w_q, wtq);
    wino_w<<<128, 256>>>(w_v, wtv);
    wino_w<<<128, 256>>>(w_k, wtk);
    wino_w_out<<<128, 256>>>(w_out, wtO0, wtO1);
    wino_in<<<dim3(16, 32), 256, DSMW>>>(x, xt);

    // fused q+v Winograd GEMM: persistent, 2304 items
    wino_gemm_p<2, 8, 0><<<148, 256, DSM2>>>(xt, XT_PLANE_B, wtq, wtv, yt, yt + YT_SET, 2304, YT_PLANE);
    // k Winograd GEMM over key frames 0/8/16/24: 288 items
    wino_gemm_p<1, 8, 1><<<148, 256, DSM1>>>(xt, XT_PLANE_B, wtk, nullptr, ytk, nullptr, 288, YTK_PLANE);

    // fused inverse transform + attention -> pooled fp32 pixel-major
    attn_wino<<<512, 256>>>(yt, ytk, gp);

    // out conv via Winograd: forward transform, GEMM (M=256 as two halves), inverse+bias+broadcast
    wino_in_p<<<dim3(16, 4), 256, DSMW>>>(gp, xtp);
    wino_gemm_p<2, 4, 2><<<148, 256, DSM2>>>(xtp, XTP_PLANE_B, wtO0, wtO1, yto, yto + YTO_HALF, 288, YTO_PLANE);
    wino_out_final<<<128, 256, DSMF>>>(yto, b_out, out);
}

// round 11
// speedup vs baseline: 6.5479x; 1.0264x over previous
#include <cuda_runtime.h>
#include <cuda_fp16.h>
#include <cstdint>

#define HW 4096
#define CHWX ((long)256 * HW)

// float offsets in g_scratch
#define OFF_GP    35651584L
#define OFF_WTO0  37748736L
#define OFF_WTO1  38338560L
#define OFF_WTQ   38928384L
#define OFF_WTV   40108032L
#define OFF_WTK   41287680L
#define OFF_XTP   42467328L
#define OFF_YTO   47185920L
#define OFF_XT    56623104L
#define OFF_YT    132120576L
#define OFF_YTK   207618048L
__device__ __align__(256) float g_scratch[212336640];

#define XT_PLANE_B  8388608L
#define XTP_PLANE_B 524288L
#define YT_PLANE    1048576L
#define YT_SET      37748736L
#define YTK_PLANE   131072L
#define YTO_PLANE   131072L
#define YTO_HALF    4718592L

// ---------------- helpers ----------------
__device__ __forceinline__ uint32_t s2u(const void* p) {
    uint32_t a;
    asm("{ .reg .u64 t; cvta.to.shared.u64 t, %1; cvt.u32.u64 %0, t; }" : "=r"(a) : "l"(p));
    return a;
}
// fp16 hi/lo split of two fp32 (f0 -> low half)
__device__ __forceinline__ void split2(float f0, float f1, uint32_t& hi, uint32_t& lo) {
    uint32_t h;
    asm("cvt.rn.f16x2.f32 %0, %1, %2;" : "=r"(h) : "f"(f1), "f"(f0));
    __half2 hh = *reinterpret_cast<__half2*>(&h);
    float l0 = f0 - __low2float(hh);
    float l1 = f1 - __high2float(hh);
    uint32_t l;
    asm("cvt.rn.f16x2.f32 %0, %1, %2;" : "=r"(l) : "f"(l1), "f"(l0));
    hi = h; lo = l;
}
__device__ __forceinline__ void ldm4(uint32_t a, uint32_t* r) {
    asm volatile("ldmatrix.sync.aligned.m8n8.x4.shared.b16 {%0,%1,%2,%3}, [%4];"
                 : "=r"(r[0]), "=r"(r[1]), "=r"(r[2]), "=r"(r[3]) : "r"(a));
}
__device__ __forceinline__ void mma_f32(float* c, const uint32_t* a, uint32_t b0, uint32_t b1) {
    asm volatile("mma.sync.aligned.m16n8k16.row.col.f32.f16.f16.f32 "
                 "{%0,%1,%2,%3}, {%4,%5,%6,%7}, {%8,%9}, {%0,%1,%2,%3};"
                 : "+f"(c[0]), "+f"(c[1]), "+f"(c[2]), "+f"(c[3])
                 : "r"(a[0]), "r"(a[1]), "r"(a[2]), "r"(a[3]), "r"(b0), "r"(b1));
}
__device__ __forceinline__ void mma_f16(uint32_t* c, const uint32_t* a, uint32_t b0, uint32_t b1) {
    asm volatile("mma.sync.aligned.m16n8k16.row.col.f16.f16.f16.f16 "
                 "{%0,%1}, {%2,%3,%4,%5}, {%6,%7}, {%0,%1};"
                 : "+r"(c[0]), "+r"(c[1])
                 : "r"(a[0]), "r"(a[1]), "r"(a[2]), "r"(a[3]), "r"(b0), "r"(b1));
}
__device__ __forceinline__ void cp16(uint32_t d, const void* s) {
    asm volatile("cp.async.cg.shared.global [%0], [%1], 16;" :: "r"(d), "l"(s));
}
__device__ __forceinline__ void cp_commit() { asm volatile("cp.async.commit_group;" ::: "memory"); }

// ---- F(4,3) weight transform: w(128,256,3,3) -> wt[comp36*8+chunk][oc128][32hi|32lo fp16] ----
__global__ void wino_w(const float* __restrict__ src, __half* __restrict__ dst) {
    int t = blockIdx.x * blockDim.x + threadIdx.x;
    if (t >= 128 * 256) return;
    int ic = t & 255, oc = t >> 8;
    float g[3][3];
#pragma unroll
    for (int r = 0; r < 3; r++)
#pragma unroll
        for (int c = 0; c < 3; c++)
            g[r][c] = src[((long)oc * 256 + ic) * 9 + r * 3 + c];
    const float i6 = 1.f / 6.f, i12 = 1.f / 12.f, i24 = 1.f / 24.f;
    float R[6][3];
#pragma unroll
    for (int c = 0; c < 3; c++) {
        R[0][c] = 0.25f * g[0][c];
        R[1][c] = -i6 * (g[0][c] + g[1][c] + g[2][c]);
        R[2][c] = i6 * (-g[0][c] + g[1][c] - g[2][c]);
        R[3][c] = i24 * g[0][c] + i12 * g[1][c] + i6 * g[2][c];
        R[4][c] = i24 * g[0][c] - i12 * g[1][c] + i6 * g[2][c];
        R[5][c] = g[2][c];
    }
    float U[6][6];
#pragma unroll
    for (int r = 0; r < 6; r++) {
        U[r][0] = 0.25f * R[r][0];
        U[r][1] = -i6 * (R[r][0] + R[r][1] + R[r][2]);
        U[r][2] = i6 * (-R[r][0] + R[r][1] - R[r][2]);
        U[r][3] = i24 * R[r][0] + i12 * R[r][1] + i6 * R[r][2];
        U[r][4] = i24 * R[r][0] - i12 * R[r][1] + i6 * R[r][2];
        U[r][5] = R[r][2];
    }
#pragma unroll
    for (int comp = 0; comp < 36; comp++) {
        float x = U[comp / 6][comp % 6];
        __half hb = __float2half_rn(x);
        float lo = x - __half2float(hb);
        long base = ((long)(comp * 8 + (ic >> 5)) * 128 + oc) * 64 + (ic & 31);
        dst[base] = hb;
        dst[base + 32] = __float2half_rn(lo);
    }
}

// ---- F(4,3) weight transform for out conv: w(256,128,3,3) -> two 128-oc halves ----
__global__ void wino_w_out(const float* __restrict__ src,
                           __half* __restrict__ dst0, __half* __restrict__ dst1) {
    int t = blockIdx.x * blockDim.x + threadIdx.x;
    if (t >= 256 * 128) return;
    int ic = t & 127, oc = t >> 7;
    float g[3][3];
#pragma unroll
    for (int r = 0; r < 3; r++)
#pragma unroll
        for (int c = 0; c < 3; c++)
            g[r][c] = src[((long)oc * 128 + ic) * 9 + r * 3 + c];
    const float i6 = 1.f / 6.f, i12 = 1.f / 12.f, i24 = 1.f / 24.f;
    float R[6][3];
#pragma unroll
    for (int c = 0; c < 3; c++) {
        R[0][c] = 0.25f * g[0][c];
        R[1][c] = -i6 * (g[0][c] + g[1][c] + g[2][c]);
        R[2][c] = i6 * (-g[0][c] + g[1][c] - g[2][c]);
        R[3][c] = i24 * g[0][c] + i12 * g[1][c] + i6 * g[2][c];
        R[4][c] = i24 * g[0][c] - i12 * g[1][c] + i6 * g[2][c];
        R[5][c] = g[2][c];
    }
    float U[6][6];
#pragma unroll
    for (int r = 0; r < 6; r++) {
        U[r][0] = 0.25f * R[r][0];
        U[r][1] = -i6 * (R[r][0] + R[r][1] + R[r][2]);
        U[r][2] = i6 * (-R[r][0] + R[r][1] - R[r][2]);
        U[r][3] = i24 * R[r][0] + i12 * R[r][1] + i6 * R[r][2];
        U[r][4] = i24 * R[r][0] - i12 * R[r][1] + i6 * R[r][2];
        U[r][5] = R[r][2];
    }
    __half* dst = (oc < 128) ? dst0 : dst1;
    int ocl = oc & 127;
#pragma unroll
    for (int comp = 0; comp < 36; comp++) {
        float x = U[comp / 6][comp % 6];
        __half hb = __float2half_rn(x);
        float lo = x - __half2float(hb);
        long base = ((long)(comp * 4 + (ic >> 5)) * 128 + ocl) * 64 + (ic & 31);
        dst[base] = hb;
        dst[base + 32] = __float2half_rn(lo);
    }
}

// ---- shared transform core: sm[32ch][6r][67] -> D[2][36] for (tx, j) ----
__device__ __forceinline__ void wtransform(const float* sm, int tx, int j, float D[2][36]) {
#pragma unroll
    for (int e = 0; e < 2; e++) {
        const float* s = sm + (2 * j + e) * 402 + 4 * tx;
        float T[6][6];
#pragma unroll
        for (int c = 0; c < 6; c++) {
            float x0 = s[c], x1 = s[67 + c], x2 = s[134 + c],
                  x3 = s[201 + c], x4 = s[268 + c], x5 = s[335 + c];
            T[0][c] = 4.f * x0 - 5.f * x2 + x4;
            T[1][c] = -4.f * x1 - 4.f * x2 + x3 + x4;
            T[2][c] = 4.f * x1 - 4.f * x2 - x3 + x4;
            T[3][c] = -2.f * x1 - x2 + 2.f * x3 + x4;
            T[4][c] = 2.f * x1 - x2 - 2.f * x3 + x4;
            T[5][c] = 4.f * x1 - 5.f * x3 + x5;
        }
#pragma unroll
        for (int r = 0; r < 6; r++) {
            float t0 = T[r][0], t1 = T[r][1], t2 = T[r][2],
                  t3 = T[r][3], t4 = T[r][4], t5 = T[r][5];
            D[e][r * 6 + 0] = 4.f * t0 - 5.f * t2 + t4;
            D[e][r * 6 + 1] = -4.f * t1 - 4.f * t2 + t3 + t4;
            D[e][r * 6 + 2] = 4.f * t1 - 4.f * t2 - t3 + t4;
            D[e][r * 6 + 3] = -2.f * t1 - t2 + 2.f * t3 + t4;
            D[e][r * 6 + 4] = 2.f * t1 - t2 - 2.f * t3 + t4;
            D[e][r * 6 + 5] = 4.f * t1 - 5.f * t3 + t5;
        }
    }
}

// ---- F(4,3) input transform: x (channel-major) -> xt[comp][tileG][chunk8][32hi|32lo fp16] ----
__global__ __launch_bounds__(256) void wino_in(const float* __restrict__ x, uint8_t* __restrict__ xt) {
    extern __shared__ float sm[];   // [32 ch][6 rows][67]
    const int f = blockIdx.y, ty = blockIdx.x;
    const int t = threadIdx.x;
    const float* xf = x + (long)f * CHWX;
    const int gr0 = 4 * ty - 1;
    const int tx = t >> 4, j = t & 15;
    const long tileG = (long)f * 256 + ty * 16 + tx;

    for (int idx = t; idx < 32 * 6; idx += 256) {
        int r = idx % 6, ch = idx / 6;
        sm[(ch * 6 + r) * 67 + 0] = 0.f;
        sm[(ch * 6 + r) * 67 + 65] = 0.f;
    }

    for (int cc = 0; cc < 8; cc++) {
        __syncthreads();
        for (int idx = t; idx < 32 * 6 * 16; idx += 256) {
            int c4 = idx & 15, rc = idx >> 4;
            int r = rc % 6, ch = rc / 6;
            int gr = gr0 + r;
            float4 v = make_float4(0.f, 0.f, 0.f, 0.f);
            if ((unsigned)gr < 64u)
                v = *(const float4*)(xf + (long)(cc * 32 + ch) * HW + gr * 64 + c4 * 4);
            float* sp = sm + (ch * 6 + r) * 67 + 1 + c4 * 4;
            sp[0] = v.x; sp[1] = v.y; sp[2] = v.z; sp[3] = v.w;
        }
        __syncthreads();
        float D[2][36];
        wtransform(sm, tx, j, D);
        uint8_t* base = xt + tileG * 1024 + cc * 128 + j * 4;
#pragma unroll
        for (int comp = 0; comp < 36; comp++) {
            uint32_t h, l;
            split2(D[0][comp], D[1][comp], h, l);
            *(uint32_t*)(base + (long)comp * XT_PLANE_B) = h;
            *(uint32_t*)(base + (long)comp * XT_PLANE_B + 64) = l;
        }
    }
}

// ---- F(4,3) input transform of pooled (pixel-major): gp -> xtp ----
__global__ __launch_bounds__(256) void wino_in_p(const float* __restrict__ gp, uint8_t* __restrict__ xtp) {
    extern __shared__ float sm[];
    const int b = blockIdx.y, ty = blockIdx.x;
    const int t = threadIdx.x;
    const float* gb = gp + (long)b * HW * 128;
    const int gr0 = 4 * ty - 1;
    const int tx = t >> 4, j = t & 15;
    const long tileG = (long)b * 256 + ty * 16 + tx;

    for (int idx = t; idx < 32 * 6; idx += 256) {
        int r = idx % 6, ch = idx / 6;
        sm[(ch * 6 + r) * 67 + 0] = 0.f;
        sm[(ch * 6 + r) * 67 + 65] = 0.f;
    }

    for (int cc = 0; cc < 4; cc++) {
        __syncthreads();
        for (int idx = t; idx < 6 * 64 * 8; idx += 256) {
            int ch4 = idx & 7, pc = idx >> 3;
            int gc = pc & 63, r = pc >> 6;
            int gr = gr0 + r;
            float4 v = make_float4(0.f, 0.f, 0.f, 0.f);
            if ((unsigned)gr < 64u)
                v = *(const float4*)(gb + (long)(gr * 64 + gc) * 128 + cc * 32 + ch4 * 4);
            int ch = ch4 * 4;
            sm[((ch + 0) * 6 + r) * 67 + 1 + gc] = v.x;
            sm[((ch + 1) * 6 + r) * 67 + 1 + gc] = v.y;
            sm[((ch + 2) * 6 + r) * 67 + 1 + gc] = v.z;
            sm[((ch + 3) * 6 + r) * 67 + 1 + gc] = v.w;
        }
        __syncthreads();
        float D[2][36];
        wtransform(sm, tx, j, D);
        uint8_t* base = xtp + tileG * 512 + cc * 128 + j * 4;
#pragma unroll
        for (int comp = 0; comp < 36; comp++) {
            uint32_t h, l;
            split2(D[0][comp], D[1][comp], h, l);
            *(uint32_t*)(base + (long)comp * XTP_PLANE_B) = h;
            *(uint32_t*)(base + (long)comp * XTP_PLANE_B + 64) = l;
        }
    }
}

// ---------------- persistent Winograd GEMM (fp16 split: f32-acc hi*hi + f16-acc cross) ----------------
// MAP 0: qv (64 tile-blocks/comp), MAP 1: k key-frames, MAP 2: out conv (8 blocks/comp)
template <int NW, int KITERS, int MAP>
__global__ __launch_bounds__(256) void wino_gemm_p(
    const uint8_t* __restrict__ xt, long xtPlaneB,
    const __half* __restrict__ wt0, const __half* __restrict__ wt1,
    float* __restrict__ yt0, float* __restrict__ yt1,
    int nItems, long ytPlane)
{
    constexpr int STAGE = 16384 * (1 + NW);
    extern __shared__ __align__(16) char dsm[];
    const uint32_t sb = s2u(dsm);
    const int t = threadIdx.x, lane = t & 31, w = t >> 5;
    const int wm = w >> 2, wn = w & 3;
    const int fp = t >> 1, fsub = (t & 1) * 4;

    const int nloc = (nItems - blockIdx.x + gridDim.x - 1) / gridDim.x;
    if (nloc <= 0) return;
    const int totalP = nloc * KITERS;

    auto issue = [&](int p) {
        const int j = p / KITERS, it = p % KITERS;
        const int item = blockIdx.x + j * (int)gridDim.x;
        int comp; long tileB0;
        if (MAP == 0)      { comp = item >> 6; tileB0 = (long)(item & 63) * 128; }
        else if (MAP == 1) { comp = item >> 3; int tb = item & 7; tileB0 = (long)(tb >> 1) * 2048 + (tb & 1) * 128; }
        else               { comp = item >> 3; tileB0 = (long)(item & 7) * 128; }
        const uint32_t bufB = sb + (p & 3) * STAGE;
        const uint32_t bufA = bufB + 16384;
        const uint8_t* srcB = xt + (long)comp * xtPlaneB + ((tileB0 + fp) * KITERS + it) * 128;
#pragma unroll
        for (int i = 0; i < 4; i++) {
            int q = fsub + i;
            cp16(bufB + fp * 128 + ((q ^ (fp & 7)) << 4), srcB + q * 16);
        }
        const long aoff = ((long)(comp * KITERS + it) * 128 + fp) * 64;
#pragma unroll
        for (int s = 0; s < NW; s++) {
            const uint8_t* srcA = (const uint8_t*)((s ? wt1 : wt0) + aoff);
#pragma unroll
            for (int i = 0; i < 4; i++) {
                int q = fsub + i;
                cp16(bufA + s * 16384 + fp * 128 + ((q ^ (fp & 7)) << 4), srcA + q * 16);
            }
        }
    };

    float acc[NW][4][4][4];
    uint32_t acch[NW][4][4][2];
#pragma unroll
    for (int s = 0; s < NW; s++)
#pragma unroll
        for (int i = 0; i < 4; i++)
#pragma unroll
            for (int jj = 0; jj < 4; jj++) {
#pragma unroll
                for (int r = 0; r < 4; r++) acc[s][i][jj][r] = 0.f;
                acch[s][i][jj][0] = 0u; acch[s][i][jj][1] = 0u;
            }

#pragma unroll
    for (int p = 0; p < 3; p++) { issue(p); cp_commit(); }

    for (int j = 0; j < nloc; j++) {
        for (int it = 0; it < KITERS; it++) {
            const int p = j * KITERS + it;
            asm volatile("cp.async.wait_group 2;" ::: "memory");
            __syncthreads();
            const uint32_t bufB = sb + (p & 3) * STAGE;
            const uint32_t bufA = bufB + 16384;
#pragma unroll
            for (int ks = 0; ks < 2; ks++) {
                uint32_t Bh[2][4], Bl[2][4];
#pragma unroll
                for (int g = 0; g < 2; g++) {
                    int pp = wn * 32 + g * 16 + (lane & 15);
                    uint32_t rb = bufB + pp * 128;
                    int p7 = pp & 7, qh = ks * 2 + (lane >> 4);
                    ldm4(rb + ((qh ^ p7) << 4), Bh[g]);
                    ldm4(rb + (((qh + 4) ^ p7) << 4), Bl[g]);
                }
#pragma unroll
                for (int s = 0; s < NW; s++) {
#pragma unroll
                    for (int i = 0; i < 4; i++) {
                        int r = wm * 64 + i * 16 + (lane & 15);
                        uint32_t ra = bufA + s * 16384 + r * 128;
                        int r7 = r & 7, qh = ks * 2 + (lane >> 4);
                        uint32_t Ah[4], Al[4];
                        ldm4(ra + ((qh ^ r7) << 4), Ah);
                        ldm4(ra + (((qh + 4) ^ r7) << 4), Al);
#pragma unroll
                        for (int jj = 0; jj < 4; jj++) {
                            int g = jj >> 1, rs = jj & 1;
                            mma_f32(acc[s][i][jj], Ah, Bh[g][rs], Bh[g][rs + 2]);
                            mma_f16(acch[s][i][jj], Ah, Bl[g][rs], Bl[g][rs + 2]);
                            mma_f16(acch[s][i][jj], Al, Bh[g][rs], Bh[g][rs + 2]);
                        }
                    }
                }
            }
            if (p + 3 < totalP) issue(p + 3);
            cp_commit();
        }

        // ---- epilogue (buffer 3 free for staging) ----
        {
            const int item = blockIdx.x + j * (int)gridDim.x;
            int comp; long ytTile0;
            if (MAP == 0) { comp = item >> 6; ytTile0 = (long)(item & 63) * 128; }
            else          { comp = item >> 3; ytTile0 = (long)(item & 7) * 128; }
            float* stage = (float*)(dsm + 3 * STAGE);
#pragma unroll
            for (int s = 0; s < NW; s++) {
                float* ytS = (s ? yt1 : yt0) + (long)comp * ytPlane + ytTile0 * 128;
#pragma unroll
                for (int pass = 0; pass < 4; pass++) {
                    __syncthreads();
                    if (wn == pass) {
#pragma unroll
                        for (int i = 0; i < 4; i++) {
                            int m = wm * 64 + i * 16 + (lane >> 2);
#pragma unroll
                            for (int jj = 0; jj < 4; jj++) {
                                int nn = jj * 8 + (lane & 3) * 2;
                                __half2 c01 = *(__half2*)&acch[s][i][jj][0];
                                __half2 c23 = *(__half2*)&acch[s][i][jj][1];
                                stage[nn * 132 + m]           = acc[s][i][jj][0] + __low2float(c01);
                                stage[(nn + 1) * 132 + m]     = acc[s][i][jj][1] + __high2float(c01);
                                stage[nn * 132 + m + 8]       = acc[s][i][jj][2] + __low2float(c23);
                                stage[(nn + 1) * 132 + m + 8] = acc[s][i][jj][3] + __high2float(c23);
                            }
                        }
                    }
                    __syncthreads();
#pragma unroll
                    for (int kk = 0; kk < 4; kk++) {
                        int idx = t + kk * 256;
                        int r = idx >> 5, q = idx & 31;
                        *(float4*)(ytS + (long)(pass * 32 + r) * 128 + q * 4) =
                            *(float4*)(stage + r * 132 + q * 4);
                    }
                }
            }
            __syncthreads();
#pragma unroll
            for (int s = 0; s < NW; s++)
#pragma unroll
                for (int i = 0; i < 4; i++)
#pragma unroll
                    for (int jj = 0; jj < 4; jj++) {
#pragma unroll
                        for (int r = 0; r < 4; r++) acc[s][i][jj][r] = 0.f;
                        acch[s][i][jj][0] = 0u; acch[s][i][jj][1] = 0u;
                    }
        }
    }
}

// ---- F(4,3) inverse transform of 36 comps -> 16 pixels (register-resident) ----
__device__ __forceinline__ void inv36(const float* __restrict__ Y, long plane, float* o) {
    float y[36];
#pragma unroll
    for (int c = 0; c < 36; c++) y[c] = __ldg(Y + c * plane);
    float Z[4][6];
#pragma unroll
    for (int c = 0; c < 6; c++) {
        float a0 = y[c], a1 = y[6 + c], a2 = y[12 + c],
              a3 = y[18 + c], a4 = y[24 + c], a5 = y[30 + c];
        Z[0][c] = a0 + a1 + a2 + a3 + a4;
        Z[1][c] = a1 - a2 + 2.f * a3 - 2.f * a4;
        Z[2][c] = a1 + a2 + 4.f * a3 + 4.f * a4;
        Z[3][c] = a1 - a2 + 8.f * a3 - 8.f * a4 + a5;
    }
#pragma unroll
    for (int a = 0; a < 4; a++) {
        float z0 = Z[a][0], z1 = Z[a][1], z2 = Z[a][2],
              z3 = Z[a][3], z4 = Z[a][4], z5 = Z[a][5];
        o[a * 4 + 0] = z0 + z1 + z2 + z3 + z4;
        o[a * 4 + 1] = z1 - z2 + 2.f * z3 - 2.f * z4;
        o[a * 4 + 2] = z1 + z2 + 4.f * z3 + 4.f * z4;
        o[a * 4 + 3] = z1 - z2 + 8.f * z3 - 8.f * z4 + z5;
    }
}

// ---- fused inverse-transform + attention -> pooled fp32 pixel-major ----
__global__ __launch_bounds__(256) void attn_wino(
    const float* __restrict__ yt, const float* __restrict__ ytk,
    float* __restrict__ gp)
{
    __shared__ float sdots[2][4][16];
    __shared__ float fdots[2][16];
    __shared__ float stage[2][16][128];
    const int t = threadIdx.x, lane = t & 31;
    const int oc = t & 127, tl = t >> 7;
    const int wsub = (t >> 5) & 3;
    const int b = blockIdx.x >> 7, tp = blockIdx.x & 127;
    const int tloc = tp * 2 + tl;

    float k16[16];
    inv36(ytk + (long)(b * 256 + tloc) * 128 + oc, YTK_PLANE, k16);

    float m[16], s[16], acc[16];

    for (int f = 0; f < 8; f++) {
        const long tg = ((long)((b * 8 + f) * 256 + tloc)) * 128 + oc;
        float q16[16];
        inv36(yt + tg, YT_PLANE, q16);
        float p[16];
#pragma unroll
        for (int px = 0; px < 16; px++) p[px] = q16[px] * k16[px];
#pragma unroll
        for (int off = 16; off; off >>= 1)
#pragma unroll
            for (int px = 0; px < 16; px++) p[px] += __shfl_xor_sync(0xFFFFFFFFu, p[px], off);
        if (lane == 0)
#pragma unroll
            for (int px = 0; px < 16; px++) sdots[tl][wsub][px] = p[px];
        __syncthreads();
        if (t < 32) {
            int t2 = t >> 4, px = t & 15;
            fdots[t2][px] = sdots[t2][0][px] + sdots[t2][1][px] + sdots[t2][2][px] + sdots[t2][3][px];
        }
        float v16[16];
        inv36(yt + YT_SET + tg, YT_PLANE, v16);
        __syncthreads();
#pragma unroll
        for (int px = 0; px < 16; px++) {
            float d = fdots[tl][px];
            if (f == 0) { m[px] = d; s[px] = 1.f; acc[px] = v16[px]; }
            else {
                float nm = fmaxf(m[px], d);
                float sc = expf(m[px] - nm);
                float e  = expf(d - nm);
                s[px] = s[px] * sc + e;
                acc[px] = acc[px] * sc + e * v16[px];
                m[px] = nm;
            }
        }
    }

#pragma unroll
    for (int px = 0; px < 16; px++) stage[tl][px][oc] = acc[px] / s[px];
    __syncthreads();
    for (int idx = t; idx < 2 * 16 * 32; idx += 256) {
        int l = idx & 31, px = (idx >> 5) & 15, tt = idx >> 9;
        int tw = tp * 2 + tt;
        int ty = tw >> 4, tx = tw & 15;
        int pix = (4 * ty + (px >> 2)) * 64 + 4 * tx + (px & 3);
        float4 v = *(float4*)&stage[tt][px][l * 4];
        *(float4*)(gp + ((long)(b * HW + pix)) * 128 + l * 4) = v;
    }
}

// ---- final: inverse transform + bias + T-broadcast, full-row staged stores ----
__global__ __launch_bounds__(256) void wino_out_final(
    const float* __restrict__ yto, const float* __restrict__ bias, float* __restrict__ out)
{
    extern __shared__ float st[];   // [4 rows][64 cols][128 oc] = 128KB
    const int b = blockIdx.x >> 5, rest = blockIdx.x & 31;
    const int ty = rest >> 1, half = rest & 1;
    const int t = threadIdx.x;
    const int oc = t & 127, tl = t >> 7;

    for (int pass = 0; pass < 8; pass++) {
        int tx = pass * 2 + tl;
        long tile = (long)b * 256 + ty * 16 + tx;
        const float* Y = yto + (long)half * YTO_HALF + tile * 128 + oc;
        float o[16];
        inv36(Y, YTO_PLANE, o);
#pragma unroll
        for (int px = 0; px < 16; px++)
            st[((px >> 2) * 64 + tx * 4 + (px & 3)) * 128 + oc] = o[px];
    }
    __syncthreads();

    for (int u = t; u < 512; u += 256) {
        int oc2 = u & 127, row = u >> 7;
        float bv = bias[half * 128 + oc2];
        float4 rv[16];
#pragma unroll
        for (int c4 = 0; c4 < 16; c4++) {
            rv[c4].x = st[(row * 64 + c4 * 4 + 0) * 128 + oc2] + bv;
            rv[c4].y = st[(row * 64 + c4 * 4 + 1) * 128 + oc2] + bv;
            rv[c4].z = st[(row * 64 + c4 * 4 + 2) * 128 + oc2] + bv;
            rv[c4].w = st[(row * 64 + c4 * 4 + 3) * 128 + oc2] + bv;
        }
#pragma unroll
        for (int tt = 0; tt < 8; tt++) {
            float* op = out + ((long)(b * 8 + tt) * 256 + half * 128 + oc2) * HW
                        + (ty * 4 + row) * 64;
#pragma unroll
            for (int c4 = 0; c4 < 16; c4++)
                *(float4*)(op + c4 * 4) = rv[c4];
        }
    }
}

// ---------------------------------------------------------------------------
extern "C" void kernel_launch(void* const* d_in, const int* in_sizes, int n_in,
                              void* d_out, int out_size)
{
    const float* x     = (const float*)d_in[0];
    const float* w_k   = (const float*)d_in[1];
    const float* w_q   = (const float*)d_in[2];
    const float* w_v   = (const float*)d_in[3];
    const float* w_out = (const float*)d_in[4];
    const float* b_out = (const float*)d_in[5];
    float* out = (float*)d_out;

    void* basev = nullptr;
    cudaGetSymbolAddress(&basev, g_scratch);
    float* S = (float*)basev;
    float* gp = S + OFF_GP;
    __half* wtO0 = (__half*)(S + OFF_WTO0);
    __half* wtO1 = (__half*)(S + OFF_WTO1);
    __half* wtq  = (__half*)(S + OFF_WTQ);
    __half* wtv  = (__half*)(S + OFF_WTV);
    __half* wtk  = (__half*)(S + OFF_WTK);
    uint8_t* xtp = (uint8_t*)(S + OFF_XTP);
    float*   yto = S + OFF_YTO;
    uint8_t* xt  = (uint8_t*)(S + OFF_XT);
    float*   yt  = S + OFF_YT;
    float*   ytk = S + OFF_YTK;

    const int DSM1 = 4 * 32768;
    const int DSM2 = 4 * 49152;
    const int DSMW = 32 * 6 * 67 * 4;
    const int DSMF = 4 * 64 * 128 * 4;
    cudaFuncSetAttribute(wino_gemm_p<2, 8, 0>, cudaFuncAttributeMaxDynamicSharedMemorySize, DSM2);
    cudaFuncSetAttribute(wino_gemm_p<1, 8, 1>, cudaFuncAttributeMaxDynamicSharedMemorySize, DSM1);
    cudaFuncSetAttribute(wino_gemm_p<2, 4, 2>, cudaFuncAttributeMaxDynamicSharedMemorySize, DSM2);
    cudaFuncSetAttribute(wino_in,   cudaFuncAttributeMaxDynamicSharedMemorySize, DSMW);
    cudaFuncSetAttribute(wino_in_p, cudaFuncAttributeMaxDynamicSharedMemorySize, DSMW);
    cudaFuncSetAttribute(wino_out_final, cudaFuncAttributeMaxDynamicSharedMemorySize, DSMF);

    wino_w<<<128, 256>>>(w_q, wtq);
    wino_w<<<128, 256>>>(w_v, wtv);
    wino_w<<<128, 256>>>(w_k, wtk);
    wino_w_out<<<128, 256>>>(w_out, wtO0, wtO1);
    wino_in<<<dim3(16, 32), 256, DSMW>>>(x, xt);

    // fused q+v Winograd GEMM: persistent, 2304 items
    wino_gemm_p<2, 8, 0><<<148, 256, DSM2>>>(xt, XT_PLANE_B, wtq, wtv, yt, yt + YT_SET, 2304, YT_PLANE);
    // k Winograd GEMM over key frames 0/8/16/24: 288 items
    wino_gemm_p<1, 8, 1><<<148, 256, DSM1>>>(xt, XT_PLANE_B, wtk, nullptr, ytk, nullptr, 288, YTK_PLANE);

    // fused inverse transform + attention -> pooled fp32 pixel-major
    attn_wino<<<512, 256>>>(yt, ytk, gp);

    // out conv via Winograd: forward transform, GEMM (M=256 as two halves), inverse+bias+broadcast
    wino_in_p<<<dim3(16, 4), 256, DSMW>>>(gp, xtp);
    wino_gemm_p<2, 4, 2><<<148, 256, DSM2>>>(xtp, XTP_PLANE_B, wtO0, wtO1, yto, yto + YTO_HALF, 288, YTO_PLANE);
    wino_out_final<<<128, 256, DSMF>>>(yto, b_out, out);
}